// round 9
// baseline (speedup 1.0000x reference)
#include <cuda_runtime.h>
#include <cuda_bf16.h>
#include <cstdint>
#include <math.h>

#define Bq 2
#define T 2048
#define C 1024
#define H 16
#define D 64
#define E 4
#define BT (Bq*T)
#define FF (4*C)
#define GROUP_CAP (BT + E*128)
#define NTILES (GROUP_CAP/128)
#define EPS_RMS 1.1920929e-07f

#define SMEM_SWIZZLE_128B(b) ((b) ^ (((b) >> 3) & 0x70))

__device__ __forceinline__ uint32_t smem_to_u32(const void* p) {
    uint32_t a;
    asm("{ .reg .u64 t; cvta.to.shared.u64 t, %1; cvt.u32.u64 %0, t; }" : "=r"(a) : "l"(p));
    return a;
}
__device__ __forceinline__ void ldsm4(uint32_t* r, uint32_t addr) {
    asm volatile("ldmatrix.sync.aligned.m8n8.x4.shared.b16 {%0,%1,%2,%3}, [%4];"
                 : "=r"(r[0]), "=r"(r[1]), "=r"(r[2]), "=r"(r[3]) : "r"(addr));
}
__device__ __forceinline__ void ldsm4t(uint32_t* r, uint32_t addr) {
    asm volatile("ldmatrix.sync.aligned.m8n8.x4.trans.shared.b16 {%0,%1,%2,%3}, [%4];"
                 : "=r"(r[0]), "=r"(r[1]), "=r"(r[2]), "=r"(r[3]) : "r"(addr));
}
__device__ __forceinline__ void mma_bf16(float* c, const uint32_t* a, const uint32_t* b) {
    asm volatile("mma.sync.aligned.m16n8k16.row.col.f32.bf16.bf16.f32 "
        "{%0,%1,%2,%3}, {%4,%5,%6,%7}, {%8,%9}, {%0,%1,%2,%3};"
        : "+f"(c[0]), "+f"(c[1]), "+f"(c[2]), "+f"(c[3])
        : "r"(a[0]), "r"(a[1]), "r"(a[2]), "r"(a[3]), "r"(b[0]), "r"(b[1]));
}
__device__ __forceinline__ float ex2f(float x) {
    float y; asm("ex2.approx.ftz.f32 %0, %1;" : "=f"(y) : "f"(x)); return y;
}
#define CP16(s, g) asm volatile("cp.async.cg.shared.global [%0], [%1], 16;" \
                                :: "r"(s), "l"(g) : "memory")

// ======================= scratch (static device globals) =======================
__device__ __nv_bfloat16 g_h1_hi[BT*C], g_h1_lo[BT*C];
__device__ float g_qk[BT*2*C];
__device__ __nv_bfloat16 g_qhi[BT*C], g_qlo[BT*C];
__device__ __nv_bfloat16 g_khi[BT*C], g_klo[BT*C];
__device__ __nv_bfloat16 g_vhi[BT*C], g_vlo[BT*C];
__device__ __nv_bfloat16 g_y_hi[BT*C], g_y_lo[BT*C];
__device__ float g_x2[BT*C], g_h2[BT*C];
__device__ __nv_bfloat16 g_h2g_hi[GROUP_CAP*C], g_h2g_lo[GROUP_CAP*C];
__device__ __nv_bfloat16 g_hid_hi[(size_t)GROUP_CAP*FF], g_hid_lo[(size_t)GROUP_CAP*FF];
__device__ float g_outg[GROUP_CAP*C];
__device__ __nv_bfloat16 g_wqkv_hi[3*C*C], g_wqkv_lo[3*C*C];
__device__ __nv_bfloat16 g_wo_hi[C*C], g_wo_lo[C*C];
__device__ __nv_bfloat16 g_wfc_hi[(size_t)E*C*FF], g_wfc_lo[(size_t)E*C*FF];
__device__ __nv_bfloat16 g_wpj_hi[(size_t)E*FF*C], g_wpj_lo[(size_t)E*FF*C];
__device__ int   g_expert[BT];
__device__ int   g_counts[E];
__device__ int   g_cursor[E];
__device__ int   g_segstart[E];
__device__ int   g_tileExpert[NTILES];
__device__ int   g_tokenOfRow[GROUP_CAP];
__device__ double g_expsum[E];
__device__ double g_zsum;
__device__ double g_entsum;

__device__ __forceinline__ void bsplit(float v, __nv_bfloat16& h, __nv_bfloat16& l) {
    h = __float2bfloat16(v);
    l = __float2bfloat16(v - __bfloat162float(h));
}
__device__ __forceinline__ void packsplit(float v0, float v1, uint32_t& hi, uint32_t& lo) {
    __nv_bfloat16 h0, l0, h1, l1;
    bsplit(v0, h0, l0); bsplit(v1, h1, l1);
    __nv_bfloat162 hh(h0, h1), ll(l0, l1);
    hi = *reinterpret_cast<uint32_t*>(&hh);
    lo = *reinterpret_cast<uint32_t*>(&ll);
}

// ======================= small kernels =======================
__global__ void reset_kernel() {
    int i = blockIdx.x * blockDim.x + threadIdx.x;
    if (i < E) { g_counts[i] = 0; g_cursor[i] = 0; g_expsum[i] = 0.0; }
    if (i == 0) { g_zsum = 0.0; g_entsum = 0.0; }
    if (i < NTILES) g_tileExpert[i] = -1;
    if (i < GROUP_CAP) g_tokenOfRow[i] = -1;
}

__global__ void zero_pad_kernel() {
    int r = blockIdx.x;
    if (g_tokenOfRow[r] >= 0) return;
    uint2 z = make_uint2(0u, 0u);
    ((uint2*)(g_h2g_hi + (size_t)r * C))[threadIdx.x] = z;
    ((uint2*)(g_h2g_lo + (size_t)r * C))[threadIdx.x] = z;
}

// transpose + bf16-split weights: W [Kd, Nd] fp32 -> T [Nd, Kd] bf16 hi/lo
__global__ void __launch_bounds__(256) wconv_kernel(
    const float* __restrict__ W,
    __nv_bfloat16* __restrict__ Thi, __nv_bfloat16* __restrict__ Tlo,
    int Kd, int Nd) {
    __shared__ float tile[64][65];
    int b = blockIdx.z;
    const float* Wb = W + (size_t)b * Kd * Nd;
    __nv_bfloat16* Th = Thi + (size_t)b * Kd * Nd;
    __nv_bfloat16* Tl = Tlo + (size_t)b * Kd * Nd;
    int n0 = blockIdx.x * 64, k0 = blockIdx.y * 64;
    int tid = threadIdx.x;
    int lr = tid >> 4, lc = (tid & 15) * 4;
    #pragma unroll
    for (int i = 0; i < 4; i++) {
        int k = lr + i * 16;
        float4 v = *(const float4*)(Wb + (size_t)(k0 + k) * Nd + n0 + lc);
        tile[k][lc] = v.x; tile[k][lc+1] = v.y; tile[k][lc+2] = v.z; tile[k][lc+3] = v.w;
    }
    __syncthreads();
    int wn = tid >> 4, wk = (tid & 15) * 4;
    #pragma unroll
    for (int i = 0; i < 4; i++) {
        int n = wn + i * 16;
        float v0 = tile[wk][n],   v1 = tile[wk+1][n];
        float v2 = tile[wk+2][n], v3 = tile[wk+3][n];
        uint32_t h01, l01, h23, l23;
        packsplit(v0, v1, h01, l01);
        packsplit(v2, v3, h23, l23);
        size_t o = (size_t)(n0 + n) * Kd + k0 + wk;
        *(uint2*)(Th + o) = make_uint2(h01, h23);
        *(uint2*)(Tl + o) = make_uint2(l01, l23);
    }
}

// RMSNorm over C -> bf16 hi/lo pair
__global__ void rmsnorm_kernel(const float* __restrict__ in,
                               __nv_bfloat16* __restrict__ ohi, __nv_bfloat16* __restrict__ olo) {
    int t = blockIdx.x;
    const float4* ip = (const float4*)(in + (size_t)t * C);
    __shared__ float red[8];
    float4 v = ip[threadIdx.x];
    float ss = v.x*v.x + v.y*v.y + v.z*v.z + v.w*v.w;
    #pragma unroll
    for (int o = 16; o; o >>= 1) ss += __shfl_xor_sync(0xffffffffu, ss, o);
    if ((threadIdx.x & 31) == 0) red[threadIdx.x >> 5] = ss;
    __syncthreads();
    if (threadIdx.x == 0) {
        float s = 0.f;
        #pragma unroll
        for (int w = 0; w < 8; w++) s += red[w];
        red[0] = s;
    }
    __syncthreads();
    float r = rsqrtf(red[0] / (float)C + EPS_RMS);
    float4 o = make_float4(v.x*r, v.y*r, v.z*r, v.w*r);
    __nv_bfloat16 h0,l0,h1,l1,h2,l2,h3,l3;
    bsplit(o.x,h0,l0); bsplit(o.y,h1,l1); bsplit(o.z,h2,l2); bsplit(o.w,h3,l3);
    __nv_bfloat162* hp = (__nv_bfloat162*)(ohi + (size_t)t * C);
    __nv_bfloat162* lp = (__nv_bfloat162*)(olo + (size_t)t * C);
    hp[threadIdx.x*2]   = __nv_bfloat162(h0, h1);
    hp[threadIdx.x*2+1] = __nv_bfloat162(h2, h3);
    lp[threadIdx.x*2]   = __nv_bfloat162(l0, l1);
    lp[threadIdx.x*2+1] = __nv_bfloat162(l2, l3);
}

// RMSNorm fp32 out + fused router
__global__ void rmsnorm_router_kernel(const float* __restrict__ in, float* __restrict__ outf,
                                      const float* __restrict__ Wr) {
    int t = blockIdx.x;
    const float4* ip = (const float4*)(in + (size_t)t * C);
    __shared__ float red[8];
    __shared__ float lred[32];
    float4 v = ip[threadIdx.x];
    float ss = v.x*v.x + v.y*v.y + v.z*v.z + v.w*v.w;
    #pragma unroll
    for (int o = 16; o; o >>= 1) ss += __shfl_xor_sync(0xffffffffu, ss, o);
    if ((threadIdx.x & 31) == 0) red[threadIdx.x >> 5] = ss;
    __syncthreads();
    if (threadIdx.x == 0) {
        float s = 0.f;
        #pragma unroll
        for (int w = 0; w < 8; w++) s += red[w];
        red[0] = s;
    }
    __syncthreads();
    float r = rsqrtf(red[0] / (float)C + EPS_RMS);
    float4 o = make_float4(v.x*r, v.y*r, v.z*r, v.w*r);
    ((float4*)(outf + (size_t)t * C))[threadIdx.x] = o;

    int c0 = threadIdx.x * 4;
    float4 w0 = *(const float4*)(Wr + (size_t)(c0+0) * E);
    float4 w1 = *(const float4*)(Wr + (size_t)(c0+1) * E);
    float4 w2 = *(const float4*)(Wr + (size_t)(c0+2) * E);
    float4 w3 = *(const float4*)(Wr + (size_t)(c0+3) * E);
    float a0 = o.x*w0.x + o.y*w1.x + o.z*w2.x + o.w*w3.x;
    float a1 = o.x*w0.y + o.y*w1.y + o.z*w2.y + o.w*w3.y;
    float a2 = o.x*w0.z + o.y*w1.z + o.z*w2.z + o.w*w3.z;
    float a3 = o.x*w0.w + o.y*w1.w + o.z*w2.w + o.w*w3.w;
    #pragma unroll
    for (int off = 16; off; off >>= 1) {
        a0 += __shfl_xor_sync(0xffffffffu, a0, off);
        a1 += __shfl_xor_sync(0xffffffffu, a1, off);
        a2 += __shfl_xor_sync(0xffffffffu, a2, off);
        a3 += __shfl_xor_sync(0xffffffffu, a3, off);
    }
    if ((threadIdx.x & 31) == 0) {
        int w = threadIdx.x >> 5;
        lred[w*4+0] = a0; lred[w*4+1] = a1; lred[w*4+2] = a2; lred[w*4+3] = a3;
    }
    __syncthreads();
    if (threadIdx.x == 0) {
        float lg[4];
        #pragma unroll
        for (int e = 0; e < 4; e++) {
            float s = 0.f;
            #pragma unroll
            for (int w = 0; w < 8; w++) s += lred[w*4+e];
            lg[e] = s;
        }
        int arg = 0;
        #pragma unroll
        for (int e = 1; e < 4; e++) if (lg[e] > lg[arg]) arg = e;
        float m = fmaxf(fmaxf(lg[0], lg[1]), fmaxf(lg[2], lg[3]));
        float ez[4]; float sum = 0.f;
        #pragma unroll
        for (int e = 0; e < 4; e++) { ez[e] = expf(lg[e] - m); sum += ez[e]; }
        float p[4];
        #pragma unroll
        for (int e = 0; e < 4; e++) p[e] = ez[e] / sum;
        g_expert[t] = arg;
        atomicAdd(&g_counts[arg], 1);
        #pragma unroll
        for (int e = 0; e < 4; e++) atomicAdd(&g_expsum[e], (double)p[e]);
        float lse = m + logf(sum);
        atomicAdd(&g_zsum, (double)lse * (double)lse);
        float ent = 0.f;
        #pragma unroll
        for (int e = 0; e < 4; e++) ent -= p[e] * logf(p[e] + 1e-9f);
        atomicAdd(&g_entsum, (double)ent);
    }
}

// per-head RMSNorm + RoPE; reads qk buffer [BT, 2048]
__global__ void qk_rope_kernel(const float* __restrict__ qk,
                               __nv_bfloat16* __restrict__ qhi, __nv_bfloat16* __restrict__ qlo,
                               __nv_bfloat16* __restrict__ khi, __nv_bfloat16* __restrict__ klo) {
    int tok  = blockIdx.x;
    int head = threadIdx.x >> 5;
    int lane = threadIdx.x & 31;
    int tpos = tok % T;
    float ex  = (float)(2 * lane) / 64.0f;
    float inv = 1.0f / powf(10000.0f, ex);
    float ang = (float)tpos * inv;
    float c = cosf(ang), s = sinf(ang);
    size_t obase = (size_t)tok * C + head * D;
    #pragma unroll
    for (int m = 0; m < 2; m++) {
        const float* src = qk + (size_t)tok * 2048 + m * 1024 + head * D;
        __nv_bfloat16* dh = (m == 0 ? qhi : khi) + obase;
        __nv_bfloat16* dl = (m == 0 ? qlo : klo) + obase;
        float x1 = src[lane], x2 = src[lane + 32];
        float ss = x1*x1 + x2*x2;
        #pragma unroll
        for (int o = 16; o; o >>= 1) ss += __shfl_xor_sync(0xffffffffu, ss, o);
        float r = rsqrtf(ss / (float)D + EPS_RMS);
        x1 *= r; x2 *= r;
        float o1 =  x1 * c + x2 * s;
        float o2 = -x1 * s + x2 * c;
        __nv_bfloat16 h, l;
        bsplit(o1, h, l); dh[lane] = h;      dl[lane] = l;
        bsplit(o2, h, l); dh[lane + 32] = h; dl[lane + 32] = l;
    }
}

// ======================= HMMA flash attention (bf16x3) =======================
#define AT_QHI 0
#define AT_QLO 16384
#define AT_STG 32768
#define AT_STGSZ 32768
#define AT_KHI 0
#define AT_KLO 8192
#define AT_VHI 16384
#define AT_VLO 24576
#define ATT_SMEM (32768 + 2*32768)

__global__ void __launch_bounds__(256) attn_mma_kernel(
    const __nv_bfloat16* __restrict__ qhi, const __nv_bfloat16* __restrict__ qlo,
    const __nv_bfloat16* __restrict__ khi, const __nv_bfloat16* __restrict__ klo,
    const __nv_bfloat16* __restrict__ vhi, const __nv_bfloat16* __restrict__ vlo,
    __nv_bfloat16* __restrict__ yhi, __nv_bfloat16* __restrict__ ylo)
{
    extern __shared__ __align__(1024) char smem[];
    uint32_t sb = smem_to_u32(smem);
    int bh = blockIdx.y;
    int b = bh / H, hh = bh % H;
    int qb = blockIdx.x;
    int q0 = qb * 128;
    int tid = threadIdx.x, wid = tid >> 5, lid = tid & 31;
    int nkt = 2 * qb + 2;

    #pragma unroll
    for (int i = 0; i < 4; i++) {
        int lin = tid + i * 256;
        int r = lin >> 3, ch = lin & 7;
        uint32_t so = SMEM_SWIZZLE_128B((uint32_t)(r * 128 + ch * 16));
        size_t g = (size_t)(b*T + q0 + r) * C + hh * D + ch * 8;
        CP16(sb + AT_QHI + so, qhi + g);
        CP16(sb + AT_QLO + so, qlo + g);
    }
    asm volatile("cp.async.commit_group;" ::: "memory");
    #pragma unroll
    for (int i = 0; i < 2; i++) {
        int lin = tid + i * 256;
        int r = lin >> 3, ch = lin & 7;
        uint32_t so = SMEM_SWIZZLE_128B((uint32_t)(r * 128 + ch * 16));
        size_t g = (size_t)(b*T + r) * C + hh * D + ch * 8;
        uint32_t st = sb + AT_STG;
        CP16(st + AT_KHI + so, khi + g);
        CP16(st + AT_KLO + so, klo + g);
        CP16(st + AT_VHI + so, vhi + g);
        CP16(st + AT_VLO + so, vlo + g);
    }
    asm volatile("cp.async.commit_group;" ::: "memory");

    uint32_t qa_hi[4][4], qa_lo[4][4];
    float oac[8][4];
    #pragma unroll
    for (int j = 0; j < 8; j++)
        #pragma unroll
        for (int r = 0; r < 4; r++) oac[j][r] = 0.f;
    float m0 = -1e30f, m1 = -1e30f, l0 = 0.f, l1 = 0.f;

    int off = lid & 7, part = lid >> 3;
    int qr = lid >> 2, qc = (lid & 3) * 2;
    const float SC2 = 0.18033688011112042f;

    for (int kt = 0; kt < nkt; kt++) {
        if (kt + 1 < nkt) {
            #pragma unroll
            for (int i = 0; i < 2; i++) {
                int lin = tid + i * 256;
                int r = lin >> 3, ch = lin & 7;
                uint32_t so = SMEM_SWIZZLE_128B((uint32_t)(r * 128 + ch * 16));
                size_t g = (size_t)(b*T + (kt + 1) * 64 + r) * C + hh * D + ch * 8;
                uint32_t st = sb + AT_STG + (uint32_t)((kt + 1) & 1) * AT_STGSZ;
                CP16(st + AT_KHI + so, khi + g);
                CP16(st + AT_KLO + so, klo + g);
                CP16(st + AT_VHI + so, vhi + g);
                CP16(st + AT_VLO + so, vlo + g);
            }
            asm volatile("cp.async.commit_group;" ::: "memory");
            asm volatile("cp.async.wait_group 1;" ::: "memory");
        } else {
            asm volatile("cp.async.wait_group 0;" ::: "memory");
        }
        __syncthreads();

        if (kt == 0) {
            #pragma unroll
            for (int kk = 0; kk < 4; kk++) {
                int row = wid * 16 + (part & 1) * 8 + off;
                int colb = kk * 32 + (part & 2) * 8;
                uint32_t so = SMEM_SWIZZLE_128B((uint32_t)(row * 128 + colb));
                ldsm4(qa_hi[kk], sb + AT_QHI + so);
                ldsm4(qa_lo[kk], sb + AT_QLO + so);
            }
        }

        uint32_t st = sb + AT_STG + (uint32_t)(kt & 1) * AT_STGSZ;

        float s[8][4];
        #pragma unroll
        for (int j = 0; j < 8; j++)
            #pragma unroll
            for (int r = 0; r < 4; r++) s[j][r] = 0.f;
        #pragma unroll
        for (int kk = 0; kk < 4; kk++) {
            #pragma unroll
            for (int jj = 0; jj < 4; jj++) {
                int row = jj * 16 + (part & 2) * 4 + off;
                int colb = kk * 32 + (part & 1) * 16;
                uint32_t so = SMEM_SWIZZLE_128B((uint32_t)(row * 128 + colb));
                uint32_t kh[4], kl[4];
                ldsm4(kh, st + AT_KHI + so);
                ldsm4(kl, st + AT_KLO + so);
                mma_bf16(s[2*jj],     qa_hi[kk], kh);
                mma_bf16(s[2*jj],     qa_hi[kk], kl);
                mma_bf16(s[2*jj],     qa_lo[kk], kh);
                mma_bf16(s[2*jj+1],   qa_hi[kk], kh + 2);
                mma_bf16(s[2*jj+1],   qa_hi[kk], kl + 2);
                mma_bf16(s[2*jj+1],   qa_lo[kk], kh + 2);
            }
        }

        bool domask = (kt >= nkt - 2);
        #pragma unroll
        for (int j = 0; j < 8; j++) {
            #pragma unroll
            for (int r = 0; r < 4; r++) {
                float v = s[j][r] * SC2;
                if (domask) {
                    int key = kt * 64 + j * 8 + qc + (r & 1);
                    int row = q0 + wid * 16 + qr + (r & 2) * 4;
                    if (key > row) v = -1e30f;
                }
                s[j][r] = v;
            }
        }

        float mx0 = -1e30f, mx1 = -1e30f;
        #pragma unroll
        for (int j = 0; j < 8; j++) {
            mx0 = fmaxf(mx0, fmaxf(s[j][0], s[j][1]));
            mx1 = fmaxf(mx1, fmaxf(s[j][2], s[j][3]));
        }
        mx0 = fmaxf(mx0, __shfl_xor_sync(0xffffffffu, mx0, 1));
        mx0 = fmaxf(mx0, __shfl_xor_sync(0xffffffffu, mx0, 2));
        mx1 = fmaxf(mx1, __shfl_xor_sync(0xffffffffu, mx1, 1));
        mx1 = fmaxf(mx1, __shfl_xor_sync(0xffffffffu, mx1, 2));
        float mn0 = fmaxf(m0, mx0), mn1 = fmaxf(m1, mx1);
        float al0 = ex2f(m0 - mn0), al1 = ex2f(m1 - mn1);
        float sm0 = 0.f, sm1 = 0.f;
        #pragma unroll
        for (int j = 0; j < 8; j++) {
            s[j][0] = ex2f(s[j][0] - mn0); sm0 += s[j][0];
            s[j][1] = ex2f(s[j][1] - mn0); sm0 += s[j][1];
            s[j][2] = ex2f(s[j][2] - mn1); sm1 += s[j][2];
            s[j][3] = ex2f(s[j][3] - mn1); sm1 += s[j][3];
        }
        sm0 += __shfl_xor_sync(0xffffffffu, sm0, 1);
        sm0 += __shfl_xor_sync(0xffffffffu, sm0, 2);
        sm1 += __shfl_xor_sync(0xffffffffu, sm1, 1);
        sm1 += __shfl_xor_sync(0xffffffffu, sm1, 2);
        l0 = l0 * al0 + sm0;  l1 = l1 * al1 + sm1;
        m0 = mn0;  m1 = mn1;
        #pragma unroll
        for (int j = 0; j < 8; j++) {
            oac[j][0] *= al0; oac[j][1] *= al0;
            oac[j][2] *= al1; oac[j][3] *= al1;
        }

        #pragma unroll
        for (int kk = 0; kk < 4; kk++) {
            uint32_t pah[4], pal[4];
            packsplit(s[2*kk][0],   s[2*kk][1],   pah[0], pal[0]);
            packsplit(s[2*kk][2],   s[2*kk][3],   pah[1], pal[1]);
            packsplit(s[2*kk+1][0], s[2*kk+1][1], pah[2], pal[2]);
            packsplit(s[2*kk+1][2], s[2*kk+1][3], pah[3], pal[3]);
            #pragma unroll
            for (int jj = 0; jj < 4; jj++) {
                int row = kk * 16 + (part & 1) * 8 + off;
                int colb = jj * 32 + (part & 2) * 8;
                uint32_t so = SMEM_SWIZZLE_128B((uint32_t)(row * 128 + colb));
                uint32_t vh[4], vl[4];
                ldsm4t(vh, st + AT_VHI + so);
                ldsm4t(vl, st + AT_VLO + so);
                mma_bf16(oac[2*jj],   pah, vh);
                mma_bf16(oac[2*jj],   pah, vl);
                mma_bf16(oac[2*jj],   pal, vh);
                mma_bf16(oac[2*jj+1], pah, vh + 2);
                mma_bf16(oac[2*jj+1], pah, vl + 2);
                mma_bf16(oac[2*jj+1], pal, vh + 2);
            }
        }
        __syncthreads();
    }

    float inv0 = 1.f / l0, inv1 = 1.f / l1;
    #pragma unroll
    for (int j = 0; j < 8; j++) {
        size_t i0 = (size_t)(b*T + q0 + wid*16 + qr) * C + hh * D + j * 8 + qc;
        size_t i1 = (size_t)(b*T + q0 + wid*16 + qr + 8) * C + hh * D + j * 8 + qc;
        uint32_t ph, pl;
        packsplit(oac[j][0] * inv0, oac[j][1] * inv0, ph, pl);
        *(uint32_t*)(yhi + i0) = ph;  *(uint32_t*)(ylo + i0) = pl;
        packsplit(oac[j][2] * inv1, oac[j][3] * inv1, ph, pl);
        *(uint32_t*)(yhi + i1) = ph;  *(uint32_t*)(ylo + i1) = pl;
    }
}

// ======================= HMMA bf16x3 GEMM — 128x128 tile, KTILE=32, 3 stages, 2 CTA/SM ===
// SMEM row layout (128 B): [32 cols hi (64B) | 32 cols lo (64B)], SW128 swizzle.
// Stage = A 16KB + B 16KB = 32 KB; 3 stages = 96 KB -> 2 CTAs/SM.
// Ring of 3 buffers: [wait 1; sync; compute kt; issue kt+2; commit] -> 1 barrier/kt.
// epi: 0 fp32; 1 fp32+resid; 2 relu(acc)^2 -> bf16 pair; 3 acc -> bf16 pair;
//      4 fused QKV: cols [0,2048) fp32 stride 2048, cols [2048,3072) bf16 pair stride 1024
#define KTILE 32
#define G_A 0
#define G_B 16384
#define G_STAGE 32768
#define SMEM_GEMM_BYTES (3*G_STAGE)

__global__ void __launch_bounds__(256, 2) gemm_bf16x3(
    const __nv_bfloat16* __restrict__ Ahi, const __nv_bfloat16* __restrict__ Alo,
    const __nv_bfloat16* __restrict__ Bhi, const __nv_bfloat16* __restrict__ Blo,
    size_t bstride,
    float* __restrict__ Cout,
    __nv_bfloat16* __restrict__ Ohi, __nv_bfloat16* __restrict__ Olo,
    const float* __restrict__ resid,
    const int* __restrict__ tileExpert,
    int N, int K, int epi)
{
    extern __shared__ __align__(1024) char smem[];
    int by = blockIdx.y, bx = blockIdx.x;
    int e = 0;
    if (tileExpert) { e = tileExpert[by]; if (e < 0) return; }
    const __nv_bfloat16* Bh = Bhi + (size_t)e * bstride;
    const __nv_bfloat16* Bl = Blo + (size_t)e * bstride;

    uint32_t sb = smem_to_u32(smem);
    int tid = threadIdx.x, wid = tid >> 5, lid = tid & 31;
    int wm = wid & 1, wn = wid >> 1;
    int row0 = by * 128, col0 = bx * 128;
    int nkt = K / KTILE;

    float acc[4][4][4];
    #pragma unroll
    for (int i = 0; i < 4; i++)
        #pragma unroll
        for (int j = 0; j < 4; j++)
            #pragma unroll
            for (int r = 0; r < 4; r++) acc[i][j][r] = 0.f;

    // loader: 1024 chunks of 16B per operand per stage; 4 per thread.
    // chunk layout: r = lin>>3 (row 0..127), ch = lin&7; ch<4 -> hi (bytes [0,64)), ch>=4 -> lo.
    int lr = tid >> 3, lc7 = tid & 7;

    // preload stages 0 and 1
    #pragma unroll
    for (int st0 = 0; st0 < 2; st0++) {
        uint32_t base = sb + (uint32_t)st0 * G_STAGE;
        int k0 = st0 * KTILE;
        #pragma unroll
        for (int i = 0; i < 4; i++) {
            int r = lr + i * 32;
            uint32_t so = SMEM_SWIZZLE_128B((uint32_t)(r * 128 + lc7 * 16));
            const __nv_bfloat16* asrc = (lc7 < 4) ? (Ahi + (size_t)(row0 + r) * K + k0 + lc7 * 8)
                                                  : (Alo + (size_t)(row0 + r) * K + k0 + (lc7 - 4) * 8);
            const __nv_bfloat16* bsrc = (lc7 < 4) ? (Bh + (size_t)(col0 + r) * K + k0 + lc7 * 8)
                                                  : (Bl + (size_t)(col0 + r) * K + k0 + (lc7 - 4) * 8);
            CP16(base + G_A + so, asrc);
            CP16(base + G_B + so, bsrc);
        }
        asm volatile("cp.async.commit_group;" ::: "memory");
    }

    for (int kt = 0; kt < nkt; kt++) {
        asm volatile("cp.async.wait_group 1;" ::: "memory");
        __syncthreads();

        uint32_t cur = sb + (uint32_t)(kt % 3) * G_STAGE;
        uint32_t sA = cur + G_A, sB = cur + G_B;
        #pragma unroll
        for (int kk = 0; kk < 2; kk++) {
            int colb = kk * 32 + (lid >> 4) * 16;       // hi bytes
            uint32_t a_hi[4][4], a_lo[4][4];
            #pragma unroll
            for (int mf = 0; mf < 4; mf++) {
                int rowm = wm * 64 + mf * 16 + (lid & 15);
                uint32_t soh = SMEM_SWIZZLE_128B((uint32_t)(rowm * 128 + colb));
                uint32_t sol = SMEM_SWIZZLE_128B((uint32_t)(rowm * 128 + colb + 64));
                ldsm4(a_hi[mf], sA + soh);
                ldsm4(a_lo[mf], sA + sol);
            }
            uint32_t b_hi[4][2], b_lo[4][2];
            #pragma unroll
            for (int g = 0; g < 2; g++) {
                int rown = wn * 32 + g * 16 + (lid & 15);
                uint32_t soh = SMEM_SWIZZLE_128B((uint32_t)(rown * 128 + colb));
                uint32_t sol = SMEM_SWIZZLE_128B((uint32_t)(rown * 128 + colb + 64));
                uint32_t r4[4];
                ldsm4(r4, sB + soh);
                b_hi[2*g][0] = r4[0]; b_hi[2*g+1][0] = r4[1];
                b_hi[2*g][1] = r4[2]; b_hi[2*g+1][1] = r4[3];
                ldsm4(r4, sB + sol);
                b_lo[2*g][0] = r4[0]; b_lo[2*g+1][0] = r4[1];
                b_lo[2*g][1] = r4[2]; b_lo[2*g+1][1] = r4[3];
            }
            #pragma unroll
            for (int mf = 0; mf < 4; mf++)
                #pragma unroll
                for (int nf = 0; nf < 4; nf++) {
                    mma_bf16(acc[mf][nf], a_hi[mf], b_hi[nf]);
                    mma_bf16(acc[mf][nf], a_hi[mf], b_lo[nf]);
                    mma_bf16(acc[mf][nf], a_lo[mf], b_hi[nf]);
                }
        }

        // issue stage kt+2 (buffer (kt+2)%3 != kt%3 and != (kt+1)%3)
        if (kt + 2 < nkt) {
            uint32_t nxt = sb + (uint32_t)((kt + 2) % 3) * G_STAGE;
            int k0 = (kt + 2) * KTILE;
            #pragma unroll
            for (int i = 0; i < 4; i++) {
                int r = lr + i * 32;
                uint32_t so = SMEM_SWIZZLE_128B((uint32_t)(r * 128 + lc7 * 16));
                const __nv_bfloat16* asrc = (lc7 < 4) ? (Ahi + (size_t)(row0 + r) * K + k0 + lc7 * 8)
                                                      : (Alo + (size_t)(row0 + r) * K + k0 + (lc7 - 4) * 8);
                const __nv_bfloat16* bsrc = (lc7 < 4) ? (Bh + (size_t)(col0 + r) * K + k0 + lc7 * 8)
                                                      : (Bl + (size_t)(col0 + r) * K + k0 + (lc7 - 4) * 8);
                CP16(nxt + G_A + so, asrc);
                CP16(nxt + G_B + so, bsrc);
            }
        }
        asm volatile("cp.async.commit_group;" ::: "memory");
    }

    int qr = lid >> 2, qc = (lid & 3) * 2;
    #pragma unroll
    for (int mf = 0; mf < 4; mf++) {
        #pragma unroll
        for (int nf = 0; nf < 4; nf++) {
            float* cc = acc[mf][nf];
            int col = col0 + wn * 32 + nf * 8 + qc;
            #pragma unroll
            for (int half = 0; half < 2; half++) {
                int row = row0 + wm * 64 + mf * 16 + qr + half * 8;
                float v0 = cc[2*half], v1 = cc[2*half + 1];
                if (epi == 0) {
                    size_t idx = (size_t)row * N + col;
                    *(float2*)(Cout + idx) = make_float2(v0, v1);
                } else if (epi == 1) {
                    size_t idx = (size_t)row * N + col;
                    float2 rr = *(const float2*)(resid + idx);
                    *(float2*)(Cout + idx) = make_float2(v0 + rr.x, v1 + rr.y);
                } else if (epi == 4) {
                    if (col < 2048) {
                        size_t idx = (size_t)row * 2048 + col;
                        *(float2*)(Cout + idx) = make_float2(v0, v1);
                    } else {
                        size_t idx = (size_t)row * 1024 + (col - 2048);
                        uint32_t ph, pl;
                        packsplit(v0, v1, ph, pl);
                        *(uint32_t*)(Ohi + idx) = ph;
                        *(uint32_t*)(Olo + idx) = pl;
                    }
                } else {
                    if (epi == 2) {
                        v0 = fmaxf(v0, 0.f); v0 *= v0;
                        v1 = fmaxf(v1, 0.f); v1 *= v1;
                    }
                    size_t idx = (size_t)row * N + col;
                    uint32_t ph, pl;
                    packsplit(v0, v1, ph, pl);
                    *(uint32_t*)(Ohi + idx) = ph;
                    *(uint32_t*)(Olo + idx) = pl;
                }
            }
        }
    }
}

// ======================= grouping / scatter / scalars =======================
__global__ void offsets_kernel() {
    if (threadIdx.x == 0 && blockIdx.x == 0) {
        int off = 0;
        for (int e = 0; e < E; e++) {
            g_segstart[e] = off;
            int padded = (g_counts[e] + 127) & ~127;
            for (int i = 0; i < padded / 128; i++)
                g_tileExpert[off / 128 + i] = e;
            off += padded;
        }
    }
}

__global__ void assign_kernel(const float* __restrict__ h2) {
    int t = blockIdx.x;
    __shared__ int slot_s;
    if (threadIdx.x == 0) {
        int e = g_expert[t];
        int slot = g_segstart[e] + atomicAdd(&g_cursor[e], 1);
        g_tokenOfRow[slot] = t;
        slot_s = slot;
    }
    __syncthreads();
    int s = slot_s;
    float4 v = ((const float4*)(h2 + (size_t)t * C))[threadIdx.x];
    __nv_bfloat16 h0,l0,h1,l1,h2b,l2,h3,l3;
    bsplit(v.x,h0,l0); bsplit(v.y,h1,l1); bsplit(v.z,h2b,l2); bsplit(v.w,h3,l3);
    __nv_bfloat162* hp = (__nv_bfloat162*)(g_h2g_hi + (size_t)s * C);
    __nv_bfloat162* lp = (__nv_bfloat162*)(g_h2g_lo + (size_t)s * C);
    hp[threadIdx.x*2]   = __nv_bfloat162(h0, h1);
    hp[threadIdx.x*2+1] = __nv_bfloat162(h2b, h3);
    lp[threadIdx.x*2]   = __nv_bfloat162(l0, l1);
    lp[threadIdx.x*2+1] = __nv_bfloat162(l2, l3);
}

__global__ void scatter_kernel(const float* __restrict__ x2, float* __restrict__ out) {
    int r = blockIdx.x;
    int t = g_tokenOfRow[r];
    if (t < 0) return;
    float4 a = ((const float4*)(x2 + (size_t)t * C))[threadIdx.x];
    float4 b = ((const float4*)(g_outg + (size_t)r * C))[threadIdx.x];
    ((float4*)(out + (size_t)t * C))[threadIdx.x] =
        make_float4(a.x + b.x, a.y + b.y, a.z + b.z, a.w + b.w);
}

__global__ void scalars_kernel(float* __restrict__ out) {
    if (threadIdx.x == 0 && blockIdx.x == 0) {
        const double NTOK = (double)BT;
        double aux = 0.0;
        for (int e = 0; e < E; e++) {
            double actual = (double)g_counts[e] / NTOK;
            double expd   = g_expsum[e] / NTOK;
            aux += actual * expd;
        }
        size_t base = (size_t)BT * C;
        out[base + 0] = (float)((double)E * aux);
        out[base + 1] = (float)(g_zsum / NTOK);
        out[base + 2] = (float)((g_entsum / NTOK) / log((double)E));
        for (int e = 0; e < E; e++)
            out[base + 3 + e] = (float)((double)g_counts[e] / NTOK);
    }
}

// ======================= launch =======================
static void* sym(const void* s) { void* p = nullptr; cudaGetSymbolAddress(&p, s); return p; }

extern "C" void kernel_launch(void* const* d_in, const int* in_sizes, int n_in,
                              void* d_out, int out_size)
{
    const float* x     = (const float*)d_in[0];
    const float* Wq    = (const float*)d_in[1];
    const float* Wk    = (const float*)d_in[2];
    const float* Wv    = (const float*)d_in[3];
    const float* Wo    = (const float*)d_in[4];
    const float* Wr    = (const float*)d_in[5];
    const float* Wfc   = (const float*)d_in[6];
    const float* Wproj = (const float*)d_in[7];
    float* out = (float*)d_out;

    static bool attr_set = false;
    if (!attr_set) {
        cudaFuncSetAttribute(gemm_bf16x3, cudaFuncAttributeMaxDynamicSharedMemorySize, SMEM_GEMM_BYTES);
        cudaFuncSetAttribute(attn_mma_kernel, cudaFuncAttributeMaxDynamicSharedMemorySize, ATT_SMEM);
        attr_set = true;
    }

    __nv_bfloat16* h1h = (__nv_bfloat16*)sym(g_h1_hi);
    __nv_bfloat16* h1l = (__nv_bfloat16*)sym(g_h1_lo);
    float* qk = (float*)sym(g_qk);
    __nv_bfloat16* qh = (__nv_bfloat16*)sym(g_qhi); __nv_bfloat16* ql = (__nv_bfloat16*)sym(g_qlo);
    __nv_bfloat16* kh = (__nv_bfloat16*)sym(g_khi); __nv_bfloat16* kl = (__nv_bfloat16*)sym(g_klo);
    __nv_bfloat16* vh = (__nv_bfloat16*)sym(g_vhi); __nv_bfloat16* vl = (__nv_bfloat16*)sym(g_vlo);
    __nv_bfloat16* yh = (__nv_bfloat16*)sym(g_y_hi);
    __nv_bfloat16* yl = (__nv_bfloat16*)sym(g_y_lo);
    float* x2 = (float*)sym(g_x2);
    float* h2 = (float*)sym(g_h2);
    __nv_bfloat16* h2gh = (__nv_bfloat16*)sym(g_h2g_hi);
    __nv_bfloat16* h2gl = (__nv_bfloat16*)sym(g_h2g_lo);
    __nv_bfloat16* hidh = (__nv_bfloat16*)sym(g_hid_hi);
    __nv_bfloat16* hidl = (__nv_bfloat16*)sym(g_hid_lo);
    float* outg = (float*)sym(g_outg);
    __nv_bfloat16* wqkvh = (__nv_bfloat16*)sym(g_wqkv_hi);
    __nv_bfloat16* wqkvl = (__nv_bfloat16*)sym(g_wqkv_lo);
    __nv_bfloat16* woh = (__nv_bfloat16*)sym(g_wo_hi); __nv_bfloat16* wol = (__nv_bfloat16*)sym(g_wo_lo);
    __nv_bfloat16* wfh = (__nv_bfloat16*)sym(g_wfc_hi); __nv_bfloat16* wfl = (__nv_bfloat16*)sym(g_wfc_lo);
    __nv_bfloat16* wph = (__nv_bfloat16*)sym(g_wpj_hi); __nv_bfloat16* wpl = (__nv_bfloat16*)sym(g_wpj_lo);
    int* tileE = (int*)sym(g_tileExpert);

    reset_kernel<<<(GROUP_CAP + 255) / 256, 256>>>();
    rmsnorm_kernel<<<BT, 256>>>(x, h1h, h1l);
    wconv_kernel<<<dim3(C/64, C/64, 1), 256>>>(Wq, wqkvh,         wqkvl,         C, C);
    wconv_kernel<<<dim3(C/64, C/64, 1), 256>>>(Wk, wqkvh + C*C,   wqkvl + C*C,   C, C);
    wconv_kernel<<<dim3(C/64, C/64, 1), 256>>>(Wv, wqkvh + 2*C*C, wqkvl + 2*C*C, C, C);
    wconv_kernel<<<dim3(C/64,  C/64,  1), 256>>>(Wo,    woh, wol, C,  C);
    wconv_kernel<<<dim3(FF/64, C/64,  E), 256>>>(Wfc,   wfh, wfl, C,  FF);
    wconv_kernel<<<dim3(C/64,  FF/64, E), 256>>>(Wproj, wph, wpl, FF, C);
    // fused QKV GEMM (N=3072)
    gemm_bf16x3<<<dim3(3*C/128, BT/128), 256, SMEM_GEMM_BYTES>>>(
        h1h, h1l, wqkvh, wqkvl, 0, qk, vh, vl, nullptr, nullptr, 3*C, C, 4);
    qk_rope_kernel<<<BT, 512>>>(qk, qh, ql, kh, kl);
    attn_mma_kernel<<<dim3(T/128, Bq*H), 256, ATT_SMEM>>>(
        qh, ql, kh, kl, vh, vl, yh, yl);
    gemm_bf16x3<<<dim3(C/128, BT/128), 256, SMEM_GEMM_BYTES>>>(
        yh, yl, woh, wol, 0, x2, nullptr, nullptr, x, nullptr, C, C, 1);
    rmsnorm_router_kernel<<<BT, 256>>>(x2, h2, Wr);
    offsets_kernel<<<1, 32>>>();
    assign_kernel<<<BT, 256>>>(h2);
    zero_pad_kernel<<<GROUP_CAP, 256>>>();
    gemm_bf16x3<<<dim3(FF/128, NTILES), 256, SMEM_GEMM_BYTES>>>(
        h2gh, h2gl, wfh, wfl, (size_t)FF * C, nullptr, hidh, hidl, nullptr, tileE, FF, C, 2);
    gemm_bf16x3<<<dim3(C/128, NTILES), 256, SMEM_GEMM_BYTES>>>(
        hidh, hidl, wph, wpl, (size_t)C * FF, outg, nullptr, nullptr, nullptr, tileE, C, FF, 0);
    scatter_kernel<<<GROUP_CAP, 256>>>(x2, out);
    scalars_kernel<<<1, 32>>>(out);
}

// round 10
// speedup vs baseline: 1.0502x; 1.0502x over previous
#include <cuda_runtime.h>
#include <cuda_bf16.h>
#include <cstdint>
#include <math.h>

#define Bq 2
#define T 2048
#define C 1024
#define H 16
#define D 64
#define E 4
#define BT (Bq*T)
#define FF (4*C)
#define GROUP_CAP (BT + E*128)
#define NTILES (GROUP_CAP/128)
#define EPS_RMS 1.1920929e-07f

#define SMEM_SWIZZLE_128B(b) ((b) ^ (((b) >> 3) & 0x70))

__device__ __forceinline__ uint32_t smem_to_u32(const void* p) {
    uint32_t a;
    asm("{ .reg .u64 t; cvta.to.shared.u64 t, %1; cvt.u32.u64 %0, t; }" : "=r"(a) : "l"(p));
    return a;
}
__device__ __forceinline__ void ldsm4(uint32_t* r, uint32_t addr) {
    asm volatile("ldmatrix.sync.aligned.m8n8.x4.shared.b16 {%0,%1,%2,%3}, [%4];"
                 : "=r"(r[0]), "=r"(r[1]), "=r"(r[2]), "=r"(r[3]) : "r"(addr));
}
__device__ __forceinline__ void ldsm4t(uint32_t* r, uint32_t addr) {
    asm volatile("ldmatrix.sync.aligned.m8n8.x4.trans.shared.b16 {%0,%1,%2,%3}, [%4];"
                 : "=r"(r[0]), "=r"(r[1]), "=r"(r[2]), "=r"(r[3]) : "r"(addr));
}
__device__ __forceinline__ void mma_bf16(float* c, const uint32_t* a, const uint32_t* b) {
    asm volatile("mma.sync.aligned.m16n8k16.row.col.f32.bf16.bf16.f32 "
        "{%0,%1,%2,%3}, {%4,%5,%6,%7}, {%8,%9}, {%0,%1,%2,%3};"
        : "+f"(c[0]), "+f"(c[1]), "+f"(c[2]), "+f"(c[3])
        : "r"(a[0]), "r"(a[1]), "r"(a[2]), "r"(a[3]), "r"(b[0]), "r"(b[1]));
}
__device__ __forceinline__ float ex2f(float x) {
    float y; asm("ex2.approx.ftz.f32 %0, %1;" : "=f"(y) : "f"(x)); return y;
}
#define CP16(s, g) asm volatile("cp.async.cg.shared.global [%0], [%1], 16;" \
                                :: "r"(s), "l"(g) : "memory")

// ======================= scratch (static device globals) =======================
__device__ __nv_bfloat16 g_h1_hi[BT*C], g_h1_lo[BT*C];
__device__ float g_qk[BT*2*C];
__device__ __nv_bfloat16 g_qhi[BT*C], g_qlo[BT*C];
__device__ __nv_bfloat16 g_khi[BT*C], g_klo[BT*C];
__device__ __nv_bfloat16 g_vhi[BT*C], g_vlo[BT*C];
__device__ __nv_bfloat16 g_y_hi[BT*C], g_y_lo[BT*C];
__device__ float g_x2[BT*C], g_h2[BT*C];
__device__ __nv_bfloat16 g_h2g_hi[GROUP_CAP*C], g_h2g_lo[GROUP_CAP*C];
__device__ __nv_bfloat16 g_hid_hi[(size_t)GROUP_CAP*FF], g_hid_lo[(size_t)GROUP_CAP*FF];
__device__ __nv_bfloat16 g_wqkv_hi[3*C*C], g_wqkv_lo[3*C*C];
__device__ __nv_bfloat16 g_wo_hi[C*C], g_wo_lo[C*C];
__device__ __nv_bfloat16 g_wfc_hi[(size_t)E*C*FF], g_wfc_lo[(size_t)E*C*FF];
__device__ __nv_bfloat16 g_wpj_hi[(size_t)E*FF*C], g_wpj_lo[(size_t)E*FF*C];
__device__ int   g_expert[BT];
__device__ int   g_counts[E];
__device__ int   g_cursor[E];
__device__ int   g_segstart[E];
__device__ int   g_tileExpert[NTILES];
__device__ int   g_tokenOfRow[GROUP_CAP];
__device__ double g_expsum[E];
__device__ double g_zsum;
__device__ double g_entsum;

__device__ __forceinline__ void bsplit(float v, __nv_bfloat16& h, __nv_bfloat16& l) {
    h = __float2bfloat16(v);
    l = __float2bfloat16(v - __bfloat162float(h));
}
__device__ __forceinline__ void packsplit(float v0, float v1, uint32_t& hi, uint32_t& lo) {
    __nv_bfloat16 h0, l0, h1, l1;
    bsplit(v0, h0, l0); bsplit(v1, h1, l1);
    __nv_bfloat162 hh(h0, h1), ll(l0, l1);
    hi = *reinterpret_cast<uint32_t*>(&hh);
    lo = *reinterpret_cast<uint32_t*>(&ll);
}

// ======================= small kernels =======================
__global__ void reset_kernel() {
    int i = blockIdx.x * blockDim.x + threadIdx.x;
    if (i < E) { g_counts[i] = 0; g_cursor[i] = 0; g_expsum[i] = 0.0; }
    if (i == 0) { g_zsum = 0.0; g_entsum = 0.0; }
    if (i < NTILES) g_tileExpert[i] = -1;
    if (i < GROUP_CAP) g_tokenOfRow[i] = -1;
}

// transpose + bf16-split weights: W [Kd, Nd] fp32 -> T [Nd, Kd] bf16 hi/lo
__global__ void __launch_bounds__(256) wconv_kernel(
    const float* __restrict__ W,
    __nv_bfloat16* __restrict__ Thi, __nv_bfloat16* __restrict__ Tlo,
    int Kd, int Nd) {
    __shared__ float tile[64][65];
    int b = blockIdx.z;
    const float* Wb = W + (size_t)b * Kd * Nd;
    __nv_bfloat16* Th = Thi + (size_t)b * Kd * Nd;
    __nv_bfloat16* Tl = Tlo + (size_t)b * Kd * Nd;
    int n0 = blockIdx.x * 64, k0 = blockIdx.y * 64;
    int tid = threadIdx.x;
    int lr = tid >> 4, lc = (tid & 15) * 4;
    #pragma unroll
    for (int i = 0; i < 4; i++) {
        int k = lr + i * 16;
        float4 v = *(const float4*)(Wb + (size_t)(k0 + k) * Nd + n0 + lc);
        tile[k][lc] = v.x; tile[k][lc+1] = v.y; tile[k][lc+2] = v.z; tile[k][lc+3] = v.w;
    }
    __syncthreads();
    int wn = tid >> 4, wk = (tid & 15) * 4;
    #pragma unroll
    for (int i = 0; i < 4; i++) {
        int n = wn + i * 16;
        float v0 = tile[wk][n],   v1 = tile[wk+1][n];
        float v2 = tile[wk+2][n], v3 = tile[wk+3][n];
        uint32_t h01, l01, h23, l23;
        packsplit(v0, v1, h01, l01);
        packsplit(v2, v3, h23, l23);
        size_t o = (size_t)(n0 + n) * Kd + k0 + wk;
        *(uint2*)(Th + o) = make_uint2(h01, h23);
        *(uint2*)(Tl + o) = make_uint2(l01, l23);
    }
}

// RMSNorm over C -> bf16 hi/lo pair
__global__ void rmsnorm_kernel(const float* __restrict__ in,
                               __nv_bfloat16* __restrict__ ohi, __nv_bfloat16* __restrict__ olo) {
    int t = blockIdx.x;
    const float4* ip = (const float4*)(in + (size_t)t * C);
    __shared__ float red[8];
    float4 v = ip[threadIdx.x];
    float ss = v.x*v.x + v.y*v.y + v.z*v.z + v.w*v.w;
    #pragma unroll
    for (int o = 16; o; o >>= 1) ss += __shfl_xor_sync(0xffffffffu, ss, o);
    if ((threadIdx.x & 31) == 0) red[threadIdx.x >> 5] = ss;
    __syncthreads();
    if (threadIdx.x == 0) {
        float s = 0.f;
        #pragma unroll
        for (int w = 0; w < 8; w++) s += red[w];
        red[0] = s;
    }
    __syncthreads();
    float r = rsqrtf(red[0] / (float)C + EPS_RMS);
    float4 o = make_float4(v.x*r, v.y*r, v.z*r, v.w*r);
    __nv_bfloat16 h0,l0,h1,l1,h2,l2,h3,l3;
    bsplit(o.x,h0,l0); bsplit(o.y,h1,l1); bsplit(o.z,h2,l2); bsplit(o.w,h3,l3);
    __nv_bfloat162* hp = (__nv_bfloat162*)(ohi + (size_t)t * C);
    __nv_bfloat162* lp = (__nv_bfloat162*)(olo + (size_t)t * C);
    hp[threadIdx.x*2]   = __nv_bfloat162(h0, h1);
    hp[threadIdx.x*2+1] = __nv_bfloat162(h2, h3);
    lp[threadIdx.x*2]   = __nv_bfloat162(l0, l1);
    lp[threadIdx.x*2+1] = __nv_bfloat162(l2, l3);
}

// RMSNorm fp32 out + fused router
__global__ void rmsnorm_router_kernel(const float* __restrict__ in, float* __restrict__ outf,
                                      const float* __restrict__ Wr) {
    int t = blockIdx.x;
    const float4* ip = (const float4*)(in + (size_t)t * C);
    __shared__ float red[8];
    __shared__ float lred[32];
    float4 v = ip[threadIdx.x];
    float ss = v.x*v.x + v.y*v.y + v.z*v.z + v.w*v.w;
    #pragma unroll
    for (int o = 16; o; o >>= 1) ss += __shfl_xor_sync(0xffffffffu, ss, o);
    if ((threadIdx.x & 31) == 0) red[threadIdx.x >> 5] = ss;
    __syncthreads();
    if (threadIdx.x == 0) {
        float s = 0.f;
        #pragma unroll
        for (int w = 0; w < 8; w++) s += red[w];
        red[0] = s;
    }
    __syncthreads();
    float r = rsqrtf(red[0] / (float)C + EPS_RMS);
    float4 o = make_float4(v.x*r, v.y*r, v.z*r, v.w*r);
    ((float4*)(outf + (size_t)t * C))[threadIdx.x] = o;

    int c0 = threadIdx.x * 4;
    float4 w0 = *(const float4*)(Wr + (size_t)(c0+0) * E);
    float4 w1 = *(const float4*)(Wr + (size_t)(c0+1) * E);
    float4 w2 = *(const float4*)(Wr + (size_t)(c0+2) * E);
    float4 w3 = *(const float4*)(Wr + (size_t)(c0+3) * E);
    float a0 = o.x*w0.x + o.y*w1.x + o.z*w2.x + o.w*w3.x;
    float a1 = o.x*w0.y + o.y*w1.y + o.z*w2.y + o.w*w3.y;
    float a2 = o.x*w0.z + o.y*w1.z + o.z*w2.z + o.w*w3.z;
    float a3 = o.x*w0.w + o.y*w1.w + o.z*w2.w + o.w*w3.w;
    #pragma unroll
    for (int off = 16; off; off >>= 1) {
        a0 += __shfl_xor_sync(0xffffffffu, a0, off);
        a1 += __shfl_xor_sync(0xffffffffu, a1, off);
        a2 += __shfl_xor_sync(0xffffffffu, a2, off);
        a3 += __shfl_xor_sync(0xffffffffu, a3, off);
    }
    if ((threadIdx.x & 31) == 0) {
        int w = threadIdx.x >> 5;
        lred[w*4+0] = a0; lred[w*4+1] = a1; lred[w*4+2] = a2; lred[w*4+3] = a3;
    }
    __syncthreads();
    if (threadIdx.x == 0) {
        float lg[4];
        #pragma unroll
        for (int e = 0; e < 4; e++) {
            float s = 0.f;
            #pragma unroll
            for (int w = 0; w < 8; w++) s += lred[w*4+e];
            lg[e] = s;
        }
        int arg = 0;
        #pragma unroll
        for (int e = 1; e < 4; e++) if (lg[e] > lg[arg]) arg = e;
        float m = fmaxf(fmaxf(lg[0], lg[1]), fmaxf(lg[2], lg[3]));
        float ez[4]; float sum = 0.f;
        #pragma unroll
        for (int e = 0; e < 4; e++) { ez[e] = expf(lg[e] - m); sum += ez[e]; }
        float p[4];
        #pragma unroll
        for (int e = 0; e < 4; e++) p[e] = ez[e] / sum;
        g_expert[t] = arg;
        atomicAdd(&g_counts[arg], 1);
        #pragma unroll
        for (int e = 0; e < 4; e++) atomicAdd(&g_expsum[e], (double)p[e]);
        float lse = m + logf(sum);
        atomicAdd(&g_zsum, (double)lse * (double)lse);
        float ent = 0.f;
        #pragma unroll
        for (int e = 0; e < 4; e++) ent -= p[e] * logf(p[e] + 1e-9f);
        atomicAdd(&g_entsum, (double)ent);
    }
}

// per-head RMSNorm + RoPE; reads qk buffer [BT, 2048]
__global__ void qk_rope_kernel(const float* __restrict__ qk,
                               __nv_bfloat16* __restrict__ qhi, __nv_bfloat16* __restrict__ qlo,
                               __nv_bfloat16* __restrict__ khi, __nv_bfloat16* __restrict__ klo) {
    int tok  = blockIdx.x;
    int head = threadIdx.x >> 5;
    int lane = threadIdx.x & 31;
    int tpos = tok % T;
    float ex  = (float)(2 * lane) / 64.0f;
    float inv = 1.0f / powf(10000.0f, ex);
    float ang = (float)tpos * inv;
    float c = cosf(ang), s = sinf(ang);
    size_t obase = (size_t)tok * C + head * D;
    #pragma unroll
    for (int m = 0; m < 2; m++) {
        const float* src = qk + (size_t)tok * 2048 + m * 1024 + head * D;
        __nv_bfloat16* dh = (m == 0 ? qhi : khi) + obase;
        __nv_bfloat16* dl = (m == 0 ? qlo : klo) + obase;
        float x1 = src[lane], x2 = src[lane + 32];
        float ss = x1*x1 + x2*x2;
        #pragma unroll
        for (int o = 16; o; o >>= 1) ss += __shfl_xor_sync(0xffffffffu, ss, o);
        float r = rsqrtf(ss / (float)D + EPS_RMS);
        x1 *= r; x2 *= r;
        float o1 =  x1 * c + x2 * s;
        float o2 = -x1 * s + x2 * c;
        __nv_bfloat16 h, l;
        bsplit(o1, h, l); dh[lane] = h;      dl[lane] = l;
        bsplit(o2, h, l); dh[lane + 32] = h; dl[lane + 32] = l;
    }
}

// ======================= HMMA flash attention (bf16x3) =======================
#define AT_QHI 0
#define AT_QLO 16384
#define AT_STG 32768
#define AT_STGSZ 32768
#define AT_KHI 0
#define AT_KLO 8192
#define AT_VHI 16384
#define AT_VLO 24576
#define ATT_SMEM (32768 + 2*32768)

__global__ void __launch_bounds__(256) attn_mma_kernel(
    const __nv_bfloat16* __restrict__ qhi, const __nv_bfloat16* __restrict__ qlo,
    const __nv_bfloat16* __restrict__ khi, const __nv_bfloat16* __restrict__ klo,
    const __nv_bfloat16* __restrict__ vhi, const __nv_bfloat16* __restrict__ vlo,
    __nv_bfloat16* __restrict__ yhi, __nv_bfloat16* __restrict__ ylo)
{
    extern __shared__ __align__(1024) char smem[];
    uint32_t sb = smem_to_u32(smem);
    int bh = blockIdx.y;
    int b = bh / H, hh = bh % H;
    int qb = blockIdx.x;
    int q0 = qb * 128;
    int tid = threadIdx.x, wid = tid >> 5, lid = tid & 31;
    int nkt = 2 * qb + 2;

    #pragma unroll
    for (int i = 0; i < 4; i++) {
        int lin = tid + i * 256;
        int r = lin >> 3, ch = lin & 7;
        uint32_t so = SMEM_SWIZZLE_128B((uint32_t)(r * 128 + ch * 16));
        size_t g = (size_t)(b*T + q0 + r) * C + hh * D + ch * 8;
        CP16(sb + AT_QHI + so, qhi + g);
        CP16(sb + AT_QLO + so, qlo + g);
    }
    asm volatile("cp.async.commit_group;" ::: "memory");
    #pragma unroll
    for (int i = 0; i < 2; i++) {
        int lin = tid + i * 256;
        int r = lin >> 3, ch = lin & 7;
        uint32_t so = SMEM_SWIZZLE_128B((uint32_t)(r * 128 + ch * 16));
        size_t g = (size_t)(b*T + r) * C + hh * D + ch * 8;
        uint32_t st = sb + AT_STG;
        CP16(st + AT_KHI + so, khi + g);
        CP16(st + AT_KLO + so, klo + g);
        CP16(st + AT_VHI + so, vhi + g);
        CP16(st + AT_VLO + so, vlo + g);
    }
    asm volatile("cp.async.commit_group;" ::: "memory");

    uint32_t qa_hi[4][4], qa_lo[4][4];
    float oac[8][4];
    #pragma unroll
    for (int j = 0; j < 8; j++)
        #pragma unroll
        for (int r = 0; r < 4; r++) oac[j][r] = 0.f;
    float m0 = -1e30f, m1 = -1e30f, l0 = 0.f, l1 = 0.f;

    int off = lid & 7, part = lid >> 3;
    int qr = lid >> 2, qc = (lid & 3) * 2;
    const float SC2 = 0.18033688011112042f;

    for (int kt = 0; kt < nkt; kt++) {
        if (kt + 1 < nkt) {
            #pragma unroll
            for (int i = 0; i < 2; i++) {
                int lin = tid + i * 256;
                int r = lin >> 3, ch = lin & 7;
                uint32_t so = SMEM_SWIZZLE_128B((uint32_t)(r * 128 + ch * 16));
                size_t g = (size_t)(b*T + (kt + 1) * 64 + r) * C + hh * D + ch * 8;
                uint32_t st = sb + AT_STG + (uint32_t)((kt + 1) & 1) * AT_STGSZ;
                CP16(st + AT_KHI + so, khi + g);
                CP16(st + AT_KLO + so, klo + g);
                CP16(st + AT_VHI + so, vhi + g);
                CP16(st + AT_VLO + so, vlo + g);
            }
            asm volatile("cp.async.commit_group;" ::: "memory");
            asm volatile("cp.async.wait_group 1;" ::: "memory");
        } else {
            asm volatile("cp.async.wait_group 0;" ::: "memory");
        }
        __syncthreads();

        if (kt == 0) {
            #pragma unroll
            for (int kk = 0; kk < 4; kk++) {
                int row = wid * 16 + (part & 1) * 8 + off;
                int colb = kk * 32 + (part & 2) * 8;
                uint32_t so = SMEM_SWIZZLE_128B((uint32_t)(row * 128 + colb));
                ldsm4(qa_hi[kk], sb + AT_QHI + so);
                ldsm4(qa_lo[kk], sb + AT_QLO + so);
            }
        }

        uint32_t st = sb + AT_STG + (uint32_t)(kt & 1) * AT_STGSZ;

        float s[8][4];
        #pragma unroll
        for (int j = 0; j < 8; j++)
            #pragma unroll
            for (int r = 0; r < 4; r++) s[j][r] = 0.f;
        #pragma unroll
        for (int kk = 0; kk < 4; kk++) {
            #pragma unroll
            for (int jj = 0; jj < 4; jj++) {
                int row = jj * 16 + (part & 2) * 4 + off;
                int colb = kk * 32 + (part & 1) * 16;
                uint32_t so = SMEM_SWIZZLE_128B((uint32_t)(row * 128 + colb));
                uint32_t kh[4], kl[4];
                ldsm4(kh, st + AT_KHI + so);
                ldsm4(kl, st + AT_KLO + so);
                mma_bf16(s[2*jj],     qa_hi[kk], kh);
                mma_bf16(s[2*jj],     qa_hi[kk], kl);
                mma_bf16(s[2*jj],     qa_lo[kk], kh);
                mma_bf16(s[2*jj+1],   qa_hi[kk], kh + 2);
                mma_bf16(s[2*jj+1],   qa_hi[kk], kl + 2);
                mma_bf16(s[2*jj+1],   qa_lo[kk], kh + 2);
            }
        }

        bool domask = (kt >= nkt - 2);
        #pragma unroll
        for (int j = 0; j < 8; j++) {
            #pragma unroll
            for (int r = 0; r < 4; r++) {
                float v = s[j][r] * SC2;
                if (domask) {
                    int key = kt * 64 + j * 8 + qc + (r & 1);
                    int row = q0 + wid * 16 + qr + (r & 2) * 4;
                    if (key > row) v = -1e30f;
                }
                s[j][r] = v;
            }
        }

        float mx0 = -1e30f, mx1 = -1e30f;
        #pragma unroll
        for (int j = 0; j < 8; j++) {
            mx0 = fmaxf(mx0, fmaxf(s[j][0], s[j][1]));
            mx1 = fmaxf(mx1, fmaxf(s[j][2], s[j][3]));
        }
        mx0 = fmaxf(mx0, __shfl_xor_sync(0xffffffffu, mx0, 1));
        mx0 = fmaxf(mx0, __shfl_xor_sync(0xffffffffu, mx0, 2));
        mx1 = fmaxf(mx1, __shfl_xor_sync(0xffffffffu, mx1, 1));
        mx1 = fmaxf(mx1, __shfl_xor_sync(0xffffffffu, mx1, 2));
        float mn0 = fmaxf(m0, mx0), mn1 = fmaxf(m1, mx1);
        float al0 = ex2f(m0 - mn0), al1 = ex2f(m1 - mn1);
        float sm0 = 0.f, sm1 = 0.f;
        #pragma unroll
        for (int j = 0; j < 8; j++) {
            s[j][0] = ex2f(s[j][0] - mn0); sm0 += s[j][0];
            s[j][1] = ex2f(s[j][1] - mn0); sm0 += s[j][1];
            s[j][2] = ex2f(s[j][2] - mn1); sm1 += s[j][2];
            s[j][3] = ex2f(s[j][3] - mn1); sm1 += s[j][3];
        }
        sm0 += __shfl_xor_sync(0xffffffffu, sm0, 1);
        sm0 += __shfl_xor_sync(0xffffffffu, sm0, 2);
        sm1 += __shfl_xor_sync(0xffffffffu, sm1, 1);
        sm1 += __shfl_xor_sync(0xffffffffu, sm1, 2);
        l0 = l0 * al0 + sm0;  l1 = l1 * al1 + sm1;
        m0 = mn0;  m1 = mn1;
        #pragma unroll
        for (int j = 0; j < 8; j++) {
            oac[j][0] *= al0; oac[j][1] *= al0;
            oac[j][2] *= al1; oac[j][3] *= al1;
        }

        #pragma unroll
        for (int kk = 0; kk < 4; kk++) {
            uint32_t pah[4], pal[4];
            packsplit(s[2*kk][0],   s[2*kk][1],   pah[0], pal[0]);
            packsplit(s[2*kk][2],   s[2*kk][3],   pah[1], pal[1]);
            packsplit(s[2*kk+1][0], s[2*kk+1][1], pah[2], pal[2]);
            packsplit(s[2*kk+1][2], s[2*kk+1][3], pah[3], pal[3]);
            #pragma unroll
            for (int jj = 0; jj < 4; jj++) {
                int row = kk * 16 + (part & 1) * 8 + off;
                int colb = jj * 32 + (part & 2) * 8;
                uint32_t so = SMEM_SWIZZLE_128B((uint32_t)(row * 128 + colb));
                uint32_t vh[4], vl[4];
                ldsm4t(vh, st + AT_VHI + so);
                ldsm4t(vl, st + AT_VLO + so);
                mma_bf16(oac[2*jj],   pah, vh);
                mma_bf16(oac[2*jj],   pah, vl);
                mma_bf16(oac[2*jj],   pal, vh);
                mma_bf16(oac[2*jj+1], pah, vh + 2);
                mma_bf16(oac[2*jj+1], pah, vl + 2);
                mma_bf16(oac[2*jj+1], pal, vh + 2);
            }
        }
        __syncthreads();
    }

    float inv0 = 1.f / l0, inv1 = 1.f / l1;
    #pragma unroll
    for (int j = 0; j < 8; j++) {
        size_t i0 = (size_t)(b*T + q0 + wid*16 + qr) * C + hh * D + j * 8 + qc;
        size_t i1 = (size_t)(b*T + q0 + wid*16 + qr + 8) * C + hh * D + j * 8 + qc;
        uint32_t ph, pl;
        packsplit(oac[j][0] * inv0, oac[j][1] * inv0, ph, pl);
        *(uint32_t*)(yhi + i0) = ph;  *(uint32_t*)(ylo + i0) = pl;
        packsplit(oac[j][2] * inv1, oac[j][3] * inv1, ph, pl);
        *(uint32_t*)(yhi + i1) = ph;  *(uint32_t*)(ylo + i1) = pl;
    }
}

// ======================= HMMA bf16x3 GEMM — 128x256 block tile (R8 config) =======================
// warp tile 64x64, 8 warps (2 m x 4 n). ldsm:mma = 1:6.
// epi: 0 fp32; 1 fp32+resid; 2 relu(acc)^2 -> bf16 pair; 3 acc -> bf16 pair;
//      4 fused QKV: cols [0,2048) fp32 stride 2048, cols [2048,3072) bf16 pair stride 1024
//      5 MoE scatter: out[token*N+col] = acc + resid[token*N+col], token = tokOfRow[row]
#define KTILE 64
#define W_AH 0
#define W_AL 16384
#define W_BH 32768
#define W_BL 65536
#define W_STAGE 98304
#define SMEM_GEMM_BYTES (2*W_STAGE)

__global__ void __launch_bounds__(256, 1) gemm_bf16x3(
    const __nv_bfloat16* __restrict__ Ahi, const __nv_bfloat16* __restrict__ Alo,
    const __nv_bfloat16* __restrict__ Bhi, const __nv_bfloat16* __restrict__ Blo,
    size_t bstride,
    float* __restrict__ Cout,
    __nv_bfloat16* __restrict__ Ohi, __nv_bfloat16* __restrict__ Olo,
    const float* __restrict__ resid,
    const int* __restrict__ tileExpert,
    const int* __restrict__ tokOfRow,
    int N, int K, int epi)
{
    extern __shared__ __align__(1024) char smem[];
    int by = blockIdx.y, bx = blockIdx.x;
    int e = 0;
    if (tileExpert) { e = tileExpert[by]; if (e < 0) return; }
    const __nv_bfloat16* Bh = Bhi + (size_t)e * bstride;
    const __nv_bfloat16* Bl = Blo + (size_t)e * bstride;

    uint32_t sb = smem_to_u32(smem);
    int tid = threadIdx.x, wid = tid >> 5, lid = tid & 31;
    int wm = wid & 1, wn = wid >> 1;
    int row0 = by * 128, col0 = bx * 256;
    int nkt = K / KTILE;

    float acc[4][8][4];
    #pragma unroll
    for (int i = 0; i < 4; i++)
        #pragma unroll
        for (int j = 0; j < 8; j++)
            #pragma unroll
            for (int r = 0; r < 4; r++) acc[i][j][r] = 0.f;

    int lr = tid >> 3, lc = tid & 7;

    // preload stage 0
    {
        #pragma unroll
        for (int i = 0; i < 4; i++) {               // A: 128 rows
            int r = lr + i * 32;
            uint32_t so = SMEM_SWIZZLE_128B((uint32_t)(r * 128 + lc * 16));
            size_t ga = (size_t)(row0 + r) * K + lc * 8;
            CP16(sb + W_AH + so, Ahi + ga);
            CP16(sb + W_AL + so, Alo + ga);
        }
        #pragma unroll
        for (int i = 0; i < 8; i++) {               // B: 256 rows
            int r = lr + i * 32;
            uint32_t so = SMEM_SWIZZLE_128B((uint32_t)(r * 128 + lc * 16));
            size_t gb = (size_t)(col0 + r) * K + lc * 8;
            CP16(sb + W_BH + so, Bh + gb);
            CP16(sb + W_BL + so, Bl + gb);
        }
        asm volatile("cp.async.commit_group;" ::: "memory");
    }

    for (int kt = 0; kt < nkt; kt++) {
        uint32_t cur = (uint32_t)(kt & 1) * W_STAGE;
        if (kt + 1 < nkt) {
            uint32_t nxt = (uint32_t)((kt + 1) & 1) * W_STAGE;
            int k0 = (kt + 1) * KTILE;
            #pragma unroll
            for (int i = 0; i < 4; i++) {
                int r = lr + i * 32;
                uint32_t so = SMEM_SWIZZLE_128B((uint32_t)(r * 128 + lc * 16));
                size_t ga = (size_t)(row0 + r) * K + k0 + lc * 8;
                CP16(sb + nxt + W_AH + so, Ahi + ga);
                CP16(sb + nxt + W_AL + so, Alo + ga);
            }
            #pragma unroll
            for (int i = 0; i < 8; i++) {
                int r = lr + i * 32;
                uint32_t so = SMEM_SWIZZLE_128B((uint32_t)(r * 128 + lc * 16));
                size_t gb = (size_t)(col0 + r) * K + k0 + lc * 8;
                CP16(sb + nxt + W_BH + so, Bh + gb);
                CP16(sb + nxt + W_BL + so, Bl + gb);
            }
            asm volatile("cp.async.commit_group;" ::: "memory");
            asm volatile("cp.async.wait_group 1;" ::: "memory");
        } else {
            asm volatile("cp.async.wait_group 0;" ::: "memory");
        }
        __syncthreads();

        uint32_t sAH = sb + cur + W_AH, sAL = sb + cur + W_AL;
        uint32_t sBH = sb + cur + W_BH, sBL = sb + cur + W_BL;
        #pragma unroll
        for (int kk = 0; kk < 4; kk++) {
            int colb = (kk * 16 + (lid >> 4) * 8) * 2;
            uint32_t a_hi[4][4], a_lo[4][4];
            #pragma unroll
            for (int mf = 0; mf < 4; mf++) {
                int rowm = wm * 64 + mf * 16 + (lid & 15);
                uint32_t so = SMEM_SWIZZLE_128B((uint32_t)(rowm * 128 + colb));
                ldsm4(a_hi[mf], sAH + so);
                ldsm4(a_lo[mf], sAL + so);
            }
            uint32_t b_hi[8][2], b_lo[8][2];
            #pragma unroll
            for (int g = 0; g < 4; g++) {
                int rown = wn * 64 + g * 16 + (lid & 15);
                uint32_t so = SMEM_SWIZZLE_128B((uint32_t)(rown * 128 + colb));
                uint32_t r4[4];
                ldsm4(r4, sBH + so);
                b_hi[2*g][0] = r4[0]; b_hi[2*g+1][0] = r4[1];
                b_hi[2*g][1] = r4[2]; b_hi[2*g+1][1] = r4[3];
                ldsm4(r4, sBL + so);
                b_lo[2*g][0] = r4[0]; b_lo[2*g+1][0] = r4[1];
                b_lo[2*g][1] = r4[2]; b_lo[2*g+1][1] = r4[3];
            }
            #pragma unroll
            for (int mf = 0; mf < 4; mf++)
                #pragma unroll
                for (int nf = 0; nf < 8; nf++) {
                    mma_bf16(acc[mf][nf], a_hi[mf], b_hi[nf]);
                    mma_bf16(acc[mf][nf], a_hi[mf], b_lo[nf]);
                    mma_bf16(acc[mf][nf], a_lo[mf], b_hi[nf]);
                }
        }
        __syncthreads();
    }

    int qr = lid >> 2, qc = (lid & 3) * 2;
    #pragma unroll
    for (int mf = 0; mf < 4; mf++) {
        #pragma unroll
        for (int nf = 0; nf < 8; nf++) {
            float* cc = acc[mf][nf];
            int col = col0 + wn * 64 + nf * 8 + qc;
            #pragma unroll
            for (int half = 0; half < 2; half++) {
                int row = row0 + wm * 64 + mf * 16 + qr + half * 8;
                float v0 = cc[2*half], v1 = cc[2*half + 1];
                if (epi == 0) {
                    size_t idx = (size_t)row * N + col;
                    *(float2*)(Cout + idx) = make_float2(v0, v1);
                } else if (epi == 1) {
                    size_t idx = (size_t)row * N + col;
                    float2 rr = *(const float2*)(resid + idx);
                    *(float2*)(Cout + idx) = make_float2(v0 + rr.x, v1 + rr.y);
                } else if (epi == 4) {
                    if (col < 2048) {
                        size_t idx = (size_t)row * 2048 + col;
                        *(float2*)(Cout + idx) = make_float2(v0, v1);
                    } else {
                        size_t idx = (size_t)row * 1024 + (col - 2048);
                        uint32_t ph, pl;
                        packsplit(v0, v1, ph, pl);
                        *(uint32_t*)(Ohi + idx) = ph;
                        *(uint32_t*)(Olo + idx) = pl;
                    }
                } else if (epi == 5) {
                    int t = tokOfRow[row];
                    if (t >= 0) {
                        size_t idx = (size_t)t * N + col;
                        float2 rr = *(const float2*)(resid + idx);
                        *(float2*)(Cout + idx) = make_float2(v0 + rr.x, v1 + rr.y);
                    }
                } else {
                    if (epi == 2) {
                        v0 = fmaxf(v0, 0.f); v0 *= v0;
                        v1 = fmaxf(v1, 0.f); v1 *= v1;
                    }
                    size_t idx = (size_t)row * N + col;
                    uint32_t ph, pl;
                    packsplit(v0, v1, ph, pl);
                    *(uint32_t*)(Ohi + idx) = ph;
                    *(uint32_t*)(Olo + idx) = pl;
                }
            }
        }
    }
}

// ======================= grouping / scalars =======================
__global__ void offsets_kernel() {
    if (threadIdx.x == 0 && blockIdx.x == 0) {
        int off = 0;
        for (int e = 0; e < E; e++) {
            g_segstart[e] = off;
            int padded = (g_counts[e] + 127) & ~127;
            for (int i = 0; i < padded / 128; i++)
                g_tileExpert[off / 128 + i] = e;
            off += padded;
        }
    }
}

__global__ void assign_kernel(const float* __restrict__ h2) {
    int t = blockIdx.x;
    __shared__ int slot_s;
    if (threadIdx.x == 0) {
        int e = g_expert[t];
        int slot = g_segstart[e] + atomicAdd(&g_cursor[e], 1);
        g_tokenOfRow[slot] = t;
        slot_s = slot;
    }
    __syncthreads();
    int s = slot_s;
    float4 v = ((const float4*)(h2 + (size_t)t * C))[threadIdx.x];
    __nv_bfloat16 h0,l0,h1,l1,h2b,l2,h3,l3;
    bsplit(v.x,h0,l0); bsplit(v.y,h1,l1); bsplit(v.z,h2b,l2); bsplit(v.w,h3,l3);
    __nv_bfloat162* hp = (__nv_bfloat162*)(g_h2g_hi + (size_t)s * C);
    __nv_bfloat162* lp = (__nv_bfloat162*)(g_h2g_lo + (size_t)s * C);
    hp[threadIdx.x*2]   = __nv_bfloat162(h0, h1);
    hp[threadIdx.x*2+1] = __nv_bfloat162(h2b, h3);
    lp[threadIdx.x*2]   = __nv_bfloat162(l0, l1);
    lp[threadIdx.x*2+1] = __nv_bfloat162(l2, l3);
}

__global__ void scalars_kernel(float* __restrict__ out) {
    if (threadIdx.x == 0 && blockIdx.x == 0) {
        const double NTOK = (double)BT;
        double aux = 0.0;
        for (int e = 0; e < E; e++) {
            double actual = (double)g_counts[e] / NTOK;
            double expd   = g_expsum[e] / NTOK;
            aux += actual * expd;
        }
        size_t base = (size_t)BT * C;
        out[base + 0] = (float)((double)E * aux);
        out[base + 1] = (float)(g_zsum / NTOK);
        out[base + 2] = (float)((g_entsum / NTOK) / log((double)E));
        for (int e = 0; e < E; e++)
            out[base + 3 + e] = (float)((double)g_counts[e] / NTOK);
    }
}

// ======================= launch =======================
static void* sym(const void* s) { void* p = nullptr; cudaGetSymbolAddress(&p, s); return p; }

extern "C" void kernel_launch(void* const* d_in, const int* in_sizes, int n_in,
                              void* d_out, int out_size)
{
    const float* x     = (const float*)d_in[0];
    const float* Wq    = (const float*)d_in[1];
    const float* Wk    = (const float*)d_in[2];
    const float* Wv    = (const float*)d_in[3];
    const float* Wo    = (const float*)d_in[4];
    const float* Wr    = (const float*)d_in[5];
    const float* Wfc   = (const float*)d_in[6];
    const float* Wproj = (const float*)d_in[7];
    float* out = (float*)d_out;

    static bool attr_set = false;
    if (!attr_set) {
        cudaFuncSetAttribute(gemm_bf16x3, cudaFuncAttributeMaxDynamicSharedMemorySize, SMEM_GEMM_BYTES);
        cudaFuncSetAttribute(attn_mma_kernel, cudaFuncAttributeMaxDynamicSharedMemorySize, ATT_SMEM);
        attr_set = true;
    }

    __nv_bfloat16* h1h = (__nv_bfloat16*)sym(g_h1_hi);
    __nv_bfloat16* h1l = (__nv_bfloat16*)sym(g_h1_lo);
    float* qk = (float*)sym(g_qk);
    __nv_bfloat16* qh = (__nv_bfloat16*)sym(g_qhi); __nv_bfloat16* ql = (__nv_bfloat16*)sym(g_qlo);
    __nv_bfloat16* kh = (__nv_bfloat16*)sym(g_khi); __nv_bfloat16* kl = (__nv_bfloat16*)sym(g_klo);
    __nv_bfloat16* vh = (__nv_bfloat16*)sym(g_vhi); __nv_bfloat16* vl = (__nv_bfloat16*)sym(g_vlo);
    __nv_bfloat16* yh = (__nv_bfloat16*)sym(g_y_hi);
    __nv_bfloat16* yl = (__nv_bfloat16*)sym(g_y_lo);
    float* x2 = (float*)sym(g_x2);
    float* h2 = (float*)sym(g_h2);
    __nv_bfloat16* h2gh = (__nv_bfloat16*)sym(g_h2g_hi);
    __nv_bfloat16* h2gl = (__nv_bfloat16*)sym(g_h2g_lo);
    __nv_bfloat16* hidh = (__nv_bfloat16*)sym(g_hid_hi);
    __nv_bfloat16* hidl = (__nv_bfloat16*)sym(g_hid_lo);
    __nv_bfloat16* wqkvh = (__nv_bfloat16*)sym(g_wqkv_hi);
    __nv_bfloat16* wqkvl = (__nv_bfloat16*)sym(g_wqkv_lo);
    __nv_bfloat16* woh = (__nv_bfloat16*)sym(g_wo_hi); __nv_bfloat16* wol = (__nv_bfloat16*)sym(g_wo_lo);
    __nv_bfloat16* wfh = (__nv_bfloat16*)sym(g_wfc_hi); __nv_bfloat16* wfl = (__nv_bfloat16*)sym(g_wfc_lo);
    __nv_bfloat16* wph = (__nv_bfloat16*)sym(g_wpj_hi); __nv_bfloat16* wpl = (__nv_bfloat16*)sym(g_wpj_lo);
    int* tileE = (int*)sym(g_tileExpert);
    int* tokR  = (int*)sym(g_tokenOfRow);

    reset_kernel<<<(GROUP_CAP + 255) / 256, 256>>>();
    rmsnorm_kernel<<<BT, 256>>>(x, h1h, h1l);
    wconv_kernel<<<dim3(C/64, C/64, 1), 256>>>(Wq, wqkvh,         wqkvl,         C, C);
    wconv_kernel<<<dim3(C/64, C/64, 1), 256>>>(Wk, wqkvh + C*C,   wqkvl + C*C,   C, C);
    wconv_kernel<<<dim3(C/64, C/64, 1), 256>>>(Wv, wqkvh + 2*C*C, wqkvl + 2*C*C, C, C);
    wconv_kernel<<<dim3(C/64,  C/64,  1), 256>>>(Wo,    woh, wol, C,  C);
    wconv_kernel<<<dim3(FF/64, C/64,  E), 256>>>(Wfc,   wfh, wfl, C,  FF);
    wconv_kernel<<<dim3(C/64,  FF/64, E), 256>>>(Wproj, wph, wpl, FF, C);
    // fused QKV GEMM (N=3072)
    gemm_bf16x3<<<dim3(3*C/256, BT/128), 256, SMEM_GEMM_BYTES>>>(
        h1h, h1l, wqkvh, wqkvl, 0, qk, vh, vl, nullptr, nullptr, nullptr, 3*C, C, 4);
    qk_rope_kernel<<<BT, 512>>>(qk, qh, ql, kh, kl);
    attn_mma_kernel<<<dim3(T/128, Bq*H), 256, ATT_SMEM>>>(
        qh, ql, kh, kl, vh, vl, yh, yl);
    gemm_bf16x3<<<dim3(C/256, BT/128), 256, SMEM_GEMM_BYTES>>>(
        yh, yl, woh, wol, 0, x2, nullptr, nullptr, x, nullptr, nullptr, C, C, 1);
    rmsnorm_router_kernel<<<BT, 256>>>(x2, h2, Wr);
    offsets_kernel<<<1, 32>>>();
    assign_kernel<<<BT, 256>>>(h2);
    gemm_bf16x3<<<dim3(FF/256, NTILES), 256, SMEM_GEMM_BYTES>>>(
        h2gh, h2gl, wfh, wfl, (size_t)FF * C, nullptr, hidh, hidl, nullptr, tileE, nullptr, FF, C, 2);
    // MoE proj GEMM with fused residual scatter: out[token] = acc + x2[token]
    gemm_bf16x3<<<dim3(C/256, NTILES), 256, SMEM_GEMM_BYTES>>>(
        hidh, hidl, wph, wpl, (size_t)C * FF, out, nullptr, nullptr, x2, tileE, tokR, C, FF, 5);
    scalars_kernel<<<1, 32>>>(out);
}

// round 11
// speedup vs baseline: 1.0591x; 1.0085x over previous
#include <cuda_runtime.h>
#include <cuda_bf16.h>
#include <cstdint>
#include <math.h>

#define Bq 2
#define T 2048
#define C 1024
#define H 16
#define D 64
#define E 4
#define BT (Bq*T)
#define FF (4*C)
#define GROUP_CAP (BT + E*128)
#define NTILES (GROUP_CAP/128)
#define EPS_RMS 1.1920929e-07f

#define SMEM_SWIZZLE_128B(b) ((b) ^ (((b) >> 3) & 0x70))

__device__ __forceinline__ uint32_t smem_to_u32(const void* p) {
    uint32_t a;
    asm("{ .reg .u64 t; cvta.to.shared.u64 t, %1; cvt.u32.u64 %0, t; }" : "=r"(a) : "l"(p));
    return a;
}
__device__ __forceinline__ void ldsm4(uint32_t* r, uint32_t addr) {
    asm volatile("ldmatrix.sync.aligned.m8n8.x4.shared.b16 {%0,%1,%2,%3}, [%4];"
                 : "=r"(r[0]), "=r"(r[1]), "=r"(r[2]), "=r"(r[3]) : "r"(addr));
}
__device__ __forceinline__ void ldsm4t(uint32_t* r, uint32_t addr) {
    asm volatile("ldmatrix.sync.aligned.m8n8.x4.trans.shared.b16 {%0,%1,%2,%3}, [%4];"
                 : "=r"(r[0]), "=r"(r[1]), "=r"(r[2]), "=r"(r[3]) : "r"(addr));
}
__device__ __forceinline__ void mma_bf16(float* c, const uint32_t* a, const uint32_t* b) {
    asm volatile("mma.sync.aligned.m16n8k16.row.col.f32.bf16.bf16.f32 "
        "{%0,%1,%2,%3}, {%4,%5,%6,%7}, {%8,%9}, {%0,%1,%2,%3};"
        : "+f"(c[0]), "+f"(c[1]), "+f"(c[2]), "+f"(c[3])
        : "r"(a[0]), "r"(a[1]), "r"(a[2]), "r"(a[3]), "r"(b[0]), "r"(b[1]));
}
__device__ __forceinline__ float ex2f(float x) {
    float y; asm("ex2.approx.ftz.f32 %0, %1;" : "=f"(y) : "f"(x)); return y;
}
#define CP16(s, g) asm volatile("cp.async.cg.shared.global [%0], [%1], 16;" \
                                :: "r"(s), "l"(g) : "memory")

// ======================= scratch (static device globals) =======================
__device__ __nv_bfloat16 g_h1_hi[BT*C], g_h1_lo[BT*C];
__device__ float g_qk[BT*2*C];
__device__ __nv_bfloat16 g_qhi[BT*C], g_qlo[BT*C];
__device__ __nv_bfloat16 g_khi[BT*C], g_klo[BT*C];
__device__ __nv_bfloat16 g_vhi[BT*C], g_vlo[BT*C];
__device__ __nv_bfloat16 g_y_hi[BT*C], g_y_lo[BT*C];
__device__ float g_x2[BT*C], g_h2[BT*C];
__device__ __nv_bfloat16 g_h2g_hi[GROUP_CAP*C], g_h2g_lo[GROUP_CAP*C];
__device__ __nv_bfloat16 g_hid_hi[(size_t)GROUP_CAP*FF], g_hid_lo[(size_t)GROUP_CAP*FF];
__device__ __nv_bfloat16 g_wqkv_hi[3*C*C], g_wqkv_lo[3*C*C];
__device__ __nv_bfloat16 g_wo_hi[C*C], g_wo_lo[C*C];
__device__ __nv_bfloat16 g_wfc_hi[(size_t)E*C*FF], g_wfc_lo[(size_t)E*C*FF];
__device__ __nv_bfloat16 g_wpj_hi[(size_t)E*FF*C], g_wpj_lo[(size_t)E*FF*C];
__device__ int   g_expert[BT];
__device__ int   g_counts[E];
__device__ int   g_cursor[E];
__device__ int   g_segstart[E];
__device__ int   g_tileExpert[NTILES];
__device__ int   g_tokenOfRow[GROUP_CAP];
__device__ double g_expsum[E];
__device__ double g_zsum;
__device__ double g_entsum;

__device__ __forceinline__ void bsplit(float v, __nv_bfloat16& h, __nv_bfloat16& l) {
    h = __float2bfloat16(v);
    l = __float2bfloat16(v - __bfloat162float(h));
}
__device__ __forceinline__ void packsplit(float v0, float v1, uint32_t& hi, uint32_t& lo) {
    __nv_bfloat16 h0, l0, h1, l1;
    bsplit(v0, h0, l0); bsplit(v1, h1, l1);
    __nv_bfloat162 hh(h0, h1), ll(l0, l1);
    hi = *reinterpret_cast<uint32_t*>(&hh);
    lo = *reinterpret_cast<uint32_t*>(&ll);
}

// ======================= small kernels =======================
__global__ void reset_kernel() {
    int i = blockIdx.x * blockDim.x + threadIdx.x;
    if (i < E) { g_counts[i] = 0; g_cursor[i] = 0; g_expsum[i] = 0.0; }
    if (i == 0) { g_zsum = 0.0; g_entsum = 0.0; }
    if (i < NTILES) g_tileExpert[i] = -1;
    if (i < GROUP_CAP) g_tokenOfRow[i] = -1;
}

// transpose + bf16-split weights: W [Kd, Nd] fp32 -> T [Nd, Kd] bf16 hi/lo
__global__ void __launch_bounds__(256) wconv_kernel(
    const float* __restrict__ W,
    __nv_bfloat16* __restrict__ Thi, __nv_bfloat16* __restrict__ Tlo,
    int Kd, int Nd) {
    __shared__ float tile[64][65];
    int b = blockIdx.z;
    const float* Wb = W + (size_t)b * Kd * Nd;
    __nv_bfloat16* Th = Thi + (size_t)b * Kd * Nd;
    __nv_bfloat16* Tl = Tlo + (size_t)b * Kd * Nd;
    int n0 = blockIdx.x * 64, k0 = blockIdx.y * 64;
    int tid = threadIdx.x;
    int lr = tid >> 4, lc = (tid & 15) * 4;
    #pragma unroll
    for (int i = 0; i < 4; i++) {
        int k = lr + i * 16;
        float4 v = *(const float4*)(Wb + (size_t)(k0 + k) * Nd + n0 + lc);
        tile[k][lc] = v.x; tile[k][lc+1] = v.y; tile[k][lc+2] = v.z; tile[k][lc+3] = v.w;
    }
    __syncthreads();
    int wn = tid >> 4, wk = (tid & 15) * 4;
    #pragma unroll
    for (int i = 0; i < 4; i++) {
        int n = wn + i * 16;
        float v0 = tile[wk][n],   v1 = tile[wk+1][n];
        float v2 = tile[wk+2][n], v3 = tile[wk+3][n];
        uint32_t h01, l01, h23, l23;
        packsplit(v0, v1, h01, l01);
        packsplit(v2, v3, h23, l23);
        size_t o = (size_t)(n0 + n) * Kd + k0 + wk;
        *(uint2*)(Th + o) = make_uint2(h01, h23);
        *(uint2*)(Tl + o) = make_uint2(l01, l23);
    }
}

// RMSNorm over C -> bf16 hi/lo pair
__global__ void rmsnorm_kernel(const float* __restrict__ in,
                               __nv_bfloat16* __restrict__ ohi, __nv_bfloat16* __restrict__ olo) {
    int t = blockIdx.x;
    const float4* ip = (const float4*)(in + (size_t)t * C);
    __shared__ float red[8];
    float4 v = ip[threadIdx.x];
    float ss = v.x*v.x + v.y*v.y + v.z*v.z + v.w*v.w;
    #pragma unroll
    for (int o = 16; o; o >>= 1) ss += __shfl_xor_sync(0xffffffffu, ss, o);
    if ((threadIdx.x & 31) == 0) red[threadIdx.x >> 5] = ss;
    __syncthreads();
    if (threadIdx.x == 0) {
        float s = 0.f;
        #pragma unroll
        for (int w = 0; w < 8; w++) s += red[w];
        red[0] = s;
    }
    __syncthreads();
    float r = rsqrtf(red[0] / (float)C + EPS_RMS);
    float4 o = make_float4(v.x*r, v.y*r, v.z*r, v.w*r);
    __nv_bfloat16 h0,l0,h1,l1,h2,l2,h3,l3;
    bsplit(o.x,h0,l0); bsplit(o.y,h1,l1); bsplit(o.z,h2,l2); bsplit(o.w,h3,l3);
    __nv_bfloat162* hp = (__nv_bfloat162*)(ohi + (size_t)t * C);
    __nv_bfloat162* lp = (__nv_bfloat162*)(olo + (size_t)t * C);
    hp[threadIdx.x*2]   = __nv_bfloat162(h0, h1);
    hp[threadIdx.x*2+1] = __nv_bfloat162(h2, h3);
    lp[threadIdx.x*2]   = __nv_bfloat162(l0, l1);
    lp[threadIdx.x*2+1] = __nv_bfloat162(l2, l3);
}

// RMSNorm fp32 out + fused router
__global__ void rmsnorm_router_kernel(const float* __restrict__ in, float* __restrict__ outf,
                                      const float* __restrict__ Wr) {
    int t = blockIdx.x;
    const float4* ip = (const float4*)(in + (size_t)t * C);
    __shared__ float red[8];
    __shared__ float lred[32];
    float4 v = ip[threadIdx.x];
    float ss = v.x*v.x + v.y*v.y + v.z*v.z + v.w*v.w;
    #pragma unroll
    for (int o = 16; o; o >>= 1) ss += __shfl_xor_sync(0xffffffffu, ss, o);
    if ((threadIdx.x & 31) == 0) red[threadIdx.x >> 5] = ss;
    __syncthreads();
    if (threadIdx.x == 0) {
        float s = 0.f;
        #pragma unroll
        for (int w = 0; w < 8; w++) s += red[w];
        red[0] = s;
    }
    __syncthreads();
    float r = rsqrtf(red[0] / (float)C + EPS_RMS);
    float4 o = make_float4(v.x*r, v.y*r, v.z*r, v.w*r);
    ((float4*)(outf + (size_t)t * C))[threadIdx.x] = o;

    int c0 = threadIdx.x * 4;
    float4 w0 = *(const float4*)(Wr + (size_t)(c0+0) * E);
    float4 w1 = *(const float4*)(Wr + (size_t)(c0+1) * E);
    float4 w2 = *(const float4*)(Wr + (size_t)(c0+2) * E);
    float4 w3 = *(const float4*)(Wr + (size_t)(c0+3) * E);
    float a0 = o.x*w0.x + o.y*w1.x + o.z*w2.x + o.w*w3.x;
    float a1 = o.x*w0.y + o.y*w1.y + o.z*w2.y + o.w*w3.y;
    float a2 = o.x*w0.z + o.y*w1.z + o.z*w2.z + o.w*w3.z;
    float a3 = o.x*w0.w + o.y*w1.w + o.z*w2.w + o.w*w3.w;
    #pragma unroll
    for (int off = 16; off; off >>= 1) {
        a0 += __shfl_xor_sync(0xffffffffu, a0, off);
        a1 += __shfl_xor_sync(0xffffffffu, a1, off);
        a2 += __shfl_xor_sync(0xffffffffu, a2, off);
        a3 += __shfl_xor_sync(0xffffffffu, a3, off);
    }
    if ((threadIdx.x & 31) == 0) {
        int w = threadIdx.x >> 5;
        lred[w*4+0] = a0; lred[w*4+1] = a1; lred[w*4+2] = a2; lred[w*4+3] = a3;
    }
    __syncthreads();
    if (threadIdx.x == 0) {
        float lg[4];
        #pragma unroll
        for (int e = 0; e < 4; e++) {
            float s = 0.f;
            #pragma unroll
            for (int w = 0; w < 8; w++) s += lred[w*4+e];
            lg[e] = s;
        }
        int arg = 0;
        #pragma unroll
        for (int e = 1; e < 4; e++) if (lg[e] > lg[arg]) arg = e;
        float m = fmaxf(fmaxf(lg[0], lg[1]), fmaxf(lg[2], lg[3]));
        float ez[4]; float sum = 0.f;
        #pragma unroll
        for (int e = 0; e < 4; e++) { ez[e] = expf(lg[e] - m); sum += ez[e]; }
        float p[4];
        #pragma unroll
        for (int e = 0; e < 4; e++) p[e] = ez[e] / sum;
        g_expert[t] = arg;
        atomicAdd(&g_counts[arg], 1);
        #pragma unroll
        for (int e = 0; e < 4; e++) atomicAdd(&g_expsum[e], (double)p[e]);
        float lse = m + logf(sum);
        atomicAdd(&g_zsum, (double)lse * (double)lse);
        float ent = 0.f;
        #pragma unroll
        for (int e = 0; e < 4; e++) ent -= p[e] * logf(p[e] + 1e-9f);
        atomicAdd(&g_entsum, (double)ent);
    }
}

// per-head RMSNorm + RoPE; reads qk buffer [BT, 2048]
__global__ void qk_rope_kernel(const float* __restrict__ qk,
                               __nv_bfloat16* __restrict__ qhi, __nv_bfloat16* __restrict__ qlo,
                               __nv_bfloat16* __restrict__ khi, __nv_bfloat16* __restrict__ klo) {
    int tok  = blockIdx.x;
    int head = threadIdx.x >> 5;
    int lane = threadIdx.x & 31;
    int tpos = tok % T;
    float ex  = (float)(2 * lane) / 64.0f;
    float inv = 1.0f / powf(10000.0f, ex);
    float ang = (float)tpos * inv;
    float c = cosf(ang), s = sinf(ang);
    size_t obase = (size_t)tok * C + head * D;
    #pragma unroll
    for (int m = 0; m < 2; m++) {
        const float* src = qk + (size_t)tok * 2048 + m * 1024 + head * D;
        __nv_bfloat16* dh = (m == 0 ? qhi : khi) + obase;
        __nv_bfloat16* dl = (m == 0 ? qlo : klo) + obase;
        float x1 = src[lane], x2 = src[lane + 32];
        float ss = x1*x1 + x2*x2;
        #pragma unroll
        for (int o = 16; o; o >>= 1) ss += __shfl_xor_sync(0xffffffffu, ss, o);
        float r = rsqrtf(ss / (float)D + EPS_RMS);
        x1 *= r; x2 *= r;
        float o1 =  x1 * c + x2 * s;
        float o2 = -x1 * s + x2 * c;
        __nv_bfloat16 h, l;
        bsplit(o1, h, l); dh[lane] = h;      dl[lane] = l;
        bsplit(o2, h, l); dh[lane + 32] = h; dl[lane + 32] = l;
    }
}

// ======================= HMMA flash attention (bf16x3) =======================
#define AT_QHI 0
#define AT_QLO 16384
#define AT_STG 32768
#define AT_STGSZ 32768
#define AT_KHI 0
#define AT_KLO 8192
#define AT_VHI 16384
#define AT_VLO 24576
#define ATT_SMEM (32768 + 2*32768)

__global__ void __launch_bounds__(256) attn_mma_kernel(
    const __nv_bfloat16* __restrict__ qhi, const __nv_bfloat16* __restrict__ qlo,
    const __nv_bfloat16* __restrict__ khi, const __nv_bfloat16* __restrict__ klo,
    const __nv_bfloat16* __restrict__ vhi, const __nv_bfloat16* __restrict__ vlo,
    __nv_bfloat16* __restrict__ yhi, __nv_bfloat16* __restrict__ ylo)
{
    extern __shared__ __align__(1024) char smem[];
    uint32_t sb = smem_to_u32(smem);
    int bh = blockIdx.y;
    int b = bh / H, hh = bh % H;
    int qb = blockIdx.x;
    int q0 = qb * 128;
    int tid = threadIdx.x, wid = tid >> 5, lid = tid & 31;
    int nkt = 2 * qb + 2;

    #pragma unroll
    for (int i = 0; i < 4; i++) {
        int lin = tid + i * 256;
        int r = lin >> 3, ch = lin & 7;
        uint32_t so = SMEM_SWIZZLE_128B((uint32_t)(r * 128 + ch * 16));
        size_t g = (size_t)(b*T + q0 + r) * C + hh * D + ch * 8;
        CP16(sb + AT_QHI + so, qhi + g);
        CP16(sb + AT_QLO + so, qlo + g);
    }
    asm volatile("cp.async.commit_group;" ::: "memory");
    #pragma unroll
    for (int i = 0; i < 2; i++) {
        int lin = tid + i * 256;
        int r = lin >> 3, ch = lin & 7;
        uint32_t so = SMEM_SWIZZLE_128B((uint32_t)(r * 128 + ch * 16));
        size_t g = (size_t)(b*T + r) * C + hh * D + ch * 8;
        uint32_t st = sb + AT_STG;
        CP16(st + AT_KHI + so, khi + g);
        CP16(st + AT_KLO + so, klo + g);
        CP16(st + AT_VHI + so, vhi + g);
        CP16(st + AT_VLO + so, vlo + g);
    }
    asm volatile("cp.async.commit_group;" ::: "memory");

    uint32_t qa_hi[4][4], qa_lo[4][4];
    float oac[8][4];
    #pragma unroll
    for (int j = 0; j < 8; j++)
        #pragma unroll
        for (int r = 0; r < 4; r++) oac[j][r] = 0.f;
    float m0 = -1e30f, m1 = -1e30f, l0 = 0.f, l1 = 0.f;

    int off = lid & 7, part = lid >> 3;
    int qr = lid >> 2, qc = (lid & 3) * 2;
    const float SC2 = 0.18033688011112042f;

    for (int kt = 0; kt < nkt; kt++) {
        if (kt + 1 < nkt) {
            #pragma unroll
            for (int i = 0; i < 2; i++) {
                int lin = tid + i * 256;
                int r = lin >> 3, ch = lin & 7;
                uint32_t so = SMEM_SWIZZLE_128B((uint32_t)(r * 128 + ch * 16));
                size_t g = (size_t)(b*T + (kt + 1) * 64 + r) * C + hh * D + ch * 8;
                uint32_t st = sb + AT_STG + (uint32_t)((kt + 1) & 1) * AT_STGSZ;
                CP16(st + AT_KHI + so, khi + g);
                CP16(st + AT_KLO + so, klo + g);
                CP16(st + AT_VHI + so, vhi + g);
                CP16(st + AT_VLO + so, vlo + g);
            }
            asm volatile("cp.async.commit_group;" ::: "memory");
            asm volatile("cp.async.wait_group 1;" ::: "memory");
        } else {
            asm volatile("cp.async.wait_group 0;" ::: "memory");
        }
        __syncthreads();

        if (kt == 0) {
            #pragma unroll
            for (int kk = 0; kk < 4; kk++) {
                int row = wid * 16 + (part & 1) * 8 + off;
                int colb = kk * 32 + (part & 2) * 8;
                uint32_t so = SMEM_SWIZZLE_128B((uint32_t)(row * 128 + colb));
                ldsm4(qa_hi[kk], sb + AT_QHI + so);
                ldsm4(qa_lo[kk], sb + AT_QLO + so);
            }
        }

        uint32_t st = sb + AT_STG + (uint32_t)(kt & 1) * AT_STGSZ;

        float s[8][4];
        #pragma unroll
        for (int j = 0; j < 8; j++)
            #pragma unroll
            for (int r = 0; r < 4; r++) s[j][r] = 0.f;
        #pragma unroll
        for (int kk = 0; kk < 4; kk++) {
            #pragma unroll
            for (int jj = 0; jj < 4; jj++) {
                int row = jj * 16 + (part & 2) * 4 + off;
                int colb = kk * 32 + (part & 1) * 16;
                uint32_t so = SMEM_SWIZZLE_128B((uint32_t)(row * 128 + colb));
                uint32_t kh[4], kl[4];
                ldsm4(kh, st + AT_KHI + so);
                ldsm4(kl, st + AT_KLO + so);
                mma_bf16(s[2*jj],     qa_hi[kk], kh);
                mma_bf16(s[2*jj],     qa_hi[kk], kl);
                mma_bf16(s[2*jj],     qa_lo[kk], kh);
                mma_bf16(s[2*jj+1],   qa_hi[kk], kh + 2);
                mma_bf16(s[2*jj+1],   qa_hi[kk], kl + 2);
                mma_bf16(s[2*jj+1],   qa_lo[kk], kh + 2);
            }
        }

        bool domask = (kt >= nkt - 2);
        #pragma unroll
        for (int j = 0; j < 8; j++) {
            #pragma unroll
            for (int r = 0; r < 4; r++) {
                float v = s[j][r] * SC2;
                if (domask) {
                    int key = kt * 64 + j * 8 + qc + (r & 1);
                    int row = q0 + wid * 16 + qr + (r & 2) * 4;
                    if (key > row) v = -1e30f;
                }
                s[j][r] = v;
            }
        }

        float mx0 = -1e30f, mx1 = -1e30f;
        #pragma unroll
        for (int j = 0; j < 8; j++) {
            mx0 = fmaxf(mx0, fmaxf(s[j][0], s[j][1]));
            mx1 = fmaxf(mx1, fmaxf(s[j][2], s[j][3]));
        }
        mx0 = fmaxf(mx0, __shfl_xor_sync(0xffffffffu, mx0, 1));
        mx0 = fmaxf(mx0, __shfl_xor_sync(0xffffffffu, mx0, 2));
        mx1 = fmaxf(mx1, __shfl_xor_sync(0xffffffffu, mx1, 1));
        mx1 = fmaxf(mx1, __shfl_xor_sync(0xffffffffu, mx1, 2));
        float mn0 = fmaxf(m0, mx0), mn1 = fmaxf(m1, mx1);
        float al0 = ex2f(m0 - mn0), al1 = ex2f(m1 - mn1);
        float sm0 = 0.f, sm1 = 0.f;
        #pragma unroll
        for (int j = 0; j < 8; j++) {
            s[j][0] = ex2f(s[j][0] - mn0); sm0 += s[j][0];
            s[j][1] = ex2f(s[j][1] - mn0); sm0 += s[j][1];
            s[j][2] = ex2f(s[j][2] - mn1); sm1 += s[j][2];
            s[j][3] = ex2f(s[j][3] - mn1); sm1 += s[j][3];
        }
        sm0 += __shfl_xor_sync(0xffffffffu, sm0, 1);
        sm0 += __shfl_xor_sync(0xffffffffu, sm0, 2);
        sm1 += __shfl_xor_sync(0xffffffffu, sm1, 1);
        sm1 += __shfl_xor_sync(0xffffffffu, sm1, 2);
        l0 = l0 * al0 + sm0;  l1 = l1 * al1 + sm1;
        m0 = mn0;  m1 = mn1;
        #pragma unroll
        for (int j = 0; j < 8; j++) {
            oac[j][0] *= al0; oac[j][1] *= al0;
            oac[j][2] *= al1; oac[j][3] *= al1;
        }

        #pragma unroll
        for (int kk = 0; kk < 4; kk++) {
            uint32_t pah[4], pal[4];
            packsplit(s[2*kk][0],   s[2*kk][1],   pah[0], pal[0]);
            packsplit(s[2*kk][2],   s[2*kk][3],   pah[1], pal[1]);
            packsplit(s[2*kk+1][0], s[2*kk+1][1], pah[2], pal[2]);
            packsplit(s[2*kk+1][2], s[2*kk+1][3], pah[3], pal[3]);
            #pragma unroll
            for (int jj = 0; jj < 4; jj++) {
                int row = kk * 16 + (part & 1) * 8 + off;
                int colb = jj * 32 + (part & 2) * 8;
                uint32_t so = SMEM_SWIZZLE_128B((uint32_t)(row * 128 + colb));
                uint32_t vh[4], vl[4];
                ldsm4t(vh, st + AT_VHI + so);
                ldsm4t(vl, st + AT_VLO + so);
                mma_bf16(oac[2*jj],   pah, vh);
                mma_bf16(oac[2*jj],   pah, vl);
                mma_bf16(oac[2*jj],   pal, vh);
                mma_bf16(oac[2*jj+1], pah, vh + 2);
                mma_bf16(oac[2*jj+1], pah, vl + 2);
                mma_bf16(oac[2*jj+1], pal, vh + 2);
            }
        }
        __syncthreads();
    }

    float inv0 = 1.f / l0, inv1 = 1.f / l1;
    #pragma unroll
    for (int j = 0; j < 8; j++) {
        size_t i0 = (size_t)(b*T + q0 + wid*16 + qr) * C + hh * D + j * 8 + qc;
        size_t i1 = (size_t)(b*T + q0 + wid*16 + qr + 8) * C + hh * D + j * 8 + qc;
        uint32_t ph, pl;
        packsplit(oac[j][0] * inv0, oac[j][1] * inv0, ph, pl);
        *(uint32_t*)(yhi + i0) = ph;  *(uint32_t*)(ylo + i0) = pl;
        packsplit(oac[j][2] * inv1, oac[j][3] * inv1, ph, pl);
        *(uint32_t*)(yhi + i1) = ph;  *(uint32_t*)(ylo + i1) = pl;
    }
}

// ======================= HMMA bf16x3 GEMM — 128x256 block tile (R8 config) =======================
// epi: 0 fp32; 1 fp32+resid; 2 relu(acc)^2 -> bf16 pair; 3 acc -> bf16 pair;
//      4 fused QKV; 5 MoE scatter (out[token] = acc + resid[token])
#define KTILE 64
#define W_AH 0
#define W_AL 16384
#define W_BH 32768
#define W_BL 65536
#define W_STAGE 98304
#define SMEM_GEMM_BYTES (2*W_STAGE)

__global__ void __launch_bounds__(256, 1) gemm_bf16x3(
    const __nv_bfloat16* __restrict__ Ahi, const __nv_bfloat16* __restrict__ Alo,
    const __nv_bfloat16* __restrict__ Bhi, const __nv_bfloat16* __restrict__ Blo,
    size_t bstride,
    float* __restrict__ Cout,
    __nv_bfloat16* __restrict__ Ohi, __nv_bfloat16* __restrict__ Olo,
    const float* __restrict__ resid,
    const int* __restrict__ tileExpert,
    const int* __restrict__ tokOfRow,
    int N, int K, int epi)
{
    extern __shared__ __align__(1024) char smem[];
    int by = blockIdx.y, bx = blockIdx.x;
    int e = 0;
    if (tileExpert) { e = tileExpert[by]; if (e < 0) return; }
    const __nv_bfloat16* Bh = Bhi + (size_t)e * bstride;
    const __nv_bfloat16* Bl = Blo + (size_t)e * bstride;

    uint32_t sb = smem_to_u32(smem);
    int tid = threadIdx.x, wid = tid >> 5, lid = tid & 31;
    int wm = wid & 1, wn = wid >> 1;
    int row0 = by * 128, col0 = bx * 256;
    int nkt = K / KTILE;

    float acc[4][8][4];
    #pragma unroll
    for (int i = 0; i < 4; i++)
        #pragma unroll
        for (int j = 0; j < 8; j++)
            #pragma unroll
            for (int r = 0; r < 4; r++) acc[i][j][r] = 0.f;

    int lr = tid >> 3, lc = tid & 7;

    {
        #pragma unroll
        for (int i = 0; i < 4; i++) {
            int r = lr + i * 32;
            uint32_t so = SMEM_SWIZZLE_128B((uint32_t)(r * 128 + lc * 16));
            size_t ga = (size_t)(row0 + r) * K + lc * 8;
            CP16(sb + W_AH + so, Ahi + ga);
            CP16(sb + W_AL + so, Alo + ga);
        }
        #pragma unroll
        for (int i = 0; i < 8; i++) {
            int r = lr + i * 32;
            uint32_t so = SMEM_SWIZZLE_128B((uint32_t)(r * 128 + lc * 16));
            size_t gb = (size_t)(col0 + r) * K + lc * 8;
            CP16(sb + W_BH + so, Bh + gb);
            CP16(sb + W_BL + so, Bl + gb);
        }
        asm volatile("cp.async.commit_group;" ::: "memory");
    }

    for (int kt = 0; kt < nkt; kt++) {
        uint32_t cur = (uint32_t)(kt & 1) * W_STAGE;
        if (kt + 1 < nkt) {
            uint32_t nxt = (uint32_t)((kt + 1) & 1) * W_STAGE;
            int k0 = (kt + 1) * KTILE;
            #pragma unroll
            for (int i = 0; i < 4; i++) {
                int r = lr + i * 32;
                uint32_t so = SMEM_SWIZZLE_128B((uint32_t)(r * 128 + lc * 16));
                size_t ga = (size_t)(row0 + r) * K + k0 + lc * 8;
                CP16(sb + nxt + W_AH + so, Ahi + ga);
                CP16(sb + nxt + W_AL + so, Alo + ga);
            }
            #pragma unroll
            for (int i = 0; i < 8; i++) {
                int r = lr + i * 32;
                uint32_t so = SMEM_SWIZZLE_128B((uint32_t)(r * 128 + lc * 16));
                size_t gb = (size_t)(col0 + r) * K + k0 + lc * 8;
                CP16(sb + nxt + W_BH + so, Bh + gb);
                CP16(sb + nxt + W_BL + so, Bl + gb);
            }
            asm volatile("cp.async.commit_group;" ::: "memory");
            asm volatile("cp.async.wait_group 1;" ::: "memory");
        } else {
            asm volatile("cp.async.wait_group 0;" ::: "memory");
        }
        __syncthreads();

        uint32_t sAH = sb + cur + W_AH, sAL = sb + cur + W_AL;
        uint32_t sBH = sb + cur + W_BH, sBL = sb + cur + W_BL;
        #pragma unroll
        for (int kk = 0; kk < 4; kk++) {
            int colb = (kk * 16 + (lid >> 4) * 8) * 2;
            uint32_t a_hi[4][4], a_lo[4][4];
            #pragma unroll
            for (int mf = 0; mf < 4; mf++) {
                int rowm = wm * 64 + mf * 16 + (lid & 15);
                uint32_t so = SMEM_SWIZZLE_128B((uint32_t)(rowm * 128 + colb));
                ldsm4(a_hi[mf], sAH + so);
                ldsm4(a_lo[mf], sAL + so);
            }
            uint32_t b_hi[8][2], b_lo[8][2];
            #pragma unroll
            for (int g = 0; g < 4; g++) {
                int rown = wn * 64 + g * 16 + (lid & 15);
                uint32_t so = SMEM_SWIZZLE_128B((uint32_t)(rown * 128 + colb));
                uint32_t r4[4];
                ldsm4(r4, sBH + so);
                b_hi[2*g][0] = r4[0]; b_hi[2*g+1][0] = r4[1];
                b_hi[2*g][1] = r4[2]; b_hi[2*g+1][1] = r4[3];
                ldsm4(r4, sBL + so);
                b_lo[2*g][0] = r4[0]; b_lo[2*g+1][0] = r4[1];
                b_lo[2*g][1] = r4[2]; b_lo[2*g+1][1] = r4[3];
            }
            #pragma unroll
            for (int mf = 0; mf < 4; mf++)
                #pragma unroll
                for (int nf = 0; nf < 8; nf++) {
                    mma_bf16(acc[mf][nf], a_hi[mf], b_hi[nf]);
                    mma_bf16(acc[mf][nf], a_hi[mf], b_lo[nf]);
                    mma_bf16(acc[mf][nf], a_lo[mf], b_hi[nf]);
                }
        }
        __syncthreads();
    }

    int qr = lid >> 2, qc = (lid & 3) * 2;
    #pragma unroll
    for (int mf = 0; mf < 4; mf++) {
        #pragma unroll
        for (int nf = 0; nf < 8; nf++) {
            float* cc = acc[mf][nf];
            int col = col0 + wn * 64 + nf * 8 + qc;
            #pragma unroll
            for (int half = 0; half < 2; half++) {
                int row = row0 + wm * 64 + mf * 16 + qr + half * 8;
                float v0 = cc[2*half], v1 = cc[2*half + 1];
                if (epi == 0) {
                    size_t idx = (size_t)row * N + col;
                    *(float2*)(Cout + idx) = make_float2(v0, v1);
                } else if (epi == 1) {
                    size_t idx = (size_t)row * N + col;
                    float2 rr = *(const float2*)(resid + idx);
                    *(float2*)(Cout + idx) = make_float2(v0 + rr.x, v1 + rr.y);
                } else if (epi == 4) {
                    if (col < 2048) {
                        size_t idx = (size_t)row * 2048 + col;
                        *(float2*)(Cout + idx) = make_float2(v0, v1);
                    } else {
                        size_t idx = (size_t)row * 1024 + (col - 2048);
                        uint32_t ph, pl;
                        packsplit(v0, v1, ph, pl);
                        *(uint32_t*)(Ohi + idx) = ph;
                        *(uint32_t*)(Olo + idx) = pl;
                    }
                } else if (epi == 5) {
                    int t = tokOfRow[row];
                    if (t >= 0) {
                        size_t idx = (size_t)t * N + col;
                        float2 rr = *(const float2*)(resid + idx);
                        *(float2*)(Cout + idx) = make_float2(v0 + rr.x, v1 + rr.y);
                    }
                } else {
                    if (epi == 2) {
                        v0 = fmaxf(v0, 0.f); v0 *= v0;
                        v1 = fmaxf(v1, 0.f); v1 *= v1;
                    }
                    size_t idx = (size_t)row * N + col;
                    uint32_t ph, pl;
                    packsplit(v0, v1, ph, pl);
                    *(uint32_t*)(Ohi + idx) = ph;
                    *(uint32_t*)(Olo + idx) = pl;
                }
            }
        }
    }
}

// ======================= grouping / scalars =======================
__global__ void offsets_kernel() {
    if (threadIdx.x == 0 && blockIdx.x == 0) {
        int off = 0;
        for (int e = 0; e < E; e++) {
            g_segstart[e] = off;
            int padded = (g_counts[e] + 127) & ~127;
            for (int i = 0; i < padded / 128; i++)
                g_tileExpert[off / 128 + i] = e;
            off += padded;
        }
    }
}

__global__ void assign_kernel(const float* __restrict__ h2) {
    int t = blockIdx.x;
    __shared__ int slot_s;
    if (threadIdx.x == 0) {
        int e = g_expert[t];
        int slot = g_segstart[e] + atomicAdd(&g_cursor[e], 1);
        g_tokenOfRow[slot] = t;
        slot_s = slot;
    }
    __syncthreads();
    int s = slot_s;
    float4 v = ((const float4*)(h2 + (size_t)t * C))[threadIdx.x];
    __nv_bfloat16 h0,l0,h1,l1,h2b,l2,h3,l3;
    bsplit(v.x,h0,l0); bsplit(v.y,h1,l1); bsplit(v.z,h2b,l2); bsplit(v.w,h3,l3);
    __nv_bfloat162* hp = (__nv_bfloat162*)(g_h2g_hi + (size_t)s * C);
    __nv_bfloat162* lp = (__nv_bfloat162*)(g_h2g_lo + (size_t)s * C);
    hp[threadIdx.x*2]   = __nv_bfloat162(h0, h1);
    hp[threadIdx.x*2+1] = __nv_bfloat162(h2b, h3);
    lp[threadIdx.x*2]   = __nv_bfloat162(l0, l1);
    lp[threadIdx.x*2+1] = __nv_bfloat162(l2, l3);
}

__global__ void scalars_kernel(float* __restrict__ out) {
    if (threadIdx.x == 0 && blockIdx.x == 0) {
        const double NTOK = (double)BT;
        double aux = 0.0;
        for (int e = 0; e < E; e++) {
            double actual = (double)g_counts[e] / NTOK;
            double expd   = g_expsum[e] / NTOK;
            aux += actual * expd;
        }
        size_t base = (size_t)BT * C;
        out[base + 0] = (float)((double)E * aux);
        out[base + 1] = (float)(g_zsum / NTOK);
        out[base + 2] = (float)((g_entsum / NTOK) / log((double)E));
        for (int e = 0; e < E; e++)
            out[base + 3 + e] = (float)((double)g_counts[e] / NTOK);
    }
}

// ======================= launch =======================
static void* sym(const void* s) { void* p = nullptr; cudaGetSymbolAddress(&p, s); return p; }

extern "C" void kernel_launch(void* const* d_in, const int* in_sizes, int n_in,
                              void* d_out, int out_size)
{
    const float* x     = (const float*)d_in[0];
    const float* Wq    = (const float*)d_in[1];
    const float* Wk    = (const float*)d_in[2];
    const float* Wv    = (const float*)d_in[3];
    const float* Wo    = (const float*)d_in[4];
    const float* Wr    = (const float*)d_in[5];
    const float* Wfc   = (const float*)d_in[6];
    const float* Wproj = (const float*)d_in[7];
    float* out = (float*)d_out;

    static bool init_done = false;
    static cudaStream_t s2;
    static cudaEvent_t evFork, evWo, evMoE;
    if (!init_done) {
        cudaFuncSetAttribute(gemm_bf16x3, cudaFuncAttributeMaxDynamicSharedMemorySize, SMEM_GEMM_BYTES);
        cudaFuncSetAttribute(attn_mma_kernel, cudaFuncAttributeMaxDynamicSharedMemorySize, ATT_SMEM);
        cudaStreamCreateWithFlags(&s2, cudaStreamNonBlocking);
        cudaEventCreateWithFlags(&evFork, cudaEventDisableTiming);
        cudaEventCreateWithFlags(&evWo,   cudaEventDisableTiming);
        cudaEventCreateWithFlags(&evMoE,  cudaEventDisableTiming);
        init_done = true;
    }

    __nv_bfloat16* h1h = (__nv_bfloat16*)sym(g_h1_hi);
    __nv_bfloat16* h1l = (__nv_bfloat16*)sym(g_h1_lo);
    float* qk = (float*)sym(g_qk);
    __nv_bfloat16* qh = (__nv_bfloat16*)sym(g_qhi); __nv_bfloat16* ql = (__nv_bfloat16*)sym(g_qlo);
    __nv_bfloat16* kh = (__nv_bfloat16*)sym(g_khi); __nv_bfloat16* kl = (__nv_bfloat16*)sym(g_klo);
    __nv_bfloat16* vh = (__nv_bfloat16*)sym(g_vhi); __nv_bfloat16* vl = (__nv_bfloat16*)sym(g_vlo);
    __nv_bfloat16* yh = (__nv_bfloat16*)sym(g_y_hi);
    __nv_bfloat16* yl = (__nv_bfloat16*)sym(g_y_lo);
    float* x2 = (float*)sym(g_x2);
    float* h2 = (float*)sym(g_h2);
    __nv_bfloat16* h2gh = (__nv_bfloat16*)sym(g_h2g_hi);
    __nv_bfloat16* h2gl = (__nv_bfloat16*)sym(g_h2g_lo);
    __nv_bfloat16* hidh = (__nv_bfloat16*)sym(g_hid_hi);
    __nv_bfloat16* hidl = (__nv_bfloat16*)sym(g_hid_lo);
    __nv_bfloat16* wqkvh = (__nv_bfloat16*)sym(g_wqkv_hi);
    __nv_bfloat16* wqkvl = (__nv_bfloat16*)sym(g_wqkv_lo);
    __nv_bfloat16* woh = (__nv_bfloat16*)sym(g_wo_hi); __nv_bfloat16* wol = (__nv_bfloat16*)sym(g_wo_lo);
    __nv_bfloat16* wfh = (__nv_bfloat16*)sym(g_wfc_hi); __nv_bfloat16* wfl = (__nv_bfloat16*)sym(g_wfc_lo);
    __nv_bfloat16* wph = (__nv_bfloat16*)sym(g_wpj_hi); __nv_bfloat16* wpl = (__nv_bfloat16*)sym(g_wpj_lo);
    int* tileE = (int*)sym(g_tileExpert);
    int* tokR  = (int*)sym(g_tokenOfRow);

    // ---- main stream (0): front section ----
    reset_kernel<<<(GROUP_CAP + 255) / 256, 256>>>();
    cudaEventRecord(evFork, 0);

    // ---- side stream: weight conversions not needed until later ----
    cudaStreamWaitEvent(s2, evFork, 0);
    wconv_kernel<<<dim3(C/64,  C/64,  1), 256, 0, s2>>>(Wo,    woh, wol, C,  C);
    cudaEventRecord(evWo, s2);
    wconv_kernel<<<dim3(FF/64, C/64,  E), 256, 0, s2>>>(Wfc,   wfh, wfl, C,  FF);
    wconv_kernel<<<dim3(C/64,  FF/64, E), 256, 0, s2>>>(Wproj, wph, wpl, FF, C);
    cudaEventRecord(evMoE, s2);

    // ---- main stream continues ----
    rmsnorm_kernel<<<BT, 256>>>(x, h1h, h1l);
    wconv_kernel<<<dim3(C/64, C/64, 1), 256>>>(Wq, wqkvh,         wqkvl,         C, C);
    wconv_kernel<<<dim3(C/64, C/64, 1), 256>>>(Wk, wqkvh + C*C,   wqkvl + C*C,   C, C);
    wconv_kernel<<<dim3(C/64, C/64, 1), 256>>>(Wv, wqkvh + 2*C*C, wqkvl + 2*C*C, C, C);
    gemm_bf16x3<<<dim3(3*C/256, BT/128), 256, SMEM_GEMM_BYTES>>>(
        h1h, h1l, wqkvh, wqkvl, 0, qk, vh, vl, nullptr, nullptr, nullptr, 3*C, C, 4);
    qk_rope_kernel<<<BT, 512>>>(qk, qh, ql, kh, kl);
    attn_mma_kernel<<<dim3(T/128, Bq*H), 256, ATT_SMEM>>>(
        qh, ql, kh, kl, vh, vl, yh, yl);

    cudaStreamWaitEvent(0, evWo, 0);
    gemm_bf16x3<<<dim3(C/256, BT/128), 256, SMEM_GEMM_BYTES>>>(
        yh, yl, woh, wol, 0, x2, nullptr, nullptr, x, nullptr, nullptr, C, C, 1);
    rmsnorm_router_kernel<<<BT, 256>>>(x2, h2, Wr);
    offsets_kernel<<<1, 32>>>();
    assign_kernel<<<BT, 256>>>(h2);

    cudaStreamWaitEvent(0, evMoE, 0);
    gemm_bf16x3<<<dim3(FF/256, NTILES), 256, SMEM_GEMM_BYTES>>>(
        h2gh, h2gl, wfh, wfl, (size_t)FF * C, nullptr, hidh, hidl, nullptr, tileE, nullptr, FF, C, 2);
    gemm_bf16x3<<<dim3(C/256, NTILES), 256, SMEM_GEMM_BYTES>>>(
        hidh, hidl, wph, wpl, (size_t)C * FF, out, nullptr, nullptr, x2, tileE, tokR, C, FF, 5);
    scalars_kernel<<<1, 32>>>(out);
}

// round 12
// speedup vs baseline: 1.4391x; 1.3588x over previous
#include <cuda_runtime.h>
#include <cuda_bf16.h>
#include <cuda_fp16.h>
#include <cstdint>
#include <math.h>

#define Bq 2
#define T 2048
#define C 1024
#define H 16
#define D 64
#define E 4
#define BT (Bq*T)
#define FF (4*C)
#define GROUP_CAP (BT + E*128)
#define NTILES (GROUP_CAP/128)
#define EPS_RMS 1.1920929e-07f

#define SMEM_SWIZZLE_128B(b) ((b) ^ (((b) >> 3) & 0x70))

__device__ __forceinline__ uint32_t smem_to_u32(const void* p) {
    uint32_t a;
    asm("{ .reg .u64 t; cvta.to.shared.u64 t, %1; cvt.u32.u64 %0, t; }" : "=r"(a) : "l"(p));
    return a;
}
__device__ __forceinline__ void ldsm4(uint32_t* r, uint32_t addr) {
    asm volatile("ldmatrix.sync.aligned.m8n8.x4.shared.b16 {%0,%1,%2,%3}, [%4];"
                 : "=r"(r[0]), "=r"(r[1]), "=r"(r[2]), "=r"(r[3]) : "r"(addr));
}
__device__ __forceinline__ void ldsm4t(uint32_t* r, uint32_t addr) {
    asm volatile("ldmatrix.sync.aligned.m8n8.x4.trans.shared.b16 {%0,%1,%2,%3}, [%4];"
                 : "=r"(r[0]), "=r"(r[1]), "=r"(r[2]), "=r"(r[3]) : "r"(addr));
}
__device__ __forceinline__ void mma_bf16(float* c, const uint32_t* a, const uint32_t* b) {
    asm volatile("mma.sync.aligned.m16n8k16.row.col.f32.bf16.bf16.f32 "
        "{%0,%1,%2,%3}, {%4,%5,%6,%7}, {%8,%9}, {%0,%1,%2,%3};"
        : "+f"(c[0]), "+f"(c[1]), "+f"(c[2]), "+f"(c[3])
        : "r"(a[0]), "r"(a[1]), "r"(a[2]), "r"(a[3]), "r"(b[0]), "r"(b[1]));
}
__device__ __forceinline__ void mma_f16(float* c, const uint32_t* a, const uint32_t* b) {
    asm volatile("mma.sync.aligned.m16n8k16.row.col.f32.f16.f16.f32 "
        "{%0,%1,%2,%3}, {%4,%5,%6,%7}, {%8,%9}, {%0,%1,%2,%3};"
        : "+f"(c[0]), "+f"(c[1]), "+f"(c[2]), "+f"(c[3])
        : "r"(a[0]), "r"(a[1]), "r"(a[2]), "r"(a[3]), "r"(b[0]), "r"(b[1]));
}
__device__ __forceinline__ float ex2f(float x) {
    float y; asm("ex2.approx.ftz.f32 %0, %1;" : "=f"(y) : "f"(x)); return y;
}
#define CP16(s, g) asm volatile("cp.async.cg.shared.global [%0], [%1], 16;" \
                                :: "r"(s), "l"(g) : "memory")

// ======================= scratch (static device globals) =======================
__device__ __half g_h1_hi[BT*C], g_h1_lo[BT*C];
__device__ float g_qk[BT*2*C];
__device__ __nv_bfloat16 g_qhi[BT*C], g_qlo[BT*C];
__device__ __nv_bfloat16 g_khi[BT*C], g_klo[BT*C];
__device__ __half g_vh[BT*C];
__device__ __half g_y_hi[BT*C], g_y_lo[BT*C];
__device__ float g_x2[BT*C], g_h2[BT*C];
__device__ __half g_h2g_hi[GROUP_CAP*C], g_h2g_lo[GROUP_CAP*C];
__device__ __half g_hid_hi[(size_t)GROUP_CAP*FF], g_hid_lo[(size_t)GROUP_CAP*FF];
__device__ __half g_wqkv[3*C*C];
__device__ __half g_wo[C*C];
__device__ __half g_wfc[(size_t)E*C*FF];   // [E][FF,C]
__device__ __half g_wpj[(size_t)E*FF*C];   // [E][C,FF]
__device__ int   g_expert[BT];
__device__ int   g_counts[E];
__device__ int   g_cursor[E];
__device__ int   g_segstart[E];
__device__ int   g_tileExpert[NTILES];
__device__ int   g_tokenOfRow[GROUP_CAP];
__device__ double g_expsum[E];
__device__ double g_zsum;
__device__ double g_entsum;

__device__ __forceinline__ void bsplit(float v, __nv_bfloat16& h, __nv_bfloat16& l) {
    h = __float2bfloat16(v);
    l = __float2bfloat16(v - __bfloat162float(h));
}
__device__ __forceinline__ void hsplit(float v, __half& h, __half& l) {
    h = __float2half(v);
    l = __float2half(v - __half2float(h));
}
__device__ __forceinline__ void packsplith(float v0, float v1, uint32_t& hi, uint32_t& lo) {
    __half h0, l0, h1, l1;
    hsplit(v0, h0, l0); hsplit(v1, h1, l1);
    __half2 hh(h0, h1), ll(l0, l1);
    hi = *reinterpret_cast<uint32_t*>(&hh);
    lo = *reinterpret_cast<uint32_t*>(&ll);
}

// ======================= small kernels =======================
__global__ void reset_kernel() {
    int i = blockIdx.x * blockDim.x + threadIdx.x;
    if (i < E) { g_counts[i] = 0; g_cursor[i] = 0; g_expsum[i] = 0.0; }
    if (i == 0) { g_zsum = 0.0; g_entsum = 0.0; }
    if (i < NTILES) g_tileExpert[i] = -1;
    if (i < GROUP_CAP) g_tokenOfRow[i] = -1;
}

// transpose weights: W [Kd, Nd] fp32 -> T [Nd, Kd] single fp16
__global__ void __launch_bounds__(256) wconv_kernel(
    const float* __restrict__ W, __half* __restrict__ Th, int Kd, int Nd) {
    __shared__ float tile[64][65];
    int b = blockIdx.z;
    const float* Wb = W + (size_t)b * Kd * Nd;
    __half* Tb = Th + (size_t)b * Kd * Nd;
    int n0 = blockIdx.x * 64, k0 = blockIdx.y * 64;
    int tid = threadIdx.x;
    int lr = tid >> 4, lc = (tid & 15) * 4;
    #pragma unroll
    for (int i = 0; i < 4; i++) {
        int k = lr + i * 16;
        float4 v = *(const float4*)(Wb + (size_t)(k0 + k) * Nd + n0 + lc);
        tile[k][lc] = v.x; tile[k][lc+1] = v.y; tile[k][lc+2] = v.z; tile[k][lc+3] = v.w;
    }
    __syncthreads();
    int wn = tid >> 4, wk = (tid & 15) * 4;
    #pragma unroll
    for (int i = 0; i < 4; i++) {
        int n = wn + i * 16;
        __half2 p01 = __floats2half2_rn(tile[wk][n],   tile[wk+1][n]);
        __half2 p23 = __floats2half2_rn(tile[wk+2][n], tile[wk+3][n]);
        size_t o = (size_t)(n0 + n) * Kd + k0 + wk;
        *(uint2*)(Tb + o) = make_uint2(*(uint32_t*)&p01, *(uint32_t*)&p23);
    }
}

// RMSNorm over C -> fp16 hi/lo pair
__global__ void rmsnorm_kernel(const float* __restrict__ in,
                               __half* __restrict__ ohi, __half* __restrict__ olo) {
    int t = blockIdx.x;
    const float4* ip = (const float4*)(in + (size_t)t * C);
    __shared__ float red[8];
    float4 v = ip[threadIdx.x];
    float ss = v.x*v.x + v.y*v.y + v.z*v.z + v.w*v.w;
    #pragma unroll
    for (int o = 16; o; o >>= 1) ss += __shfl_xor_sync(0xffffffffu, ss, o);
    if ((threadIdx.x & 31) == 0) red[threadIdx.x >> 5] = ss;
    __syncthreads();
    if (threadIdx.x == 0) {
        float s = 0.f;
        #pragma unroll
        for (int w = 0; w < 8; w++) s += red[w];
        red[0] = s;
    }
    __syncthreads();
    float r = rsqrtf(red[0] / (float)C + EPS_RMS);
    float4 o = make_float4(v.x*r, v.y*r, v.z*r, v.w*r);
    uint32_t h01, l01, h23, l23;
    packsplith(o.x, o.y, h01, l01);
    packsplith(o.z, o.w, h23, l23);
    uint2* hp = (uint2*)(ohi + (size_t)t * C);
    uint2* lp = (uint2*)(olo + (size_t)t * C);
    hp[threadIdx.x] = make_uint2(h01, h23);
    lp[threadIdx.x] = make_uint2(l01, l23);
}

// RMSNorm fp32 out + fused router
__global__ void rmsnorm_router_kernel(const float* __restrict__ in, float* __restrict__ outf,
                                      const float* __restrict__ Wr) {
    int t = blockIdx.x;
    const float4* ip = (const float4*)(in + (size_t)t * C);
    __shared__ float red[8];
    __shared__ float lred[32];
    float4 v = ip[threadIdx.x];
    float ss = v.x*v.x + v.y*v.y + v.z*v.z + v.w*v.w;
    #pragma unroll
    for (int o = 16; o; o >>= 1) ss += __shfl_xor_sync(0xffffffffu, ss, o);
    if ((threadIdx.x & 31) == 0) red[threadIdx.x >> 5] = ss;
    __syncthreads();
    if (threadIdx.x == 0) {
        float s = 0.f;
        #pragma unroll
        for (int w = 0; w < 8; w++) s += red[w];
        red[0] = s;
    }
    __syncthreads();
    float r = rsqrtf(red[0] / (float)C + EPS_RMS);
    float4 o = make_float4(v.x*r, v.y*r, v.z*r, v.w*r);
    ((float4*)(outf + (size_t)t * C))[threadIdx.x] = o;

    int c0 = threadIdx.x * 4;
    float4 w0 = *(const float4*)(Wr + (size_t)(c0+0) * E);
    float4 w1 = *(const float4*)(Wr + (size_t)(c0+1) * E);
    float4 w2 = *(const float4*)(Wr + (size_t)(c0+2) * E);
    float4 w3 = *(const float4*)(Wr + (size_t)(c0+3) * E);
    float a0 = o.x*w0.x + o.y*w1.x + o.z*w2.x + o.w*w3.x;
    float a1 = o.x*w0.y + o.y*w1.y + o.z*w2.y + o.w*w3.y;
    float a2 = o.x*w0.z + o.y*w1.z + o.z*w2.z + o.w*w3.z;
    float a3 = o.x*w0.w + o.y*w1.w + o.z*w2.w + o.w*w3.w;
    #pragma unroll
    for (int off = 16; off; off >>= 1) {
        a0 += __shfl_xor_sync(0xffffffffu, a0, off);
        a1 += __shfl_xor_sync(0xffffffffu, a1, off);
        a2 += __shfl_xor_sync(0xffffffffu, a2, off);
        a3 += __shfl_xor_sync(0xffffffffu, a3, off);
    }
    if ((threadIdx.x & 31) == 0) {
        int w = threadIdx.x >> 5;
        lred[w*4+0] = a0; lred[w*4+1] = a1; lred[w*4+2] = a2; lred[w*4+3] = a3;
    }
    __syncthreads();
    if (threadIdx.x == 0) {
        float lg[4];
        #pragma unroll
        for (int e = 0; e < 4; e++) {
            float s = 0.f;
            #pragma unroll
            for (int w = 0; w < 8; w++) s += lred[w*4+e];
            lg[e] = s;
        }
        int arg = 0;
        #pragma unroll
        for (int e = 1; e < 4; e++) if (lg[e] > lg[arg]) arg = e;
        float m = fmaxf(fmaxf(lg[0], lg[1]), fmaxf(lg[2], lg[3]));
        float ez[4]; float sum = 0.f;
        #pragma unroll
        for (int e = 0; e < 4; e++) { ez[e] = expf(lg[e] - m); sum += ez[e]; }
        float p[4];
        #pragma unroll
        for (int e = 0; e < 4; e++) p[e] = ez[e] / sum;
        g_expert[t] = arg;
        atomicAdd(&g_counts[arg], 1);
        #pragma unroll
        for (int e = 0; e < 4; e++) atomicAdd(&g_expsum[e], (double)p[e]);
        float lse = m + logf(sum);
        atomicAdd(&g_zsum, (double)lse * (double)lse);
        float ent = 0.f;
        #pragma unroll
        for (int e = 0; e < 4; e++) ent -= p[e] * logf(p[e] + 1e-9f);
        atomicAdd(&g_entsum, (double)ent);
    }
}

// per-head RMSNorm + RoPE; reads qk buffer [BT, 2048]; q/k bf16 pairs out
__global__ void qk_rope_kernel(const float* __restrict__ qk,
                               __nv_bfloat16* __restrict__ qhi, __nv_bfloat16* __restrict__ qlo,
                               __nv_bfloat16* __restrict__ khi, __nv_bfloat16* __restrict__ klo) {
    int tok  = blockIdx.x;
    int head = threadIdx.x >> 5;
    int lane = threadIdx.x & 31;
    int tpos = tok % T;
    float ex  = (float)(2 * lane) / 64.0f;
    float inv = 1.0f / powf(10000.0f, ex);
    float ang = (float)tpos * inv;
    float c = cosf(ang), s = sinf(ang);
    size_t obase = (size_t)tok * C + head * D;
    #pragma unroll
    for (int m = 0; m < 2; m++) {
        const float* src = qk + (size_t)tok * 2048 + m * 1024 + head * D;
        __nv_bfloat16* dh = (m == 0 ? qhi : khi) + obase;
        __nv_bfloat16* dl = (m == 0 ? qlo : klo) + obase;
        float x1 = src[lane], x2 = src[lane + 32];
        float ss = x1*x1 + x2*x2;
        #pragma unroll
        for (int o = 16; o; o >>= 1) ss += __shfl_xor_sync(0xffffffffu, ss, o);
        float r = rsqrtf(ss / (float)D + EPS_RMS);
        x1 *= r; x2 *= r;
        float o1 =  x1 * c + x2 * s;
        float o2 = -x1 * s + x2 * c;
        __nv_bfloat16 h, l;
        bsplit(o1, h, l); dh[lane] = h;      dl[lane] = l;
        bsplit(o2, h, l); dh[lane + 32] = h; dl[lane + 32] = l;
    }
}

// ======================= HMMA flash attention (QK bf16x3, PV fp16x2) =======================
#define AT_QHI 0
#define AT_QLO 16384
#define AT_STG 32768
#define AT_STGSZ 24576
#define AT_KHI 0
#define AT_KLO 8192
#define AT_V   16384
#define ATT_SMEM (32768 + 2*24576)

__global__ void __launch_bounds__(256) attn_mma_kernel(
    const __nv_bfloat16* __restrict__ qhi, const __nv_bfloat16* __restrict__ qlo,
    const __nv_bfloat16* __restrict__ khi, const __nv_bfloat16* __restrict__ klo,
    const __half* __restrict__ vv,
    __half* __restrict__ yhi, __half* __restrict__ ylo)
{
    extern __shared__ __align__(1024) char smem[];
    uint32_t sb = smem_to_u32(smem);
    int bh = blockIdx.y;
    int b = bh / H, hh = bh % H;
    int qb = blockIdx.x;
    int q0 = qb * 128;
    int tid = threadIdx.x, wid = tid >> 5, lid = tid & 31;
    int nkt = 2 * qb + 2;

    #pragma unroll
    for (int i = 0; i < 4; i++) {
        int lin = tid + i * 256;
        int r = lin >> 3, ch = lin & 7;
        uint32_t so = SMEM_SWIZZLE_128B((uint32_t)(r * 128 + ch * 16));
        size_t g = (size_t)(b*T + q0 + r) * C + hh * D + ch * 8;
        CP16(sb + AT_QHI + so, qhi + g);
        CP16(sb + AT_QLO + so, qlo + g);
    }
    asm volatile("cp.async.commit_group;" ::: "memory");
    #pragma unroll
    for (int i = 0; i < 2; i++) {
        int lin = tid + i * 256;
        int r = lin >> 3, ch = lin & 7;
        uint32_t so = SMEM_SWIZZLE_128B((uint32_t)(r * 128 + ch * 16));
        size_t g = (size_t)(b*T + r) * C + hh * D + ch * 8;
        uint32_t st = sb + AT_STG;
        CP16(st + AT_KHI + so, khi + g);
        CP16(st + AT_KLO + so, klo + g);
        CP16(st + AT_V   + so, vv  + g);
    }
    asm volatile("cp.async.commit_group;" ::: "memory");

    uint32_t qa_hi[4][4], qa_lo[4][4];
    float oac[8][4];
    #pragma unroll
    for (int j = 0; j < 8; j++)
        #pragma unroll
        for (int r = 0; r < 4; r++) oac[j][r] = 0.f;
    float m0 = -1e30f, m1 = -1e30f, l0 = 0.f, l1 = 0.f;

    int off = lid & 7, part = lid >> 3;
    int qr = lid >> 2, qc = (lid & 3) * 2;
    const float SC2 = 0.18033688011112042f;

    for (int kt = 0; kt < nkt; kt++) {
        if (kt + 1 < nkt) {
            #pragma unroll
            for (int i = 0; i < 2; i++) {
                int lin = tid + i * 256;
                int r = lin >> 3, ch = lin & 7;
                uint32_t so = SMEM_SWIZZLE_128B((uint32_t)(r * 128 + ch * 16));
                size_t g = (size_t)(b*T + (kt + 1) * 64 + r) * C + hh * D + ch * 8;
                uint32_t st = sb + AT_STG + (uint32_t)((kt + 1) & 1) * AT_STGSZ;
                CP16(st + AT_KHI + so, khi + g);
                CP16(st + AT_KLO + so, klo + g);
                CP16(st + AT_V   + so, vv  + g);
            }
            asm volatile("cp.async.commit_group;" ::: "memory");
            asm volatile("cp.async.wait_group 1;" ::: "memory");
        } else {
            asm volatile("cp.async.wait_group 0;" ::: "memory");
        }
        __syncthreads();

        if (kt == 0) {
            #pragma unroll
            for (int kk = 0; kk < 4; kk++) {
                int row = wid * 16 + (part & 1) * 8 + off;
                int colb = kk * 32 + (part & 2) * 8;
                uint32_t so = SMEM_SWIZZLE_128B((uint32_t)(row * 128 + colb));
                ldsm4(qa_hi[kk], sb + AT_QHI + so);
                ldsm4(qa_lo[kk], sb + AT_QLO + so);
            }
        }

        uint32_t st = sb + AT_STG + (uint32_t)(kt & 1) * AT_STGSZ;

        float s[8][4];
        #pragma unroll
        for (int j = 0; j < 8; j++)
            #pragma unroll
            for (int r = 0; r < 4; r++) s[j][r] = 0.f;
        #pragma unroll
        for (int kk = 0; kk < 4; kk++) {
            #pragma unroll
            for (int jj = 0; jj < 4; jj++) {
                int row = jj * 16 + (part & 2) * 4 + off;
                int colb = kk * 32 + (part & 1) * 16;
                uint32_t so = SMEM_SWIZZLE_128B((uint32_t)(row * 128 + colb));
                uint32_t kh[4], kl[4];
                ldsm4(kh, st + AT_KHI + so);
                ldsm4(kl, st + AT_KLO + so);
                mma_bf16(s[2*jj],     qa_hi[kk], kh);
                mma_bf16(s[2*jj],     qa_hi[kk], kl);
                mma_bf16(s[2*jj],     qa_lo[kk], kh);
                mma_bf16(s[2*jj+1],   qa_hi[kk], kh + 2);
                mma_bf16(s[2*jj+1],   qa_hi[kk], kl + 2);
                mma_bf16(s[2*jj+1],   qa_lo[kk], kh + 2);
            }
        }

        bool domask = (kt >= nkt - 2);
        #pragma unroll
        for (int j = 0; j < 8; j++) {
            #pragma unroll
            for (int r = 0; r < 4; r++) {
                float v = s[j][r] * SC2;
                if (domask) {
                    int key = kt * 64 + j * 8 + qc + (r & 1);
                    int row = q0 + wid * 16 + qr + (r & 2) * 4;
                    if (key > row) v = -1e30f;
                }
                s[j][r] = v;
            }
        }

        float mx0 = -1e30f, mx1 = -1e30f;
        #pragma unroll
        for (int j = 0; j < 8; j++) {
            mx0 = fmaxf(mx0, fmaxf(s[j][0], s[j][1]));
            mx1 = fmaxf(mx1, fmaxf(s[j][2], s[j][3]));
        }
        mx0 = fmaxf(mx0, __shfl_xor_sync(0xffffffffu, mx0, 1));
        mx0 = fmaxf(mx0, __shfl_xor_sync(0xffffffffu, mx0, 2));
        mx1 = fmaxf(mx1, __shfl_xor_sync(0xffffffffu, mx1, 1));
        mx1 = fmaxf(mx1, __shfl_xor_sync(0xffffffffu, mx1, 2));
        float mn0 = fmaxf(m0, mx0), mn1 = fmaxf(m1, mx1);
        float al0 = ex2f(m0 - mn0), al1 = ex2f(m1 - mn1);
        float sm0 = 0.f, sm1 = 0.f;
        #pragma unroll
        for (int j = 0; j < 8; j++) {
            s[j][0] = ex2f(s[j][0] - mn0); sm0 += s[j][0];
            s[j][1] = ex2f(s[j][1] - mn0); sm0 += s[j][1];
            s[j][2] = ex2f(s[j][2] - mn1); sm1 += s[j][2];
            s[j][3] = ex2f(s[j][3] - mn1); sm1 += s[j][3];
        }
        sm0 += __shfl_xor_sync(0xffffffffu, sm0, 1);
        sm0 += __shfl_xor_sync(0xffffffffu, sm0, 2);
        sm1 += __shfl_xor_sync(0xffffffffu, sm1, 1);
        sm1 += __shfl_xor_sync(0xffffffffu, sm1, 2);
        l0 = l0 * al0 + sm0;  l1 = l1 * al1 + sm1;
        m0 = mn0;  m1 = mn1;
        #pragma unroll
        for (int j = 0; j < 8; j++) {
            oac[j][0] *= al0; oac[j][1] *= al0;
            oac[j][2] *= al1; oac[j][3] *= al1;
        }

        // ---- O += P V  (P fp16 pair x V single fp16) ----
        #pragma unroll
        for (int kk = 0; kk < 4; kk++) {
            uint32_t pah[4], pal[4];
            packsplith(s[2*kk][0],   s[2*kk][1],   pah[0], pal[0]);
            packsplith(s[2*kk][2],   s[2*kk][3],   pah[1], pal[1]);
            packsplith(s[2*kk+1][0], s[2*kk+1][1], pah[2], pal[2]);
            packsplith(s[2*kk+1][2], s[2*kk+1][3], pah[3], pal[3]);
            #pragma unroll
            for (int jj = 0; jj < 4; jj++) {
                int row = kk * 16 + (part & 1) * 8 + off;
                int colb = jj * 32 + (part & 2) * 8;
                uint32_t so = SMEM_SWIZZLE_128B((uint32_t)(row * 128 + colb));
                uint32_t v4[4];
                ldsm4t(v4, st + AT_V + so);
                mma_f16(oac[2*jj],   pah, v4);
                mma_f16(oac[2*jj],   pal, v4);
                mma_f16(oac[2*jj+1], pah, v4 + 2);
                mma_f16(oac[2*jj+1], pal, v4 + 2);
            }
        }
        __syncthreads();
    }

    float inv0 = 1.f / l0, inv1 = 1.f / l1;
    #pragma unroll
    for (int j = 0; j < 8; j++) {
        size_t i0 = (size_t)(b*T + q0 + wid*16 + qr) * C + hh * D + j * 8 + qc;
        size_t i1 = (size_t)(b*T + q0 + wid*16 + qr + 8) * C + hh * D + j * 8 + qc;
        uint32_t ph, pl;
        packsplith(oac[j][0] * inv0, oac[j][1] * inv0, ph, pl);
        *(uint32_t*)(yhi + i0) = ph;  *(uint32_t*)(ylo + i0) = pl;
        packsplith(oac[j][2] * inv1, oac[j][3] * inv1, ph, pl);
        *(uint32_t*)(yhi + i1) = ph;  *(uint32_t*)(ylo + i1) = pl;
    }
}

// ======================= HMMA fp16x2 GEMM — 128x256 tile, A pair x B single ==============
// epi: 0 fp32; 1 fp32+resid; 2 relu(acc)^2 -> fp16 pair;
//      4 fused QKV: cols [0,2048) fp32 stride 2048, cols [2048,3072) single fp16 stride 1024
//      5 MoE scatter: out[token*N+col] = acc + resid[token*N+col]
#define KTILE 64
#define W_AH 0
#define W_AL 16384
#define W_B  32768
#define W_STAGE 65536
#define SMEM_GEMM_BYTES (2*W_STAGE)

__global__ void __launch_bounds__(256, 1) gemm_fp16x2(
    const __half* __restrict__ Ahi, const __half* __restrict__ Alo,
    const __half* __restrict__ Bw, size_t bstride,
    float* __restrict__ Cout,
    __half* __restrict__ Ohi, __half* __restrict__ Olo,
    const float* __restrict__ resid,
    const int* __restrict__ tileExpert,
    const int* __restrict__ tokOfRow,
    int N, int K, int epi)
{
    extern __shared__ __align__(1024) char smem[];
    int by = blockIdx.y, bx = blockIdx.x;
    int e = 0;
    if (tileExpert) { e = tileExpert[by]; if (e < 0) return; }
    const __half* Bh = Bw + (size_t)e * bstride;

    uint32_t sb = smem_to_u32(smem);
    int tid = threadIdx.x, wid = tid >> 5, lid = tid & 31;
    int wm = wid & 1, wn = wid >> 1;
    int row0 = by * 128, col0 = bx * 256;
    int nkt = K / KTILE;

    float acc[4][8][4];
    #pragma unroll
    for (int i = 0; i < 4; i++)
        #pragma unroll
        for (int j = 0; j < 8; j++)
            #pragma unroll
            for (int r = 0; r < 4; r++) acc[i][j][r] = 0.f;

    int lr = tid >> 3, lc = tid & 7;

    // preload stage 0
    {
        #pragma unroll
        for (int i = 0; i < 4; i++) {               // A: 128 rows (hi + lo)
            int r = lr + i * 32;
            uint32_t so = SMEM_SWIZZLE_128B((uint32_t)(r * 128 + lc * 16));
            size_t ga = (size_t)(row0 + r) * K + lc * 8;
            CP16(sb + W_AH + so, Ahi + ga);
            CP16(sb + W_AL + so, Alo + ga);
        }
        #pragma unroll
        for (int i = 0; i < 8; i++) {               // B: 256 rows (single)
            int r = lr + i * 32;
            uint32_t so = SMEM_SWIZZLE_128B((uint32_t)(r * 128 + lc * 16));
            size_t gb = (size_t)(col0 + r) * K + lc * 8;
            CP16(sb + W_B + so, Bh + gb);
        }
        asm volatile("cp.async.commit_group;" ::: "memory");
    }

    for (int kt = 0; kt < nkt; kt++) {
        uint32_t cur = (uint32_t)(kt & 1) * W_STAGE;
        if (kt + 1 < nkt) {
            uint32_t nxt = (uint32_t)((kt + 1) & 1) * W_STAGE;
            int k0 = (kt + 1) * KTILE;
            #pragma unroll
            for (int i = 0; i < 4; i++) {
                int r = lr + i * 32;
                uint32_t so = SMEM_SWIZZLE_128B((uint32_t)(r * 128 + lc * 16));
                size_t ga = (size_t)(row0 + r) * K + k0 + lc * 8;
                CP16(sb + nxt + W_AH + so, Ahi + ga);
                CP16(sb + nxt + W_AL + so, Alo + ga);
            }
            #pragma unroll
            for (int i = 0; i < 8; i++) {
                int r = lr + i * 32;
                uint32_t so = SMEM_SWIZZLE_128B((uint32_t)(r * 128 + lc * 16));
                size_t gb = (size_t)(col0 + r) * K + k0 + lc * 8;
                CP16(sb + nxt + W_B + so, Bh + gb);
            }
            asm volatile("cp.async.commit_group;" ::: "memory");
            asm volatile("cp.async.wait_group 1;" ::: "memory");
        } else {
            asm volatile("cp.async.wait_group 0;" ::: "memory");
        }
        __syncthreads();

        uint32_t sAH = sb + cur + W_AH, sAL = sb + cur + W_AL;
        uint32_t sB  = sb + cur + W_B;
        #pragma unroll
        for (int kk = 0; kk < 4; kk++) {
            int colb = (kk * 16 + (lid >> 4) * 8) * 2;
            uint32_t a_hi[4][4], a_lo[4][4];
            #pragma unroll
            for (int mf = 0; mf < 4; mf++) {
                int rowm = wm * 64 + mf * 16 + (lid & 15);
                uint32_t so = SMEM_SWIZZLE_128B((uint32_t)(rowm * 128 + colb));
                ldsm4(a_hi[mf], sAH + so);
                ldsm4(a_lo[mf], sAL + so);
            }
            uint32_t b[8][2];
            #pragma unroll
            for (int g = 0; g < 4; g++) {
                int rown = wn * 64 + g * 16 + (lid & 15);
                uint32_t so = SMEM_SWIZZLE_128B((uint32_t)(rown * 128 + colb));
                uint32_t r4[4];
                ldsm4(r4, sB + so);
                b[2*g][0] = r4[0]; b[2*g+1][0] = r4[1];
                b[2*g][1] = r4[2]; b[2*g+1][1] = r4[3];
            }
            #pragma unroll
            for (int mf = 0; mf < 4; mf++)
                #pragma unroll
                for (int nf = 0; nf < 8; nf++) {
                    mma_f16(acc[mf][nf], a_hi[mf], b[nf]);
                    mma_f16(acc[mf][nf], a_lo[mf], b[nf]);
                }
        }
        __syncthreads();
    }

    int qr = lid >> 2, qc = (lid & 3) * 2;
    #pragma unroll
    for (int mf = 0; mf < 4; mf++) {
        #pragma unroll
        for (int nf = 0; nf < 8; nf++) {
            float* cc = acc[mf][nf];
            int col = col0 + wn * 64 + nf * 8 + qc;
            #pragma unroll
            for (int half = 0; half < 2; half++) {
                int row = row0 + wm * 64 + mf * 16 + qr + half * 8;
                float v0 = cc[2*half], v1 = cc[2*half + 1];
                if (epi == 0) {
                    size_t idx = (size_t)row * N + col;
                    *(float2*)(Cout + idx) = make_float2(v0, v1);
                } else if (epi == 1) {
                    size_t idx = (size_t)row * N + col;
                    float2 rr = *(const float2*)(resid + idx);
                    *(float2*)(Cout + idx) = make_float2(v0 + rr.x, v1 + rr.y);
                } else if (epi == 4) {
                    if (col < 2048) {
                        size_t idx = (size_t)row * 2048 + col;
                        *(float2*)(Cout + idx) = make_float2(v0, v1);
                    } else {
                        size_t idx = (size_t)row * 1024 + (col - 2048);
                        __half2 p = __floats2half2_rn(v0, v1);
                        *(uint32_t*)(Ohi + idx) = *(uint32_t*)&p;
                    }
                } else if (epi == 5) {
                    int t = tokOfRow[row];
                    if (t >= 0) {
                        size_t idx = (size_t)t * N + col;
                        float2 rr = *(const float2*)(resid + idx);
                        *(float2*)(Cout + idx) = make_float2(v0 + rr.x, v1 + rr.y);
                    }
                } else {   // epi == 2: relu^2 -> fp16 pair
                    v0 = fmaxf(v0, 0.f); v0 *= v0;
                    v1 = fmaxf(v1, 0.f); v1 *= v1;
                    size_t idx = (size_t)row * N + col;
                    uint32_t ph, pl;
                    packsplith(v0, v1, ph, pl);
                    *(uint32_t*)(Ohi + idx) = ph;
                    *(uint32_t*)(Olo + idx) = pl;
                }
            }
        }
    }
}

// ======================= grouping / scalars =======================
__global__ void offsets_kernel() {
    if (threadIdx.x == 0 && blockIdx.x == 0) {
        int off = 0;
        for (int e = 0; e < E; e++) {
            g_segstart[e] = off;
            int padded = (g_counts[e] + 127) & ~127;
            for (int i = 0; i < padded / 128; i++)
                g_tileExpert[off / 128 + i] = e;
            off += padded;
        }
    }
}

__global__ void assign_kernel(const float* __restrict__ h2) {
    int t = blockIdx.x;
    __shared__ int slot_s;
    if (threadIdx.x == 0) {
        int e = g_expert[t];
        int slot = g_segstart[e] + atomicAdd(&g_cursor[e], 1);
        g_tokenOfRow[slot] = t;
        slot_s = slot;
    }
    __syncthreads();
    int s = slot_s;
    float4 v = ((const float4*)(h2 + (size_t)t * C))[threadIdx.x];
    uint32_t h01, l01, h23, l23;
    packsplith(v.x, v.y, h01, l01);
    packsplith(v.z, v.w, h23, l23);
    uint2* hp = (uint2*)(g_h2g_hi + (size_t)s * C);
    uint2* lp = (uint2*)(g_h2g_lo + (size_t)s * C);
    hp[threadIdx.x] = make_uint2(h01, h23);
    lp[threadIdx.x] = make_uint2(l01, l23);
}

__global__ void scalars_kernel(float* __restrict__ out) {
    if (threadIdx.x == 0 && blockIdx.x == 0) {
        const double NTOK = (double)BT;
        double aux = 0.0;
        for (int e = 0; e < E; e++) {
            double actual = (double)g_counts[e] / NTOK;
            double expd   = g_expsum[e] / NTOK;
            aux += actual * expd;
        }
        size_t base = (size_t)BT * C;
        out[base + 0] = (float)((double)E * aux);
        out[base + 1] = (float)(g_zsum / NTOK);
        out[base + 2] = (float)((g_entsum / NTOK) / log((double)E));
        for (int e = 0; e < E; e++)
            out[base + 3 + e] = (float)((double)g_counts[e] / NTOK);
    }
}

// ======================= launch =======================
static void* sym(const void* s) { void* p = nullptr; cudaGetSymbolAddress(&p, s); return p; }

extern "C" void kernel_launch(void* const* d_in, const int* in_sizes, int n_in,
                              void* d_out, int out_size)
{
    const float* x     = (const float*)d_in[0];
    const float* Wq    = (const float*)d_in[1];
    const float* Wk    = (const float*)d_in[2];
    const float* Wv    = (const float*)d_in[3];
    const float* Wo    = (const float*)d_in[4];
    const float* Wr    = (const float*)d_in[5];
    const float* Wfc   = (const float*)d_in[6];
    const float* Wproj = (const float*)d_in[7];
    float* out = (float*)d_out;

    static bool init_done = false;
    static cudaStream_t s2;
    static cudaEvent_t evFork, evWo, evMoE;
    if (!init_done) {
        cudaFuncSetAttribute(gemm_fp16x2, cudaFuncAttributeMaxDynamicSharedMemorySize, SMEM_GEMM_BYTES);
        cudaFuncSetAttribute(attn_mma_kernel, cudaFuncAttributeMaxDynamicSharedMemorySize, ATT_SMEM);
        cudaStreamCreateWithFlags(&s2, cudaStreamNonBlocking);
        cudaEventCreateWithFlags(&evFork, cudaEventDisableTiming);
        cudaEventCreateWithFlags(&evWo,   cudaEventDisableTiming);
        cudaEventCreateWithFlags(&evMoE,  cudaEventDisableTiming);
        init_done = true;
    }

    __half* h1h = (__half*)sym(g_h1_hi);
    __half* h1l = (__half*)sym(g_h1_lo);
    float* qk = (float*)sym(g_qk);
    __nv_bfloat16* qh = (__nv_bfloat16*)sym(g_qhi); __nv_bfloat16* ql = (__nv_bfloat16*)sym(g_qlo);
    __nv_bfloat16* kh = (__nv_bfloat16*)sym(g_khi); __nv_bfloat16* kl = (__nv_bfloat16*)sym(g_klo);
    __half* vh = (__half*)sym(g_vh);
    __half* yh = (__half*)sym(g_y_hi);
    __half* yl = (__half*)sym(g_y_lo);
    float* x2 = (float*)sym(g_x2);
    float* h2 = (float*)sym(g_h2);
    __half* h2gh = (__half*)sym(g_h2g_hi);
    __half* h2gl = (__half*)sym(g_h2g_lo);
    __half* hidh = (__half*)sym(g_hid_hi);
    __half* hidl = (__half*)sym(g_hid_lo);
    __half* wqkv = (__half*)sym(g_wqkv);
    __half* wo   = (__half*)sym(g_wo);
    __half* wfc  = (__half*)sym(g_wfc);
    __half* wpj  = (__half*)sym(g_wpj);
    int* tileE = (int*)sym(g_tileExpert);
    int* tokR  = (int*)sym(g_tokenOfRow);

    // ---- main stream (0): front section ----
    reset_kernel<<<(GROUP_CAP + 255) / 256, 256>>>();
    cudaEventRecord(evFork, 0);

    // ---- side stream: weight conversions needed later ----
    cudaStreamWaitEvent(s2, evFork, 0);
    wconv_kernel<<<dim3(C/64,  C/64,  1), 256, 0, s2>>>(Wo,    wo,  C,  C);
    cudaEventRecord(evWo, s2);
    wconv_kernel<<<dim3(FF/64, C/64,  E), 256, 0, s2>>>(Wfc,   wfc, C,  FF);
    wconv_kernel<<<dim3(C/64,  FF/64, E), 256, 0, s2>>>(Wproj, wpj, FF, C);
    cudaEventRecord(evMoE, s2);

    // ---- main stream continues ----
    rmsnorm_kernel<<<BT, 256>>>(x, h1h, h1l);
    wconv_kernel<<<dim3(C/64, C/64, 1), 256>>>(Wq, wqkv,         C, C);
    wconv_kernel<<<dim3(C/64, C/64, 1), 256>>>(Wk, wqkv + C*C,   C, C);
    wconv_kernel<<<dim3(C/64, C/64, 1), 256>>>(Wv, wqkv + 2*C*C, C, C);
    gemm_fp16x2<<<dim3(3*C/256, BT/128), 256, SMEM_GEMM_BYTES>>>(
        h1h, h1l, wqkv, 0, qk, vh, nullptr, nullptr, nullptr, nullptr, 3*C, C, 4);
    qk_rope_kernel<<<BT, 512>>>(qk, qh, ql, kh, kl);
    attn_mma_kernel<<<dim3(T/128, Bq*H), 256, ATT_SMEM>>>(
        qh, ql, kh, kl, vh, yh, yl);

    cudaStreamWaitEvent(0, evWo, 0);
    gemm_fp16x2<<<dim3(C/256, BT/128), 256, SMEM_GEMM_BYTES>>>(
        yh, yl, wo, 0, x2, nullptr, nullptr, x, nullptr, nullptr, C, C, 1);
    rmsnorm_router_kernel<<<BT, 256>>>(x2, h2, Wr);
    offsets_kernel<<<1, 32>>>();
    assign_kernel<<<BT, 256>>>(h2);

    cudaStreamWaitEvent(0, evMoE, 0);
    gemm_fp16x2<<<dim3(FF/256, NTILES), 256, SMEM_GEMM_BYTES>>>(
        h2gh, h2gl, wfc, (size_t)FF * C, nullptr, hidh, hidl, nullptr, tileE, nullptr, FF, C, 2);
    gemm_fp16x2<<<dim3(C/256, NTILES), 256, SMEM_GEMM_BYTES>>>(
        hidh, hidl, wpj, (size_t)C * FF, out, nullptr, nullptr, x2, tileE, tokR, C, FF, 5);
    scalars_kernel<<<1, 32>>>(out);
}

// round 13
// speedup vs baseline: 1.6489x; 1.1458x over previous
#include <cuda_runtime.h>
#include <cuda_bf16.h>
#include <cuda_fp16.h>
#include <cstdint>
#include <math.h>

#define Bq 2
#define T 2048
#define C 1024
#define H 16
#define D 64
#define E 4
#define BT (Bq*T)
#define FF (4*C)
#define GROUP_CAP (BT + E*128)
#define NTILES (GROUP_CAP/128)
#define EPS_RMS 1.1920929e-07f

#define SMEM_SWIZZLE_128B(b) ((b) ^ (((b) >> 3) & 0x70))

__device__ __forceinline__ uint32_t smem_to_u32(const void* p) {
    uint32_t a;
    asm("{ .reg .u64 t; cvta.to.shared.u64 t, %1; cvt.u32.u64 %0, t; }" : "=r"(a) : "l"(p));
    return a;
}
__device__ __forceinline__ void ldsm4(uint32_t* r, uint32_t addr) {
    asm volatile("ldmatrix.sync.aligned.m8n8.x4.shared.b16 {%0,%1,%2,%3}, [%4];"
                 : "=r"(r[0]), "=r"(r[1]), "=r"(r[2]), "=r"(r[3]) : "r"(addr));
}
__device__ __forceinline__ void ldsm4t(uint32_t* r, uint32_t addr) {
    asm volatile("ldmatrix.sync.aligned.m8n8.x4.trans.shared.b16 {%0,%1,%2,%3}, [%4];"
                 : "=r"(r[0]), "=r"(r[1]), "=r"(r[2]), "=r"(r[3]) : "r"(addr));
}
__device__ __forceinline__ void mma_bf16(float* c, const uint32_t* a, const uint32_t* b) {
    asm volatile("mma.sync.aligned.m16n8k16.row.col.f32.bf16.bf16.f32 "
        "{%0,%1,%2,%3}, {%4,%5,%6,%7}, {%8,%9}, {%0,%1,%2,%3};"
        : "+f"(c[0]), "+f"(c[1]), "+f"(c[2]), "+f"(c[3])
        : "r"(a[0]), "r"(a[1]), "r"(a[2]), "r"(a[3]), "r"(b[0]), "r"(b[1]));
}
__device__ __forceinline__ void mma_f16(float* c, const uint32_t* a, const uint32_t* b) {
    asm volatile("mma.sync.aligned.m16n8k16.row.col.f32.f16.f16.f32 "
        "{%0,%1,%2,%3}, {%4,%5,%6,%7}, {%8,%9}, {%0,%1,%2,%3};"
        : "+f"(c[0]), "+f"(c[1]), "+f"(c[2]), "+f"(c[3])
        : "r"(a[0]), "r"(a[1]), "r"(a[2]), "r"(a[3]), "r"(b[0]), "r"(b[1]));
}
__device__ __forceinline__ float ex2f(float x) {
    float y; asm("ex2.approx.ftz.f32 %0, %1;" : "=f"(y) : "f"(x)); return y;
}
#define CP16(s, g) asm volatile("cp.async.cg.shared.global [%0], [%1], 16;" \
                                :: "r"(s), "l"(g) : "memory")

// ======================= scratch (static device globals) =======================
__device__ __half g_h1_hi[BT*C], g_h1_lo[BT*C];
__device__ float g_qk[BT*2*C];
__device__ __nv_bfloat16 g_qhi[BT*C], g_qlo[BT*C];
__device__ __nv_bfloat16 g_khi[BT*C], g_klo[BT*C];
__device__ __half g_vh[BT*C];
__device__ __half g_y_hi[BT*C], g_y_lo[BT*C];
__device__ float g_x2[BT*C], g_h2[BT*C];
__device__ __half g_h2g_hi[GROUP_CAP*C], g_h2g_lo[GROUP_CAP*C];
__device__ __half g_hid[(size_t)GROUP_CAP*FF];
__device__ __half g_wqkv[3*C*C];
__device__ __half g_wo[C*C];
__device__ __half g_wfc[(size_t)E*C*FF];   // [E][FF,C]
__device__ __half g_wpj[(size_t)E*FF*C];   // [E][C,FF]
__device__ int   g_expert[BT];
__device__ int   g_counts[E];
__device__ int   g_cursor[E];
__device__ int   g_segstart[E];
__device__ int   g_tileExpert[NTILES];
__device__ int   g_tokenOfRow[GROUP_CAP];
__device__ double g_expsum[E];
__device__ double g_zsum;
__device__ double g_entsum;

__device__ __forceinline__ void bsplit(float v, __nv_bfloat16& h, __nv_bfloat16& l) {
    h = __float2bfloat16(v);
    l = __float2bfloat16(v - __bfloat162float(h));
}
__device__ __forceinline__ void hsplit(float v, __half& h, __half& l) {
    h = __float2half(v);
    l = __float2half(v - __half2float(h));
}
__device__ __forceinline__ void packsplith(float v0, float v1, uint32_t& hi, uint32_t& lo) {
    __half h0, l0, h1, l1;
    hsplit(v0, h0, l0); hsplit(v1, h1, l1);
    __half2 hh(h0, h1), ll(l0, l1);
    hi = *reinterpret_cast<uint32_t*>(&hh);
    lo = *reinterpret_cast<uint32_t*>(&ll);
}

// ======================= small kernels =======================
__global__ void reset_kernel() {
    int i = blockIdx.x * blockDim.x + threadIdx.x;
    if (i < E) { g_counts[i] = 0; g_cursor[i] = 0; g_expsum[i] = 0.0; }
    if (i == 0) { g_zsum = 0.0; g_entsum = 0.0; }
    if (i < NTILES) g_tileExpert[i] = -1;
    if (i < GROUP_CAP) g_tokenOfRow[i] = -1;
}

// transpose weights: W [Kd, Nd] fp32 -> T [Nd, Kd] single fp16
__global__ void __launch_bounds__(256) wconv_kernel(
    const float* __restrict__ W, __half* __restrict__ Th, int Kd, int Nd) {
    __shared__ float tile[64][65];
    int b = blockIdx.z;
    const float* Wb = W + (size_t)b * Kd * Nd;
    __half* Tb = Th + (size_t)b * Kd * Nd;
    int n0 = blockIdx.x * 64, k0 = blockIdx.y * 64;
    int tid = threadIdx.x;
    int lr = tid >> 4, lc = (tid & 15) * 4;
    #pragma unroll
    for (int i = 0; i < 4; i++) {
        int k = lr + i * 16;
        float4 v = *(const float4*)(Wb + (size_t)(k0 + k) * Nd + n0 + lc);
        tile[k][lc] = v.x; tile[k][lc+1] = v.y; tile[k][lc+2] = v.z; tile[k][lc+3] = v.w;
    }
    __syncthreads();
    int wn = tid >> 4, wk = (tid & 15) * 4;
    #pragma unroll
    for (int i = 0; i < 4; i++) {
        int n = wn + i * 16;
        __half2 p01 = __floats2half2_rn(tile[wk][n],   tile[wk+1][n]);
        __half2 p23 = __floats2half2_rn(tile[wk+2][n], tile[wk+3][n]);
        size_t o = (size_t)(n0 + n) * Kd + k0 + wk;
        *(uint2*)(Tb + o) = make_uint2(*(uint32_t*)&p01, *(uint32_t*)&p23);
    }
}

// RMSNorm over C -> fp16 hi/lo pair
__global__ void rmsnorm_kernel(const float* __restrict__ in,
                               __half* __restrict__ ohi, __half* __restrict__ olo) {
    int t = blockIdx.x;
    const float4* ip = (const float4*)(in + (size_t)t * C);
    __shared__ float red[8];
    float4 v = ip[threadIdx.x];
    float ss = v.x*v.x + v.y*v.y + v.z*v.z + v.w*v.w;
    #pragma unroll
    for (int o = 16; o; o >>= 1) ss += __shfl_xor_sync(0xffffffffu, ss, o);
    if ((threadIdx.x & 31) == 0) red[threadIdx.x >> 5] = ss;
    __syncthreads();
    if (threadIdx.x == 0) {
        float s = 0.f;
        #pragma unroll
        for (int w = 0; w < 8; w++) s += red[w];
        red[0] = s;
    }
    __syncthreads();
    float r = rsqrtf(red[0] / (float)C + EPS_RMS);
    float4 o = make_float4(v.x*r, v.y*r, v.z*r, v.w*r);
    uint32_t h01, l01, h23, l23;
    packsplith(o.x, o.y, h01, l01);
    packsplith(o.z, o.w, h23, l23);
    uint2* hp = (uint2*)(ohi + (size_t)t * C);
    uint2* lp = (uint2*)(olo + (size_t)t * C);
    hp[threadIdx.x] = make_uint2(h01, h23);
    lp[threadIdx.x] = make_uint2(l01, l23);
}

// RMSNorm fp32 out + fused router
__global__ void rmsnorm_router_kernel(const float* __restrict__ in, float* __restrict__ outf,
                                      const float* __restrict__ Wr) {
    int t = blockIdx.x;
    const float4* ip = (const float4*)(in + (size_t)t * C);
    __shared__ float red[8];
    __shared__ float lred[32];
    float4 v = ip[threadIdx.x];
    float ss = v.x*v.x + v.y*v.y + v.z*v.z + v.w*v.w;
    #pragma unroll
    for (int o = 16; o; o >>= 1) ss += __shfl_xor_sync(0xffffffffu, ss, o);
    if ((threadIdx.x & 31) == 0) red[threadIdx.x >> 5] = ss;
    __syncthreads();
    if (threadIdx.x == 0) {
        float s = 0.f;
        #pragma unroll
        for (int w = 0; w < 8; w++) s += red[w];
        red[0] = s;
    }
    __syncthreads();
    float r = rsqrtf(red[0] / (float)C + EPS_RMS);
    float4 o = make_float4(v.x*r, v.y*r, v.z*r, v.w*r);
    ((float4*)(outf + (size_t)t * C))[threadIdx.x] = o;

    int c0 = threadIdx.x * 4;
    float4 w0 = *(const float4*)(Wr + (size_t)(c0+0) * E);
    float4 w1 = *(const float4*)(Wr + (size_t)(c0+1) * E);
    float4 w2 = *(const float4*)(Wr + (size_t)(c0+2) * E);
    float4 w3 = *(const float4*)(Wr + (size_t)(c0+3) * E);
    float a0 = o.x*w0.x + o.y*w1.x + o.z*w2.x + o.w*w3.x;
    float a1 = o.x*w0.y + o.y*w1.y + o.z*w2.y + o.w*w3.y;
    float a2 = o.x*w0.z + o.y*w1.z + o.z*w2.z + o.w*w3.z;
    float a3 = o.x*w0.w + o.y*w1.w + o.z*w2.w + o.w*w3.w;
    #pragma unroll
    for (int off = 16; off; off >>= 1) {
        a0 += __shfl_xor_sync(0xffffffffu, a0, off);
        a1 += __shfl_xor_sync(0xffffffffu, a1, off);
        a2 += __shfl_xor_sync(0xffffffffu, a2, off);
        a3 += __shfl_xor_sync(0xffffffffu, a3, off);
    }
    if ((threadIdx.x & 31) == 0) {
        int w = threadIdx.x >> 5;
        lred[w*4+0] = a0; lred[w*4+1] = a1; lred[w*4+2] = a2; lred[w*4+3] = a3;
    }
    __syncthreads();
    if (threadIdx.x == 0) {
        float lg[4];
        #pragma unroll
        for (int e = 0; e < 4; e++) {
            float s = 0.f;
            #pragma unroll
            for (int w = 0; w < 8; w++) s += lred[w*4+e];
            lg[e] = s;
        }
        int arg = 0;
        #pragma unroll
        for (int e = 1; e < 4; e++) if (lg[e] > lg[arg]) arg = e;
        float m = fmaxf(fmaxf(lg[0], lg[1]), fmaxf(lg[2], lg[3]));
        float ez[4]; float sum = 0.f;
        #pragma unroll
        for (int e = 0; e < 4; e++) { ez[e] = expf(lg[e] - m); sum += ez[e]; }
        float p[4];
        #pragma unroll
        for (int e = 0; e < 4; e++) p[e] = ez[e] / sum;
        g_expert[t] = arg;
        atomicAdd(&g_counts[arg], 1);
        #pragma unroll
        for (int e = 0; e < 4; e++) atomicAdd(&g_expsum[e], (double)p[e]);
        float lse = m + logf(sum);
        atomicAdd(&g_zsum, (double)lse * (double)lse);
        float ent = 0.f;
        #pragma unroll
        for (int e = 0; e < 4; e++) ent -= p[e] * logf(p[e] + 1e-9f);
        atomicAdd(&g_entsum, (double)ent);
    }
}

// per-head RMSNorm + RoPE; reads qk buffer [BT, 2048]; q/k bf16 pairs out
__global__ void qk_rope_kernel(const float* __restrict__ qk,
                               __nv_bfloat16* __restrict__ qhi, __nv_bfloat16* __restrict__ qlo,
                               __nv_bfloat16* __restrict__ khi, __nv_bfloat16* __restrict__ klo) {
    int tok  = blockIdx.x;
    int head = threadIdx.x >> 5;
    int lane = threadIdx.x & 31;
    int tpos = tok % T;
    float ex  = (float)(2 * lane) / 64.0f;
    float inv = 1.0f / powf(10000.0f, ex);
    float ang = (float)tpos * inv;
    float c = cosf(ang), s = sinf(ang);
    size_t obase = (size_t)tok * C + head * D;
    #pragma unroll
    for (int m = 0; m < 2; m++) {
        const float* src = qk + (size_t)tok * 2048 + m * 1024 + head * D;
        __nv_bfloat16* dh = (m == 0 ? qhi : khi) + obase;
        __nv_bfloat16* dl = (m == 0 ? qlo : klo) + obase;
        float x1 = src[lane], x2 = src[lane + 32];
        float ss = x1*x1 + x2*x2;
        #pragma unroll
        for (int o = 16; o; o >>= 1) ss += __shfl_xor_sync(0xffffffffu, ss, o);
        float r = rsqrtf(ss / (float)D + EPS_RMS);
        x1 *= r; x2 *= r;
        float o1 =  x1 * c + x2 * s;
        float o2 = -x1 * s + x2 * c;
        __nv_bfloat16 h, l;
        bsplit(o1, h, l); dh[lane] = h;      dl[lane] = l;
        bsplit(o2, h, l); dh[lane + 32] = h; dl[lane + 32] = l;
    }
}

// ======================= HMMA flash attention (QK bf16x3, PV fp16x2) =======================
#define AT_QHI 0
#define AT_QLO 16384
#define AT_STG 32768
#define AT_STGSZ 24576
#define AT_KHI 0
#define AT_KLO 8192
#define AT_V   16384
#define ATT_SMEM (32768 + 2*24576)

__global__ void __launch_bounds__(256) attn_mma_kernel(
    const __nv_bfloat16* __restrict__ qhi, const __nv_bfloat16* __restrict__ qlo,
    const __nv_bfloat16* __restrict__ khi, const __nv_bfloat16* __restrict__ klo,
    const __half* __restrict__ vv,
    __half* __restrict__ yhi, __half* __restrict__ ylo)
{
    extern __shared__ __align__(1024) char smem[];
    uint32_t sb = smem_to_u32(smem);
    int bh = blockIdx.y;
    int b = bh / H, hh = bh % H;
    int qb = blockIdx.x;
    int q0 = qb * 128;
    int tid = threadIdx.x, wid = tid >> 5, lid = tid & 31;
    int nkt = 2 * qb + 2;

    #pragma unroll
    for (int i = 0; i < 4; i++) {
        int lin = tid + i * 256;
        int r = lin >> 3, ch = lin & 7;
        uint32_t so = SMEM_SWIZZLE_128B((uint32_t)(r * 128 + ch * 16));
        size_t g = (size_t)(b*T + q0 + r) * C + hh * D + ch * 8;
        CP16(sb + AT_QHI + so, qhi + g);
        CP16(sb + AT_QLO + so, qlo + g);
    }
    asm volatile("cp.async.commit_group;" ::: "memory");
    #pragma unroll
    for (int i = 0; i < 2; i++) {
        int lin = tid + i * 256;
        int r = lin >> 3, ch = lin & 7;
        uint32_t so = SMEM_SWIZZLE_128B((uint32_t)(r * 128 + ch * 16));
        size_t g = (size_t)(b*T + r) * C + hh * D + ch * 8;
        uint32_t st = sb + AT_STG;
        CP16(st + AT_KHI + so, khi + g);
        CP16(st + AT_KLO + so, klo + g);
        CP16(st + AT_V   + so, vv  + g);
    }
    asm volatile("cp.async.commit_group;" ::: "memory");

    uint32_t qa_hi[4][4], qa_lo[4][4];
    float oac[8][4];
    #pragma unroll
    for (int j = 0; j < 8; j++)
        #pragma unroll
        for (int r = 0; r < 4; r++) oac[j][r] = 0.f;
    float m0 = -1e30f, m1 = -1e30f, l0 = 0.f, l1 = 0.f;

    int off = lid & 7, part = lid >> 3;
    int qr = lid >> 2, qc = (lid & 3) * 2;
    const float SC2 = 0.18033688011112042f;

    for (int kt = 0; kt < nkt; kt++) {
        if (kt + 1 < nkt) {
            #pragma unroll
            for (int i = 0; i < 2; i++) {
                int lin = tid + i * 256;
                int r = lin >> 3, ch = lin & 7;
                uint32_t so = SMEM_SWIZZLE_128B((uint32_t)(r * 128 + ch * 16));
                size_t g = (size_t)(b*T + (kt + 1) * 64 + r) * C + hh * D + ch * 8;
                uint32_t st = sb + AT_STG + (uint32_t)((kt + 1) & 1) * AT_STGSZ;
                CP16(st + AT_KHI + so, khi + g);
                CP16(st + AT_KLO + so, klo + g);
                CP16(st + AT_V   + so, vv  + g);
            }
            asm volatile("cp.async.commit_group;" ::: "memory");
            asm volatile("cp.async.wait_group 1;" ::: "memory");
        } else {
            asm volatile("cp.async.wait_group 0;" ::: "memory");
        }
        __syncthreads();

        if (kt == 0) {
            #pragma unroll
            for (int kk = 0; kk < 4; kk++) {
                int row = wid * 16 + (part & 1) * 8 + off;
                int colb = kk * 32 + (part & 2) * 8;
                uint32_t so = SMEM_SWIZZLE_128B((uint32_t)(row * 128 + colb));
                ldsm4(qa_hi[kk], sb + AT_QHI + so);
                ldsm4(qa_lo[kk], sb + AT_QLO + so);
            }
        }

        uint32_t st = sb + AT_STG + (uint32_t)(kt & 1) * AT_STGSZ;

        float s[8][4];
        #pragma unroll
        for (int j = 0; j < 8; j++)
            #pragma unroll
            for (int r = 0; r < 4; r++) s[j][r] = 0.f;
        #pragma unroll
        for (int kk = 0; kk < 4; kk++) {
            #pragma unroll
            for (int jj = 0; jj < 4; jj++) {
                int row = jj * 16 + (part & 2) * 4 + off;
                int colb = kk * 32 + (part & 1) * 16;
                uint32_t so = SMEM_SWIZZLE_128B((uint32_t)(row * 128 + colb));
                uint32_t kh[4], kl[4];
                ldsm4(kh, st + AT_KHI + so);
                ldsm4(kl, st + AT_KLO + so);
                mma_bf16(s[2*jj],     qa_hi[kk], kh);
                mma_bf16(s[2*jj],     qa_hi[kk], kl);
                mma_bf16(s[2*jj],     qa_lo[kk], kh);
                mma_bf16(s[2*jj+1],   qa_hi[kk], kh + 2);
                mma_bf16(s[2*jj+1],   qa_hi[kk], kl + 2);
                mma_bf16(s[2*jj+1],   qa_lo[kk], kh + 2);
            }
        }

        bool domask = (kt >= nkt - 2);
        #pragma unroll
        for (int j = 0; j < 8; j++) {
            #pragma unroll
            for (int r = 0; r < 4; r++) {
                float v = s[j][r] * SC2;
                if (domask) {
                    int key = kt * 64 + j * 8 + qc + (r & 1);
                    int row = q0 + wid * 16 + qr + (r & 2) * 4;
                    if (key > row) v = -1e30f;
                }
                s[j][r] = v;
            }
        }

        float mx0 = -1e30f, mx1 = -1e30f;
        #pragma unroll
        for (int j = 0; j < 8; j++) {
            mx0 = fmaxf(mx0, fmaxf(s[j][0], s[j][1]));
            mx1 = fmaxf(mx1, fmaxf(s[j][2], s[j][3]));
        }
        mx0 = fmaxf(mx0, __shfl_xor_sync(0xffffffffu, mx0, 1));
        mx0 = fmaxf(mx0, __shfl_xor_sync(0xffffffffu, mx0, 2));
        mx1 = fmaxf(mx1, __shfl_xor_sync(0xffffffffu, mx1, 1));
        mx1 = fmaxf(mx1, __shfl_xor_sync(0xffffffffu, mx1, 2));
        float mn0 = fmaxf(m0, mx0), mn1 = fmaxf(m1, mx1);
        float al0 = ex2f(m0 - mn0), al1 = ex2f(m1 - mn1);
        float sm0 = 0.f, sm1 = 0.f;
        #pragma unroll
        for (int j = 0; j < 8; j++) {
            s[j][0] = ex2f(s[j][0] - mn0); sm0 += s[j][0];
            s[j][1] = ex2f(s[j][1] - mn0); sm0 += s[j][1];
            s[j][2] = ex2f(s[j][2] - mn1); sm1 += s[j][2];
            s[j][3] = ex2f(s[j][3] - mn1); sm1 += s[j][3];
        }
        sm0 += __shfl_xor_sync(0xffffffffu, sm0, 1);
        sm0 += __shfl_xor_sync(0xffffffffu, sm0, 2);
        sm1 += __shfl_xor_sync(0xffffffffu, sm1, 1);
        sm1 += __shfl_xor_sync(0xffffffffu, sm1, 2);
        l0 = l0 * al0 + sm0;  l1 = l1 * al1 + sm1;
        m0 = mn0;  m1 = mn1;
        #pragma unroll
        for (int j = 0; j < 8; j++) {
            oac[j][0] *= al0; oac[j][1] *= al0;
            oac[j][2] *= al1; oac[j][3] *= al1;
        }

        #pragma unroll
        for (int kk = 0; kk < 4; kk++) {
            uint32_t pah[4], pal[4];
            packsplith(s[2*kk][0],   s[2*kk][1],   pah[0], pal[0]);
            packsplith(s[2*kk][2],   s[2*kk][3],   pah[1], pal[1]);
            packsplith(s[2*kk+1][0], s[2*kk+1][1], pah[2], pal[2]);
            packsplith(s[2*kk+1][2], s[2*kk+1][3], pah[3], pal[3]);
            #pragma unroll
            for (int jj = 0; jj < 4; jj++) {
                int row = kk * 16 + (part & 1) * 8 + off;
                int colb = jj * 32 + (part & 2) * 8;
                uint32_t so = SMEM_SWIZZLE_128B((uint32_t)(row * 128 + colb));
                uint32_t v4[4];
                ldsm4t(v4, st + AT_V + so);
                mma_f16(oac[2*jj],   pah, v4);
                mma_f16(oac[2*jj],   pal, v4);
                mma_f16(oac[2*jj+1], pah, v4 + 2);
                mma_f16(oac[2*jj+1], pal, v4 + 2);
            }
        }
        __syncthreads();
    }

    float inv0 = 1.f / l0, inv1 = 1.f / l1;
    #pragma unroll
    for (int j = 0; j < 8; j++) {
        size_t i0 = (size_t)(b*T + q0 + wid*16 + qr) * C + hh * D + j * 8 + qc;
        size_t i1 = (size_t)(b*T + q0 + wid*16 + qr + 8) * C + hh * D + j * 8 + qc;
        uint32_t ph, pl;
        packsplith(oac[j][0] * inv0, oac[j][1] * inv0, ph, pl);
        *(uint32_t*)(yhi + i0) = ph;  *(uint32_t*)(ylo + i0) = pl;
        packsplith(oac[j][2] * inv1, oac[j][3] * inv1, ph, pl);
        *(uint32_t*)(yhi + i1) = ph;  *(uint32_t*)(ylo + i1) = pl;
    }
}

// ======================= HMMA fp16x2 GEMM — 128x256 tile, A pair x B single ==============
// epi: 0 fp32; 1 fp32+resid; 2 relu(acc)^2 -> SINGLE fp16;
//      4 fused QKV: cols [0,2048) fp32 stride 2048, cols [2048,3072) single fp16 stride 1024
#define KTILE 64
#define W_AH 0
#define W_AL 16384
#define W_B  32768
#define W_STAGE 65536
#define SMEM_GEMM_BYTES (2*W_STAGE)

__global__ void __launch_bounds__(256, 1) gemm_fp16x2(
    const __half* __restrict__ Ahi, const __half* __restrict__ Alo,
    const __half* __restrict__ Bw, size_t bstride,
    float* __restrict__ Cout,
    __half* __restrict__ Oh,
    const float* __restrict__ resid,
    const int* __restrict__ tileExpert,
    int N, int K, int epi)
{
    extern __shared__ __align__(1024) char smem[];
    int by = blockIdx.y, bx = blockIdx.x;
    int e = 0;
    if (tileExpert) { e = tileExpert[by]; if (e < 0) return; }
    const __half* Bh = Bw + (size_t)e * bstride;

    uint32_t sb = smem_to_u32(smem);
    int tid = threadIdx.x, wid = tid >> 5, lid = tid & 31;
    int wm = wid & 1, wn = wid >> 1;
    int row0 = by * 128, col0 = bx * 256;
    int nkt = K / KTILE;

    float acc[4][8][4];
    #pragma unroll
    for (int i = 0; i < 4; i++)
        #pragma unroll
        for (int j = 0; j < 8; j++)
            #pragma unroll
            for (int r = 0; r < 4; r++) acc[i][j][r] = 0.f;

    int lr = tid >> 3, lc = tid & 7;

    {
        #pragma unroll
        for (int i = 0; i < 4; i++) {
            int r = lr + i * 32;
            uint32_t so = SMEM_SWIZZLE_128B((uint32_t)(r * 128 + lc * 16));
            size_t ga = (size_t)(row0 + r) * K + lc * 8;
            CP16(sb + W_AH + so, Ahi + ga);
            CP16(sb + W_AL + so, Alo + ga);
        }
        #pragma unroll
        for (int i = 0; i < 8; i++) {
            int r = lr + i * 32;
            uint32_t so = SMEM_SWIZZLE_128B((uint32_t)(r * 128 + lc * 16));
            size_t gb = (size_t)(col0 + r) * K + lc * 8;
            CP16(sb + W_B + so, Bh + gb);
        }
        asm volatile("cp.async.commit_group;" ::: "memory");
    }

    for (int kt = 0; kt < nkt; kt++) {
        uint32_t cur = (uint32_t)(kt & 1) * W_STAGE;
        if (kt + 1 < nkt) {
            uint32_t nxt = (uint32_t)((kt + 1) & 1) * W_STAGE;
            int k0 = (kt + 1) * KTILE;
            #pragma unroll
            for (int i = 0; i < 4; i++) {
                int r = lr + i * 32;
                uint32_t so = SMEM_SWIZZLE_128B((uint32_t)(r * 128 + lc * 16));
                size_t ga = (size_t)(row0 + r) * K + k0 + lc * 8;
                CP16(sb + nxt + W_AH + so, Ahi + ga);
                CP16(sb + nxt + W_AL + so, Alo + ga);
            }
            #pragma unroll
            for (int i = 0; i < 8; i++) {
                int r = lr + i * 32;
                uint32_t so = SMEM_SWIZZLE_128B((uint32_t)(r * 128 + lc * 16));
                size_t gb = (size_t)(col0 + r) * K + k0 + lc * 8;
                CP16(sb + nxt + W_B + so, Bh + gb);
            }
            asm volatile("cp.async.commit_group;" ::: "memory");
            asm volatile("cp.async.wait_group 1;" ::: "memory");
        } else {
            asm volatile("cp.async.wait_group 0;" ::: "memory");
        }
        __syncthreads();

        uint32_t sAH = sb + cur + W_AH, sAL = sb + cur + W_AL;
        uint32_t sB  = sb + cur + W_B;
        #pragma unroll
        for (int kk = 0; kk < 4; kk++) {
            int colb = (kk * 16 + (lid >> 4) * 8) * 2;
            uint32_t a_hi[4][4], a_lo[4][4];
            #pragma unroll
            for (int mf = 0; mf < 4; mf++) {
                int rowm = wm * 64 + mf * 16 + (lid & 15);
                uint32_t so = SMEM_SWIZZLE_128B((uint32_t)(rowm * 128 + colb));
                ldsm4(a_hi[mf], sAH + so);
                ldsm4(a_lo[mf], sAL + so);
            }
            uint32_t b[8][2];
            #pragma unroll
            for (int g = 0; g < 4; g++) {
                int rown = wn * 64 + g * 16 + (lid & 15);
                uint32_t so = SMEM_SWIZZLE_128B((uint32_t)(rown * 128 + colb));
                uint32_t r4[4];
                ldsm4(r4, sB + so);
                b[2*g][0] = r4[0]; b[2*g+1][0] = r4[1];
                b[2*g][1] = r4[2]; b[2*g+1][1] = r4[3];
            }
            #pragma unroll
            for (int mf = 0; mf < 4; mf++)
                #pragma unroll
                for (int nf = 0; nf < 8; nf++) {
                    mma_f16(acc[mf][nf], a_hi[mf], b[nf]);
                    mma_f16(acc[mf][nf], a_lo[mf], b[nf]);
                }
        }
        __syncthreads();
    }

    int qr = lid >> 2, qc = (lid & 3) * 2;
    #pragma unroll
    for (int mf = 0; mf < 4; mf++) {
        #pragma unroll
        for (int nf = 0; nf < 8; nf++) {
            float* cc = acc[mf][nf];
            int col = col0 + wn * 64 + nf * 8 + qc;
            #pragma unroll
            for (int half = 0; half < 2; half++) {
                int row = row0 + wm * 64 + mf * 16 + qr + half * 8;
                float v0 = cc[2*half], v1 = cc[2*half + 1];
                if (epi == 0) {
                    size_t idx = (size_t)row * N + col;
                    *(float2*)(Cout + idx) = make_float2(v0, v1);
                } else if (epi == 1) {
                    size_t idx = (size_t)row * N + col;
                    float2 rr = *(const float2*)(resid + idx);
                    *(float2*)(Cout + idx) = make_float2(v0 + rr.x, v1 + rr.y);
                } else if (epi == 4) {
                    if (col < 2048) {
                        size_t idx = (size_t)row * 2048 + col;
                        *(float2*)(Cout + idx) = make_float2(v0, v1);
                    } else {
                        size_t idx = (size_t)row * 1024 + (col - 2048);
                        __half2 p = __floats2half2_rn(v0, v1);
                        *(uint32_t*)(Oh + idx) = *(uint32_t*)&p;
                    }
                } else {   // epi == 2: relu^2 -> single fp16
                    v0 = fmaxf(v0, 0.f); v0 *= v0;
                    v1 = fmaxf(v1, 0.f); v1 *= v1;
                    size_t idx = (size_t)row * N + col;
                    __half2 p = __floats2half2_rn(v0, v1);
                    *(uint32_t*)(Oh + idx) = *(uint32_t*)&p;
                }
            }
        }
    }
}

// ======================= HMMA fp16x1 GEMM — A single x B single, 1 MMA ====================
// epi: 5 MoE scatter: out[token*N+col] = acc + resid[token*N+col]
#define X_A 0
#define X_B 16384
#define X_STAGE 49152
#define SMEM_GEMM1_BYTES (2*X_STAGE)

__global__ void __launch_bounds__(256, 1) gemm_fp16x1(
    const __half* __restrict__ Aw,
    const __half* __restrict__ Bw, size_t bstride,
    float* __restrict__ Cout,
    const float* __restrict__ resid,
    const int* __restrict__ tileExpert,
    const int* __restrict__ tokOfRow,
    int N, int K)
{
    extern __shared__ __align__(1024) char smem[];
    int by = blockIdx.y, bx = blockIdx.x;
    int e = tileExpert[by];
    if (e < 0) return;
    const __half* Bh = Bw + (size_t)e * bstride;

    uint32_t sb = smem_to_u32(smem);
    int tid = threadIdx.x, wid = tid >> 5, lid = tid & 31;
    int wm = wid & 1, wn = wid >> 1;
    int row0 = by * 128, col0 = bx * 256;
    int nkt = K / KTILE;

    float acc[4][8][4];
    #pragma unroll
    for (int i = 0; i < 4; i++)
        #pragma unroll
        for (int j = 0; j < 8; j++)
            #pragma unroll
            for (int r = 0; r < 4; r++) acc[i][j][r] = 0.f;

    int lr = tid >> 3, lc = tid & 7;

    {
        #pragma unroll
        for (int i = 0; i < 4; i++) {
            int r = lr + i * 32;
            uint32_t so = SMEM_SWIZZLE_128B((uint32_t)(r * 128 + lc * 16));
            size_t ga = (size_t)(row0 + r) * K + lc * 8;
            CP16(sb + X_A + so, Aw + ga);
        }
        #pragma unroll
        for (int i = 0; i < 8; i++) {
            int r = lr + i * 32;
            uint32_t so = SMEM_SWIZZLE_128B((uint32_t)(r * 128 + lc * 16));
            size_t gb = (size_t)(col0 + r) * K + lc * 8;
            CP16(sb + X_B + so, Bh + gb);
        }
        asm volatile("cp.async.commit_group;" ::: "memory");
    }

    for (int kt = 0; kt < nkt; kt++) {
        uint32_t cur = (uint32_t)(kt & 1) * X_STAGE;
        if (kt + 1 < nkt) {
            uint32_t nxt = (uint32_t)((kt + 1) & 1) * X_STAGE;
            int k0 = (kt + 1) * KTILE;
            #pragma unroll
            for (int i = 0; i < 4; i++) {
                int r = lr + i * 32;
                uint32_t so = SMEM_SWIZZLE_128B((uint32_t)(r * 128 + lc * 16));
                size_t ga = (size_t)(row0 + r) * K + k0 + lc * 8;
                CP16(sb + nxt + X_A + so, Aw + ga);
            }
            #pragma unroll
            for (int i = 0; i < 8; i++) {
                int r = lr + i * 32;
                uint32_t so = SMEM_SWIZZLE_128B((uint32_t)(r * 128 + lc * 16));
                size_t gb = (size_t)(col0 + r) * K + k0 + lc * 8;
                CP16(sb + nxt + X_B + so, Bh + gb);
            }
            asm volatile("cp.async.commit_group;" ::: "memory");
            asm volatile("cp.async.wait_group 1;" ::: "memory");
        } else {
            asm volatile("cp.async.wait_group 0;" ::: "memory");
        }
        __syncthreads();

        uint32_t sA = sb + cur + X_A, sB = sb + cur + X_B;
        #pragma unroll
        for (int kk = 0; kk < 4; kk++) {
            int colb = (kk * 16 + (lid >> 4) * 8) * 2;
            uint32_t a[4][4];
            #pragma unroll
            for (int mf = 0; mf < 4; mf++) {
                int rowm = wm * 64 + mf * 16 + (lid & 15);
                uint32_t so = SMEM_SWIZZLE_128B((uint32_t)(rowm * 128 + colb));
                ldsm4(a[mf], sA + so);
            }
            uint32_t b[8][2];
            #pragma unroll
            for (int g = 0; g < 4; g++) {
                int rown = wn * 64 + g * 16 + (lid & 15);
                uint32_t so = SMEM_SWIZZLE_128B((uint32_t)(rown * 128 + colb));
                uint32_t r4[4];
                ldsm4(r4, sB + so);
                b[2*g][0] = r4[0]; b[2*g+1][0] = r4[1];
                b[2*g][1] = r4[2]; b[2*g+1][1] = r4[3];
            }
            #pragma unroll
            for (int mf = 0; mf < 4; mf++)
                #pragma unroll
                for (int nf = 0; nf < 8; nf++)
                    mma_f16(acc[mf][nf], a[mf], b[nf]);
        }
        __syncthreads();
    }

    int qr = lid >> 2, qc = (lid & 3) * 2;
    #pragma unroll
    for (int mf = 0; mf < 4; mf++) {
        #pragma unroll
        for (int nf = 0; nf < 8; nf++) {
            float* cc = acc[mf][nf];
            int col = col0 + wn * 64 + nf * 8 + qc;
            #pragma unroll
            for (int half = 0; half < 2; half++) {
                int row = row0 + wm * 64 + mf * 16 + qr + half * 8;
                int t = tokOfRow[row];
                if (t >= 0) {
                    size_t idx = (size_t)t * N + col;
                    float2 rr = *(const float2*)(resid + idx);
                    *(float2*)(Cout + idx) =
                        make_float2(cc[2*half] + rr.x, cc[2*half + 1] + rr.y);
                }
            }
        }
    }
}

// ======================= grouping / scalars =======================
__global__ void offsets_kernel() {
    if (threadIdx.x == 0 && blockIdx.x == 0) {
        int off = 0;
        for (int e = 0; e < E; e++) {
            g_segstart[e] = off;
            int padded = (g_counts[e] + 127) & ~127;
            for (int i = 0; i < padded / 128; i++)
                g_tileExpert[off / 128 + i] = e;
            off += padded;
        }
    }
}

__global__ void assign_kernel(const float* __restrict__ h2) {
    int t = blockIdx.x;
    __shared__ int slot_s;
    if (threadIdx.x == 0) {
        int e = g_expert[t];
        int slot = g_segstart[e] + atomicAdd(&g_cursor[e], 1);
        g_tokenOfRow[slot] = t;
        slot_s = slot;
    }
    __syncthreads();
    int s = slot_s;
    float4 v = ((const float4*)(h2 + (size_t)t * C))[threadIdx.x];
    uint32_t h01, l01, h23, l23;
    packsplith(v.x, v.y, h01, l01);
    packsplith(v.z, v.w, h23, l23);
    uint2* hp = (uint2*)(g_h2g_hi + (size_t)s * C);
    uint2* lp = (uint2*)(g_h2g_lo + (size_t)s * C);
    hp[threadIdx.x] = make_uint2(h01, h23);
    lp[threadIdx.x] = make_uint2(l01, l23);
}

__global__ void scalars_kernel(float* __restrict__ out) {
    if (threadIdx.x == 0 && blockIdx.x == 0) {
        const double NTOK = (double)BT;
        double aux = 0.0;
        for (int e = 0; e < E; e++) {
            double actual = (double)g_counts[e] / NTOK;
            double expd   = g_expsum[e] / NTOK;
            aux += actual * expd;
        }
        size_t base = (size_t)BT * C;
        out[base + 0] = (float)((double)E * aux);
        out[base + 1] = (float)(g_zsum / NTOK);
        out[base + 2] = (float)((g_entsum / NTOK) / log((double)E));
        for (int e = 0; e < E; e++)
            out[base + 3 + e] = (float)((double)g_counts[e] / NTOK);
    }
}

// ======================= launch =======================
static void* sym(const void* s) { void* p = nullptr; cudaGetSymbolAddress(&p, s); return p; }

extern "C" void kernel_launch(void* const* d_in, const int* in_sizes, int n_in,
                              void* d_out, int out_size)
{
    const float* x     = (const float*)d_in[0];
    const float* Wq    = (const float*)d_in[1];
    const float* Wk    = (const float*)d_in[2];
    const float* Wv    = (const float*)d_in[3];
    const float* Wo    = (const float*)d_in[4];
    const float* Wr    = (const float*)d_in[5];
    const float* Wfc   = (const float*)d_in[6];
    const float* Wproj = (const float*)d_in[7];
    float* out = (float*)d_out;

    static bool init_done = false;
    static cudaStream_t s2;
    static cudaEvent_t evFork, evWo, evMoE;
    if (!init_done) {
        cudaFuncSetAttribute(gemm_fp16x2, cudaFuncAttributeMaxDynamicSharedMemorySize, SMEM_GEMM_BYTES);
        cudaFuncSetAttribute(gemm_fp16x1, cudaFuncAttributeMaxDynamicSharedMemorySize, SMEM_GEMM1_BYTES);
        cudaFuncSetAttribute(attn_mma_kernel, cudaFuncAttributeMaxDynamicSharedMemorySize, ATT_SMEM);
        cudaStreamCreateWithFlags(&s2, cudaStreamNonBlocking);
        cudaEventCreateWithFlags(&evFork, cudaEventDisableTiming);
        cudaEventCreateWithFlags(&evWo,   cudaEventDisableTiming);
        cudaEventCreateWithFlags(&evMoE,  cudaEventDisableTiming);
        init_done = true;
    }

    __half* h1h = (__half*)sym(g_h1_hi);
    __half* h1l = (__half*)sym(g_h1_lo);
    float* qk = (float*)sym(g_qk);
    __nv_bfloat16* qh = (__nv_bfloat16*)sym(g_qhi); __nv_bfloat16* ql = (__nv_bfloat16*)sym(g_qlo);
    __nv_bfloat16* kh = (__nv_bfloat16*)sym(g_khi); __nv_bfloat16* kl = (__nv_bfloat16*)sym(g_klo);
    __half* vh = (__half*)sym(g_vh);
    __half* yh = (__half*)sym(g_y_hi);
    __half* yl = (__half*)sym(g_y_lo);
    float* x2 = (float*)sym(g_x2);
    float* h2 = (float*)sym(g_h2);
    __half* h2gh = (__half*)sym(g_h2g_hi);
    __half* h2gl = (__half*)sym(g_h2g_lo);
    __half* hid  = (__half*)sym(g_hid);
    __half* wqkv = (__half*)sym(g_wqkv);
    __half* wo   = (__half*)sym(g_wo);
    __half* wfc  = (__half*)sym(g_wfc);
    __half* wpj  = (__half*)sym(g_wpj);
    int* tileE = (int*)sym(g_tileExpert);
    int* tokR  = (int*)sym(g_tokenOfRow);

    // ---- main stream (0): front section ----
    reset_kernel<<<(GROUP_CAP + 255) / 256, 256>>>();
    cudaEventRecord(evFork, 0);

    // ---- side stream: weight conversions needed later ----
    cudaStreamWaitEvent(s2, evFork, 0);
    wconv_kernel<<<dim3(C/64,  C/64,  1), 256, 0, s2>>>(Wo,    wo,  C,  C);
    cudaEventRecord(evWo, s2);
    wconv_kernel<<<dim3(FF/64, C/64,  E), 256, 0, s2>>>(Wfc,   wfc, C,  FF);
    wconv_kernel<<<dim3(C/64,  FF/64, E), 256, 0, s2>>>(Wproj, wpj, FF, C);
    cudaEventRecord(evMoE, s2);

    // ---- main stream continues ----
    rmsnorm_kernel<<<BT, 256>>>(x, h1h, h1l);
    wconv_kernel<<<dim3(C/64, C/64, 1), 256>>>(Wq, wqkv,         C, C);
    wconv_kernel<<<dim3(C/64, C/64, 1), 256>>>(Wk, wqkv + C*C,   C, C);
    wconv_kernel<<<dim3(C/64, C/64, 1), 256>>>(Wv, wqkv + 2*C*C, C, C);
    gemm_fp16x2<<<dim3(3*C/256, BT/128), 256, SMEM_GEMM_BYTES>>>(
        h1h, h1l, wqkv, 0, qk, vh, nullptr, nullptr, 3*C, C, 4);
    qk_rope_kernel<<<BT, 512>>>(qk, qh, ql, kh, kl);
    attn_mma_kernel<<<dim3(T/128, Bq*H), 256, ATT_SMEM>>>(
        qh, ql, kh, kl, vh, yh, yl);

    cudaStreamWaitEvent(0, evWo, 0);
    gemm_fp16x2<<<dim3(C/256, BT/128), 256, SMEM_GEMM_BYTES>>>(
        yh, yl, wo, 0, x2, nullptr, x, nullptr, C, C, 1);
    rmsnorm_router_kernel<<<BT, 256>>>(x2, h2, Wr);
    offsets_kernel<<<1, 32>>>();
    assign_kernel<<<BT, 256>>>(h2);

    cudaStreamWaitEvent(0, evMoE, 0);
    gemm_fp16x2<<<dim3(FF/256, NTILES), 256, SMEM_GEMM_BYTES>>>(
        h2gh, h2gl, wfc, (size_t)FF * C, nullptr, hid, nullptr, tileE, FF, C, 2);
    gemm_fp16x1<<<dim3(C/256, NTILES), 256, SMEM_GEMM1_BYTES>>>(
        hid, wpj, (size_t)C * FF, out, x2, tileE, tokR, C, FF);
    scalars_kernel<<<1, 32>>>(out);
}

// round 14
// speedup vs baseline: 1.9338x; 1.1728x over previous
#include <cuda_runtime.h>
#include <cuda_bf16.h>
#include <cuda_fp16.h>
#include <cstdint>
#include <math.h>

#define Bq 2
#define T 2048
#define C 1024
#define H 16
#define D 64
#define E 4
#define BT (Bq*T)
#define FF (4*C)
#define GROUP_CAP (BT + E*128)
#define NTILES (GROUP_CAP/128)
#define EPS_RMS 1.1920929e-07f

#define SMEM_SWIZZLE_128B(b) ((b) ^ (((b) >> 3) & 0x70))

__device__ __forceinline__ uint32_t smem_to_u32(const void* p) {
    uint32_t a;
    asm("{ .reg .u64 t; cvta.to.shared.u64 t, %1; cvt.u32.u64 %0, t; }" : "=r"(a) : "l"(p));
    return a;
}
__device__ __forceinline__ void ldsm4(uint32_t* r, uint32_t addr) {
    asm volatile("ldmatrix.sync.aligned.m8n8.x4.shared.b16 {%0,%1,%2,%3}, [%4];"
                 : "=r"(r[0]), "=r"(r[1]), "=r"(r[2]), "=r"(r[3]) : "r"(addr));
}
__device__ __forceinline__ void ldsm4t(uint32_t* r, uint32_t addr) {
    asm volatile("ldmatrix.sync.aligned.m8n8.x4.trans.shared.b16 {%0,%1,%2,%3}, [%4];"
                 : "=r"(r[0]), "=r"(r[1]), "=r"(r[2]), "=r"(r[3]) : "r"(addr));
}
__device__ __forceinline__ void mma_bf16(float* c, const uint32_t* a, const uint32_t* b) {
    asm volatile("mma.sync.aligned.m16n8k16.row.col.f32.bf16.bf16.f32 "
        "{%0,%1,%2,%3}, {%4,%5,%6,%7}, {%8,%9}, {%0,%1,%2,%3};"
        : "+f"(c[0]), "+f"(c[1]), "+f"(c[2]), "+f"(c[3])
        : "r"(a[0]), "r"(a[1]), "r"(a[2]), "r"(a[3]), "r"(b[0]), "r"(b[1]));
}
__device__ __forceinline__ void mma_f16(float* c, const uint32_t* a, const uint32_t* b) {
    asm volatile("mma.sync.aligned.m16n8k16.row.col.f32.f16.f16.f32 "
        "{%0,%1,%2,%3}, {%4,%5,%6,%7}, {%8,%9}, {%0,%1,%2,%3};"
        : "+f"(c[0]), "+f"(c[1]), "+f"(c[2]), "+f"(c[3])
        : "r"(a[0]), "r"(a[1]), "r"(a[2]), "r"(a[3]), "r"(b[0]), "r"(b[1]));
}
__device__ __forceinline__ float ex2f(float x) {
    float y; asm("ex2.approx.ftz.f32 %0, %1;" : "=f"(y) : "f"(x)); return y;
}
#define CP16(s, g) asm volatile("cp.async.cg.shared.global [%0], [%1], 16;" \
                                :: "r"(s), "l"(g) : "memory")

// ======================= scratch (static device globals) =======================
__device__ __half g_h1_hi[BT*C], g_h1_lo[BT*C];
__device__ float g_qk[BT*2*C];
__device__ __nv_bfloat16 g_qhi[BT*C], g_qlo[BT*C];
__device__ __nv_bfloat16 g_khi[BT*C], g_klo[BT*C];
__device__ __half g_vh[BT*C];
__device__ __half g_y[BT*C];
__device__ float g_x2[BT*C], g_h2[BT*C];
__device__ __half g_h2g[GROUP_CAP*C];
__device__ __half g_hid[(size_t)GROUP_CAP*FF];
__device__ __half g_wqkv[3*C*C];
__device__ __half g_wo[C*C];
__device__ __half g_wfc[(size_t)E*C*FF];   // [E][FF,C]
__device__ __half g_wpj[(size_t)E*FF*C];   // [E][C,FF]
__device__ int   g_expert[BT];
__device__ int   g_counts[E];
__device__ int   g_cursor[E];
__device__ int   g_segstart[E];
__device__ int   g_tileExpert[NTILES];
__device__ int   g_tokenOfRow[GROUP_CAP];
__device__ double g_expsum[E];
__device__ double g_zsum;
__device__ double g_entsum;

__device__ __forceinline__ void bsplit(float v, __nv_bfloat16& h, __nv_bfloat16& l) {
    h = __float2bfloat16(v);
    l = __float2bfloat16(v - __bfloat162float(h));
}
__device__ __forceinline__ void hsplit(float v, __half& h, __half& l) {
    h = __float2half(v);
    l = __float2half(v - __half2float(h));
}
__device__ __forceinline__ void packsplith(float v0, float v1, uint32_t& hi, uint32_t& lo) {
    __half h0, l0, h1, l1;
    hsplit(v0, h0, l0); hsplit(v1, h1, l1);
    __half2 hh(h0, h1), ll(l0, l1);
    hi = *reinterpret_cast<uint32_t*>(&hh);
    lo = *reinterpret_cast<uint32_t*>(&ll);
}

// ======================= small kernels =======================
__global__ void reset_kernel() {
    int i = blockIdx.x * blockDim.x + threadIdx.x;
    if (i < E) { g_counts[i] = 0; g_cursor[i] = 0; g_expsum[i] = 0.0; }
    if (i == 0) { g_zsum = 0.0; g_entsum = 0.0; }
    if (i < NTILES) g_tileExpert[i] = -1;
    if (i < GROUP_CAP) g_tokenOfRow[i] = -1;
}

// transpose weights: W [Kd, Nd] fp32 -> T [Nd, Kd] single fp16
__global__ void __launch_bounds__(256) wconv_kernel(
    const float* __restrict__ W, __half* __restrict__ Th, int Kd, int Nd) {
    __shared__ float tile[64][65];
    int b = blockIdx.z;
    const float* Wb = W + (size_t)b * Kd * Nd;
    __half* Tb = Th + (size_t)b * Kd * Nd;
    int n0 = blockIdx.x * 64, k0 = blockIdx.y * 64;
    int tid = threadIdx.x;
    int lr = tid >> 4, lc = (tid & 15) * 4;
    #pragma unroll
    for (int i = 0; i < 4; i++) {
        int k = lr + i * 16;
        float4 v = *(const float4*)(Wb + (size_t)(k0 + k) * Nd + n0 + lc);
        tile[k][lc] = v.x; tile[k][lc+1] = v.y; tile[k][lc+2] = v.z; tile[k][lc+3] = v.w;
    }
    __syncthreads();
    int wn = tid >> 4, wk = (tid & 15) * 4;
    #pragma unroll
    for (int i = 0; i < 4; i++) {
        int n = wn + i * 16;
        __half2 p01 = __floats2half2_rn(tile[wk][n],   tile[wk+1][n]);
        __half2 p23 = __floats2half2_rn(tile[wk+2][n], tile[wk+3][n]);
        size_t o = (size_t)(n0 + n) * Kd + k0 + wk;
        *(uint2*)(Tb + o) = make_uint2(*(uint32_t*)&p01, *(uint32_t*)&p23);
    }
}

// RMSNorm over C -> fp16 hi/lo pair
__global__ void rmsnorm_kernel(const float* __restrict__ in,
                               __half* __restrict__ ohi, __half* __restrict__ olo) {
    int t = blockIdx.x;
    const float4* ip = (const float4*)(in + (size_t)t * C);
    __shared__ float red[8];
    float4 v = ip[threadIdx.x];
    float ss = v.x*v.x + v.y*v.y + v.z*v.z + v.w*v.w;
    #pragma unroll
    for (int o = 16; o; o >>= 1) ss += __shfl_xor_sync(0xffffffffu, ss, o);
    if ((threadIdx.x & 31) == 0) red[threadIdx.x >> 5] = ss;
    __syncthreads();
    if (threadIdx.x == 0) {
        float s = 0.f;
        #pragma unroll
        for (int w = 0; w < 8; w++) s += red[w];
        red[0] = s;
    }
    __syncthreads();
    float r = rsqrtf(red[0] / (float)C + EPS_RMS);
    float4 o = make_float4(v.x*r, v.y*r, v.z*r, v.w*r);
    uint32_t h01, l01, h23, l23;
    packsplith(o.x, o.y, h01, l01);
    packsplith(o.z, o.w, h23, l23);
    uint2* hp = (uint2*)(ohi + (size_t)t * C);
    uint2* lp = (uint2*)(olo + (size_t)t * C);
    hp[threadIdx.x] = make_uint2(h01, h23);
    lp[threadIdx.x] = make_uint2(l01, l23);
}

// RMSNorm fp32 out + fused router
__global__ void rmsnorm_router_kernel(const float* __restrict__ in, float* __restrict__ outf,
                                      const float* __restrict__ Wr) {
    int t = blockIdx.x;
    const float4* ip = (const float4*)(in + (size_t)t * C);
    __shared__ float red[8];
    __shared__ float lred[32];
    float4 v = ip[threadIdx.x];
    float ss = v.x*v.x + v.y*v.y + v.z*v.z + v.w*v.w;
    #pragma unroll
    for (int o = 16; o; o >>= 1) ss += __shfl_xor_sync(0xffffffffu, ss, o);
    if ((threadIdx.x & 31) == 0) red[threadIdx.x >> 5] = ss;
    __syncthreads();
    if (threadIdx.x == 0) {
        float s = 0.f;
        #pragma unroll
        for (int w = 0; w < 8; w++) s += red[w];
        red[0] = s;
    }
    __syncthreads();
    float r = rsqrtf(red[0] / (float)C + EPS_RMS);
    float4 o = make_float4(v.x*r, v.y*r, v.z*r, v.w*r);
    ((float4*)(outf + (size_t)t * C))[threadIdx.x] = o;

    int c0 = threadIdx.x * 4;
    float4 w0 = *(const float4*)(Wr + (size_t)(c0+0) * E);
    float4 w1 = *(const float4*)(Wr + (size_t)(c0+1) * E);
    float4 w2 = *(const float4*)(Wr + (size_t)(c0+2) * E);
    float4 w3 = *(const float4*)(Wr + (size_t)(c0+3) * E);
    float a0 = o.x*w0.x + o.y*w1.x + o.z*w2.x + o.w*w3.x;
    float a1 = o.x*w0.y + o.y*w1.y + o.z*w2.y + o.w*w3.y;
    float a2 = o.x*w0.z + o.y*w1.z + o.z*w2.z + o.w*w3.z;
    float a3 = o.x*w0.w + o.y*w1.w + o.z*w2.w + o.w*w3.w;
    #pragma unroll
    for (int off = 16; off; off >>= 1) {
        a0 += __shfl_xor_sync(0xffffffffu, a0, off);
        a1 += __shfl_xor_sync(0xffffffffu, a1, off);
        a2 += __shfl_xor_sync(0xffffffffu, a2, off);
        a3 += __shfl_xor_sync(0xffffffffu, a3, off);
    }
    if ((threadIdx.x & 31) == 0) {
        int w = threadIdx.x >> 5;
        lred[w*4+0] = a0; lred[w*4+1] = a1; lred[w*4+2] = a2; lred[w*4+3] = a3;
    }
    __syncthreads();
    if (threadIdx.x == 0) {
        float lg[4];
        #pragma unroll
        for (int e = 0; e < 4; e++) {
            float s = 0.f;
            #pragma unroll
            for (int w = 0; w < 8; w++) s += lred[w*4+e];
            lg[e] = s;
        }
        int arg = 0;
        #pragma unroll
        for (int e = 1; e < 4; e++) if (lg[e] > lg[arg]) arg = e;
        float m = fmaxf(fmaxf(lg[0], lg[1]), fmaxf(lg[2], lg[3]));
        float ez[4]; float sum = 0.f;
        #pragma unroll
        for (int e = 0; e < 4; e++) { ez[e] = expf(lg[e] - m); sum += ez[e]; }
        float p[4];
        #pragma unroll
        for (int e = 0; e < 4; e++) p[e] = ez[e] / sum;
        g_expert[t] = arg;
        atomicAdd(&g_counts[arg], 1);
        #pragma unroll
        for (int e = 0; e < 4; e++) atomicAdd(&g_expsum[e], (double)p[e]);
        float lse = m + logf(sum);
        atomicAdd(&g_zsum, (double)lse * (double)lse);
        float ent = 0.f;
        #pragma unroll
        for (int e = 0; e < 4; e++) ent -= p[e] * logf(p[e] + 1e-9f);
        atomicAdd(&g_entsum, (double)ent);
    }
}

// per-head RMSNorm + RoPE; reads qk buffer [BT, 2048]; q/k bf16 pairs out
__global__ void qk_rope_kernel(const float* __restrict__ qk,
                               __nv_bfloat16* __restrict__ qhi, __nv_bfloat16* __restrict__ qlo,
                               __nv_bfloat16* __restrict__ khi, __nv_bfloat16* __restrict__ klo) {
    int tok  = blockIdx.x;
    int head = threadIdx.x >> 5;
    int lane = threadIdx.x & 31;
    int tpos = tok % T;
    float ex  = (float)(2 * lane) / 64.0f;
    float inv = 1.0f / powf(10000.0f, ex);
    float ang = (float)tpos * inv;
    float c = cosf(ang), s = sinf(ang);
    size_t obase = (size_t)tok * C + head * D;
    #pragma unroll
    for (int m = 0; m < 2; m++) {
        const float* src = qk + (size_t)tok * 2048 + m * 1024 + head * D;
        __nv_bfloat16* dh = (m == 0 ? qhi : khi) + obase;
        __nv_bfloat16* dl = (m == 0 ? qlo : klo) + obase;
        float x1 = src[lane], x2 = src[lane + 32];
        float ss = x1*x1 + x2*x2;
        #pragma unroll
        for (int o = 16; o; o >>= 1) ss += __shfl_xor_sync(0xffffffffu, ss, o);
        float r = rsqrtf(ss / (float)D + EPS_RMS);
        x1 *= r; x2 *= r;
        float o1 =  x1 * c + x2 * s;
        float o2 = -x1 * s + x2 * c;
        __nv_bfloat16 h, l;
        bsplit(o1, h, l); dh[lane] = h;      dl[lane] = l;
        bsplit(o2, h, l); dh[lane + 32] = h; dl[lane + 32] = l;
    }
}

// ======================= HMMA flash attention (QK bf16x3, PV fp16x2) =======================
#define AT_QHI 0
#define AT_QLO 16384
#define AT_STG 32768
#define AT_STGSZ 24576
#define AT_KHI 0
#define AT_KLO 8192
#define AT_V   16384
#define ATT_SMEM (32768 + 2*24576)

__global__ void __launch_bounds__(256) attn_mma_kernel(
    const __nv_bfloat16* __restrict__ qhi, const __nv_bfloat16* __restrict__ qlo,
    const __nv_bfloat16* __restrict__ khi, const __nv_bfloat16* __restrict__ klo,
    const __half* __restrict__ vv,
    __half* __restrict__ yo)
{
    extern __shared__ __align__(1024) char smem[];
    uint32_t sb = smem_to_u32(smem);
    int bh = blockIdx.y;
    int b = bh / H, hh = bh % H;
    int qb = blockIdx.x;
    int q0 = qb * 128;
    int tid = threadIdx.x, wid = tid >> 5, lid = tid & 31;
    int nkt = 2 * qb + 2;

    #pragma unroll
    for (int i = 0; i < 4; i++) {
        int lin = tid + i * 256;
        int r = lin >> 3, ch = lin & 7;
        uint32_t so = SMEM_SWIZZLE_128B((uint32_t)(r * 128 + ch * 16));
        size_t g = (size_t)(b*T + q0 + r) * C + hh * D + ch * 8;
        CP16(sb + AT_QHI + so, qhi + g);
        CP16(sb + AT_QLO + so, qlo + g);
    }
    asm volatile("cp.async.commit_group;" ::: "memory");
    #pragma unroll
    for (int i = 0; i < 2; i++) {
        int lin = tid + i * 256;
        int r = lin >> 3, ch = lin & 7;
        uint32_t so = SMEM_SWIZZLE_128B((uint32_t)(r * 128 + ch * 16));
        size_t g = (size_t)(b*T + r) * C + hh * D + ch * 8;
        uint32_t st = sb + AT_STG;
        CP16(st + AT_KHI + so, khi + g);
        CP16(st + AT_KLO + so, klo + g);
        CP16(st + AT_V   + so, vv  + g);
    }
    asm volatile("cp.async.commit_group;" ::: "memory");

    uint32_t qa_hi[4][4], qa_lo[4][4];
    float oac[8][4];
    #pragma unroll
    for (int j = 0; j < 8; j++)
        #pragma unroll
        for (int r = 0; r < 4; r++) oac[j][r] = 0.f;
    float m0 = -1e30f, m1 = -1e30f, l0 = 0.f, l1 = 0.f;

    int off = lid & 7, part = lid >> 3;
    int qr = lid >> 2, qc = (lid & 3) * 2;
    const float SC2 = 0.18033688011112042f;

    for (int kt = 0; kt < nkt; kt++) {
        if (kt + 1 < nkt) {
            #pragma unroll
            for (int i = 0; i < 2; i++) {
                int lin = tid + i * 256;
                int r = lin >> 3, ch = lin & 7;
                uint32_t so = SMEM_SWIZZLE_128B((uint32_t)(r * 128 + ch * 16));
                size_t g = (size_t)(b*T + (kt + 1) * 64 + r) * C + hh * D + ch * 8;
                uint32_t st = sb + AT_STG + (uint32_t)((kt + 1) & 1) * AT_STGSZ;
                CP16(st + AT_KHI + so, khi + g);
                CP16(st + AT_KLO + so, klo + g);
                CP16(st + AT_V   + so, vv  + g);
            }
            asm volatile("cp.async.commit_group;" ::: "memory");
            asm volatile("cp.async.wait_group 1;" ::: "memory");
        } else {
            asm volatile("cp.async.wait_group 0;" ::: "memory");
        }
        __syncthreads();

        if (kt == 0) {
            #pragma unroll
            for (int kk = 0; kk < 4; kk++) {
                int row = wid * 16 + (part & 1) * 8 + off;
                int colb = kk * 32 + (part & 2) * 8;
                uint32_t so = SMEM_SWIZZLE_128B((uint32_t)(row * 128 + colb));
                ldsm4(qa_hi[kk], sb + AT_QHI + so);
                ldsm4(qa_lo[kk], sb + AT_QLO + so);
            }
        }

        uint32_t st = sb + AT_STG + (uint32_t)(kt & 1) * AT_STGSZ;

        float s[8][4];
        #pragma unroll
        for (int j = 0; j < 8; j++)
            #pragma unroll
            for (int r = 0; r < 4; r++) s[j][r] = 0.f;
        #pragma unroll
        for (int kk = 0; kk < 4; kk++) {
            #pragma unroll
            for (int jj = 0; jj < 4; jj++) {
                int row = jj * 16 + (part & 2) * 4 + off;
                int colb = kk * 32 + (part & 1) * 16;
                uint32_t so = SMEM_SWIZZLE_128B((uint32_t)(row * 128 + colb));
                uint32_t kh[4], kl[4];
                ldsm4(kh, st + AT_KHI + so);
                ldsm4(kl, st + AT_KLO + so);
                mma_bf16(s[2*jj],     qa_hi[kk], kh);
                mma_bf16(s[2*jj],     qa_hi[kk], kl);
                mma_bf16(s[2*jj],     qa_lo[kk], kh);
                mma_bf16(s[2*jj+1],   qa_hi[kk], kh + 2);
                mma_bf16(s[2*jj+1],   qa_hi[kk], kl + 2);
                mma_bf16(s[2*jj+1],   qa_lo[kk], kh + 2);
            }
        }

        bool domask = (kt >= nkt - 2);
        #pragma unroll
        for (int j = 0; j < 8; j++) {
            #pragma unroll
            for (int r = 0; r < 4; r++) {
                float v = s[j][r] * SC2;
                if (domask) {
                    int key = kt * 64 + j * 8 + qc + (r & 1);
                    int row = q0 + wid * 16 + qr + (r & 2) * 4;
                    if (key > row) v = -1e30f;
                }
                s[j][r] = v;
            }
        }

        float mx0 = -1e30f, mx1 = -1e30f;
        #pragma unroll
        for (int j = 0; j < 8; j++) {
            mx0 = fmaxf(mx0, fmaxf(s[j][0], s[j][1]));
            mx1 = fmaxf(mx1, fmaxf(s[j][2], s[j][3]));
        }
        mx0 = fmaxf(mx0, __shfl_xor_sync(0xffffffffu, mx0, 1));
        mx0 = fmaxf(mx0, __shfl_xor_sync(0xffffffffu, mx0, 2));
        mx1 = fmaxf(mx1, __shfl_xor_sync(0xffffffffu, mx1, 1));
        mx1 = fmaxf(mx1, __shfl_xor_sync(0xffffffffu, mx1, 2));
        float mn0 = fmaxf(m0, mx0), mn1 = fmaxf(m1, mx1);
        float al0 = ex2f(m0 - mn0), al1 = ex2f(m1 - mn1);
        float sm0 = 0.f, sm1 = 0.f;
        #pragma unroll
        for (int j = 0; j < 8; j++) {
            s[j][0] = ex2f(s[j][0] - mn0); sm0 += s[j][0];
            s[j][1] = ex2f(s[j][1] - mn0); sm0 += s[j][1];
            s[j][2] = ex2f(s[j][2] - mn1); sm1 += s[j][2];
            s[j][3] = ex2f(s[j][3] - mn1); sm1 += s[j][3];
        }
        sm0 += __shfl_xor_sync(0xffffffffu, sm0, 1);
        sm0 += __shfl_xor_sync(0xffffffffu, sm0, 2);
        sm1 += __shfl_xor_sync(0xffffffffu, sm1, 1);
        sm1 += __shfl_xor_sync(0xffffffffu, sm1, 2);
        l0 = l0 * al0 + sm0;  l1 = l1 * al1 + sm1;
        m0 = mn0;  m1 = mn1;
        #pragma unroll
        for (int j = 0; j < 8; j++) {
            oac[j][0] *= al0; oac[j][1] *= al0;
            oac[j][2] *= al1; oac[j][3] *= al1;
        }

        #pragma unroll
        for (int kk = 0; kk < 4; kk++) {
            uint32_t pah[4], pal[4];
            packsplith(s[2*kk][0],   s[2*kk][1],   pah[0], pal[0]);
            packsplith(s[2*kk][2],   s[2*kk][3],   pah[1], pal[1]);
            packsplith(s[2*kk+1][0], s[2*kk+1][1], pah[2], pal[2]);
            packsplith(s[2*kk+1][2], s[2*kk+1][3], pah[3], pal[3]);
            #pragma unroll
            for (int jj = 0; jj < 4; jj++) {
                int row = kk * 16 + (part & 1) * 8 + off;
                int colb = jj * 32 + (part & 2) * 8;
                uint32_t so = SMEM_SWIZZLE_128B((uint32_t)(row * 128 + colb));
                uint32_t v4[4];
                ldsm4t(v4, st + AT_V + so);
                mma_f16(oac[2*jj],   pah, v4);
                mma_f16(oac[2*jj],   pal, v4);
                mma_f16(oac[2*jj+1], pah, v4 + 2);
                mma_f16(oac[2*jj+1], pal, v4 + 2);
            }
        }
        __syncthreads();
    }

    float inv0 = 1.f / l0, inv1 = 1.f / l1;
    #pragma unroll
    for (int j = 0; j < 8; j++) {
        size_t i0 = (size_t)(b*T + q0 + wid*16 + qr) * C + hh * D + j * 8 + qc;
        size_t i1 = (size_t)(b*T + q0 + wid*16 + qr + 8) * C + hh * D + j * 8 + qc;
        __half2 p0 = __floats2half2_rn(oac[j][0] * inv0, oac[j][1] * inv0);
        __half2 p1 = __floats2half2_rn(oac[j][2] * inv1, oac[j][3] * inv1);
        *(uint32_t*)(yo + i0) = *(uint32_t*)&p0;
        *(uint32_t*)(yo + i1) = *(uint32_t*)&p1;
    }
}

// ======================= HMMA fp16x2 GEMM — 128x256 tile, A pair x B single ==============
// epi 4 only: fused QKV (cols [0,2048) fp32 stride 2048, cols [2048,3072) single fp16 stride 1024)
#define KTILE 64
#define W_AH 0
#define W_AL 16384
#define W_B  32768
#define W_STAGE 65536
#define SMEM_GEMM_BYTES (2*W_STAGE)

__global__ void __launch_bounds__(256, 1) gemm_fp16x2(
    const __half* __restrict__ Ahi, const __half* __restrict__ Alo,
    const __half* __restrict__ Bw,
    float* __restrict__ Cout, __half* __restrict__ Oh,
    int N, int K)
{
    extern __shared__ __align__(1024) char smem[];
    int by = blockIdx.y, bx = blockIdx.x;
    const __half* Bh = Bw;

    uint32_t sb = smem_to_u32(smem);
    int tid = threadIdx.x, wid = tid >> 5, lid = tid & 31;
    int wm = wid & 1, wn = wid >> 1;
    int row0 = by * 128, col0 = bx * 256;
    int nkt = K / KTILE;

    float acc[4][8][4];
    #pragma unroll
    for (int i = 0; i < 4; i++)
        #pragma unroll
        for (int j = 0; j < 8; j++)
            #pragma unroll
            for (int r = 0; r < 4; r++) acc[i][j][r] = 0.f;

    int lr = tid >> 3, lc = tid & 7;

    {
        #pragma unroll
        for (int i = 0; i < 4; i++) {
            int r = lr + i * 32;
            uint32_t so = SMEM_SWIZZLE_128B((uint32_t)(r * 128 + lc * 16));
            size_t ga = (size_t)(row0 + r) * K + lc * 8;
            CP16(sb + W_AH + so, Ahi + ga);
            CP16(sb + W_AL + so, Alo + ga);
        }
        #pragma unroll
        for (int i = 0; i < 8; i++) {
            int r = lr + i * 32;
            uint32_t so = SMEM_SWIZZLE_128B((uint32_t)(r * 128 + lc * 16));
            size_t gb = (size_t)(col0 + r) * K + lc * 8;
            CP16(sb + W_B + so, Bh + gb);
        }
        asm volatile("cp.async.commit_group;" ::: "memory");
    }

    for (int kt = 0; kt < nkt; kt++) {
        uint32_t cur = (uint32_t)(kt & 1) * W_STAGE;
        if (kt + 1 < nkt) {
            uint32_t nxt = (uint32_t)((kt + 1) & 1) * W_STAGE;
            int k0 = (kt + 1) * KTILE;
            #pragma unroll
            for (int i = 0; i < 4; i++) {
                int r = lr + i * 32;
                uint32_t so = SMEM_SWIZZLE_128B((uint32_t)(r * 128 + lc * 16));
                size_t ga = (size_t)(row0 + r) * K + k0 + lc * 8;
                CP16(sb + nxt + W_AH + so, Ahi + ga);
                CP16(sb + nxt + W_AL + so, Alo + ga);
            }
            #pragma unroll
            for (int i = 0; i < 8; i++) {
                int r = lr + i * 32;
                uint32_t so = SMEM_SWIZZLE_128B((uint32_t)(r * 128 + lc * 16));
                size_t gb = (size_t)(col0 + r) * K + k0 + lc * 8;
                CP16(sb + nxt + W_B + so, Bh + gb);
            }
            asm volatile("cp.async.commit_group;" ::: "memory");
            asm volatile("cp.async.wait_group 1;" ::: "memory");
        } else {
            asm volatile("cp.async.wait_group 0;" ::: "memory");
        }
        __syncthreads();

        uint32_t sAH = sb + cur + W_AH, sAL = sb + cur + W_AL;
        uint32_t sB  = sb + cur + W_B;
        #pragma unroll
        for (int kk = 0; kk < 4; kk++) {
            int colb = (kk * 16 + (lid >> 4) * 8) * 2;
            uint32_t a_hi[4][4], a_lo[4][4];
            #pragma unroll
            for (int mf = 0; mf < 4; mf++) {
                int rowm = wm * 64 + mf * 16 + (lid & 15);
                uint32_t so = SMEM_SWIZZLE_128B((uint32_t)(rowm * 128 + colb));
                ldsm4(a_hi[mf], sAH + so);
                ldsm4(a_lo[mf], sAL + so);
            }
            uint32_t b[8][2];
            #pragma unroll
            for (int g = 0; g < 4; g++) {
                int rown = wn * 64 + g * 16 + (lid & 15);
                uint32_t so = SMEM_SWIZZLE_128B((uint32_t)(rown * 128 + colb));
                uint32_t r4[4];
                ldsm4(r4, sB + so);
                b[2*g][0] = r4[0]; b[2*g+1][0] = r4[1];
                b[2*g][1] = r4[2]; b[2*g+1][1] = r4[3];
            }
            #pragma unroll
            for (int mf = 0; mf < 4; mf++)
                #pragma unroll
                for (int nf = 0; nf < 8; nf++) {
                    mma_f16(acc[mf][nf], a_hi[mf], b[nf]);
                    mma_f16(acc[mf][nf], a_lo[mf], b[nf]);
                }
        }
        __syncthreads();
    }

    int qr = lid >> 2, qc = (lid & 3) * 2;
    #pragma unroll
    for (int mf = 0; mf < 4; mf++) {
        #pragma unroll
        for (int nf = 0; nf < 8; nf++) {
            float* cc = acc[mf][nf];
            int col = col0 + wn * 64 + nf * 8 + qc;
            #pragma unroll
            for (int half = 0; half < 2; half++) {
                int row = row0 + wm * 64 + mf * 16 + qr + half * 8;
                float v0 = cc[2*half], v1 = cc[2*half + 1];
                if (col < 2048) {
                    size_t idx = (size_t)row * 2048 + col;
                    *(float2*)(Cout + idx) = make_float2(v0, v1);
                } else {
                    size_t idx = (size_t)row * 1024 + (col - 2048);
                    __half2 p = __floats2half2_rn(v0, v1);
                    *(uint32_t*)(Oh + idx) = *(uint32_t*)&p;
                }
            }
        }
    }
}

// ======================= HMMA fp16x1 GEMM — A single x B single, 1 MMA ====================
// epi: 1 Cout = acc + resid; 2 relu(acc)^2 -> single fp16;
//      5 MoE scatter: out[token*N+col] = acc + resid[token*N+col]
#define X_A 0
#define X_B 16384
#define X_STAGE 49152
#define SMEM_GEMM1_BYTES (2*X_STAGE)

__global__ void __launch_bounds__(256, 1) gemm_fp16x1(
    const __half* __restrict__ Aw,
    const __half* __restrict__ Bw, size_t bstride,
    float* __restrict__ Cout,
    __half* __restrict__ Oh,
    const float* __restrict__ resid,
    const int* __restrict__ tileExpert,
    const int* __restrict__ tokOfRow,
    int N, int K, int epi)
{
    extern __shared__ __align__(1024) char smem[];
    int by = blockIdx.y, bx = blockIdx.x;
    int e = 0;
    if (tileExpert) { e = tileExpert[by]; if (e < 0) return; }
    const __half* Bh = Bw + (size_t)e * bstride;

    uint32_t sb = smem_to_u32(smem);
    int tid = threadIdx.x, wid = tid >> 5, lid = tid & 31;
    int wm = wid & 1, wn = wid >> 1;
    int row0 = by * 128, col0 = bx * 256;
    int nkt = K / KTILE;

    float acc[4][8][4];
    #pragma unroll
    for (int i = 0; i < 4; i++)
        #pragma unroll
        for (int j = 0; j < 8; j++)
            #pragma unroll
            for (int r = 0; r < 4; r++) acc[i][j][r] = 0.f;

    int lr = tid >> 3, lc = tid & 7;

    {
        #pragma unroll
        for (int i = 0; i < 4; i++) {
            int r = lr + i * 32;
            uint32_t so = SMEM_SWIZZLE_128B((uint32_t)(r * 128 + lc * 16));
            size_t ga = (size_t)(row0 + r) * K + lc * 8;
            CP16(sb + X_A + so, Aw + ga);
        }
        #pragma unroll
        for (int i = 0; i < 8; i++) {
            int r = lr + i * 32;
            uint32_t so = SMEM_SWIZZLE_128B((uint32_t)(r * 128 + lc * 16));
            size_t gb = (size_t)(col0 + r) * K + lc * 8;
            CP16(sb + X_B + so, Bh + gb);
        }
        asm volatile("cp.async.commit_group;" ::: "memory");
    }

    for (int kt = 0; kt < nkt; kt++) {
        uint32_t cur = (uint32_t)(kt & 1) * X_STAGE;
        if (kt + 1 < nkt) {
            uint32_t nxt = (uint32_t)((kt + 1) & 1) * X_STAGE;
            int k0 = (kt + 1) * KTILE;
            #pragma unroll
            for (int i = 0; i < 4; i++) {
                int r = lr + i * 32;
                uint32_t so = SMEM_SWIZZLE_128B((uint32_t)(r * 128 + lc * 16));
                size_t ga = (size_t)(row0 + r) * K + k0 + lc * 8;
                CP16(sb + nxt + X_A + so, Aw + ga);
            }
            #pragma unroll
            for (int i = 0; i < 8; i++) {
                int r = lr + i * 32;
                uint32_t so = SMEM_SWIZZLE_128B((uint32_t)(r * 128 + lc * 16));
                size_t gb = (size_t)(col0 + r) * K + k0 + lc * 8;
                CP16(sb + nxt + X_B + so, Bh + gb);
            }
            asm volatile("cp.async.commit_group;" ::: "memory");
            asm volatile("cp.async.wait_group 1;" ::: "memory");
        } else {
            asm volatile("cp.async.wait_group 0;" ::: "memory");
        }
        __syncthreads();

        uint32_t sA = sb + cur + X_A, sB = sb + cur + X_B;
        #pragma unroll
        for (int kk = 0; kk < 4; kk++) {
            int colb = (kk * 16 + (lid >> 4) * 8) * 2;
            uint32_t a[4][4];
            #pragma unroll
            for (int mf = 0; mf < 4; mf++) {
                int rowm = wm * 64 + mf * 16 + (lid & 15);
                uint32_t so = SMEM_SWIZZLE_128B((uint32_t)(rowm * 128 + colb));
                ldsm4(a[mf], sA + so);
            }
            uint32_t b[8][2];
            #pragma unroll
            for (int g = 0; g < 4; g++) {
                int rown = wn * 64 + g * 16 + (lid & 15);
                uint32_t so = SMEM_SWIZZLE_128B((uint32_t)(rown * 128 + colb));
                uint32_t r4[4];
                ldsm4(r4, sB + so);
                b[2*g][0] = r4[0]; b[2*g+1][0] = r4[1];
                b[2*g][1] = r4[2]; b[2*g+1][1] = r4[3];
            }
            #pragma unroll
            for (int mf = 0; mf < 4; mf++)
                #pragma unroll
                for (int nf = 0; nf < 8; nf++)
                    mma_f16(acc[mf][nf], a[mf], b[nf]);
        }
        __syncthreads();
    }

    int qr = lid >> 2, qc = (lid & 3) * 2;
    #pragma unroll
    for (int mf = 0; mf < 4; mf++) {
        #pragma unroll
        for (int nf = 0; nf < 8; nf++) {
            float* cc = acc[mf][nf];
            int col = col0 + wn * 64 + nf * 8 + qc;
            #pragma unroll
            for (int half = 0; half < 2; half++) {
                int row = row0 + wm * 64 + mf * 16 + qr + half * 8;
                float v0 = cc[2*half], v1 = cc[2*half + 1];
                if (epi == 1) {
                    size_t idx = (size_t)row * N + col;
                    float2 rr = *(const float2*)(resid + idx);
                    *(float2*)(Cout + idx) = make_float2(v0 + rr.x, v1 + rr.y);
                } else if (epi == 2) {
                    v0 = fmaxf(v0, 0.f); v0 *= v0;
                    v1 = fmaxf(v1, 0.f); v1 *= v1;
                    size_t idx = (size_t)row * N + col;
                    __half2 p = __floats2half2_rn(v0, v1);
                    *(uint32_t*)(Oh + idx) = *(uint32_t*)&p;
                } else {   // epi == 5
                    int t = tokOfRow[row];
                    if (t >= 0) {
                        size_t idx = (size_t)t * N + col;
                        float2 rr = *(const float2*)(resid + idx);
                        *(float2*)(Cout + idx) = make_float2(v0 + rr.x, v1 + rr.y);
                    }
                }
            }
        }
    }
}

// ======================= grouping / scalars =======================
__global__ void offsets_kernel() {
    if (threadIdx.x == 0 && blockIdx.x == 0) {
        int off = 0;
        for (int e = 0; e < E; e++) {
            g_segstart[e] = off;
            int padded = (g_counts[e] + 127) & ~127;
            for (int i = 0; i < padded / 128; i++)
                g_tileExpert[off / 128 + i] = e;
            off += padded;
        }
    }
}

__global__ void assign_kernel(const float* __restrict__ h2) {
    int t = blockIdx.x;
    __shared__ int slot_s;
    if (threadIdx.x == 0) {
        int e = g_expert[t];
        int slot = g_segstart[e] + atomicAdd(&g_cursor[e], 1);
        g_tokenOfRow[slot] = t;
        slot_s = slot;
    }
    __syncthreads();
    int s = slot_s;
    float4 v = ((const float4*)(h2 + (size_t)t * C))[threadIdx.x];
    __half2 p01 = __floats2half2_rn(v.x, v.y);
    __half2 p23 = __floats2half2_rn(v.z, v.w);
    ((uint2*)(g_h2g + (size_t)s * C))[threadIdx.x] =
        make_uint2(*(uint32_t*)&p01, *(uint32_t*)&p23);
}

__global__ void scalars_kernel(float* __restrict__ out) {
    if (threadIdx.x == 0 && blockIdx.x == 0) {
        const double NTOK = (double)BT;
        double aux = 0.0;
        for (int e = 0; e < E; e++) {
            double actual = (double)g_counts[e] / NTOK;
            double expd   = g_expsum[e] / NTOK;
            aux += actual * expd;
        }
        size_t base = (size_t)BT * C;
        out[base + 0] = (float)((double)E * aux);
        out[base + 1] = (float)(g_zsum / NTOK);
        out[base + 2] = (float)((g_entsum / NTOK) / log((double)E));
        for (int e = 0; e < E; e++)
            out[base + 3 + e] = (float)((double)g_counts[e] / NTOK);
    }
}

// ======================= launch =======================
static void* sym(const void* s) { void* p = nullptr; cudaGetSymbolAddress(&p, s); return p; }

extern "C" void kernel_launch(void* const* d_in, const int* in_sizes, int n_in,
                              void* d_out, int out_size)
{
    const float* x     = (const float*)d_in[0];
    const float* Wq    = (const float*)d_in[1];
    const float* Wk    = (const float*)d_in[2];
    const float* Wv    = (const float*)d_in[3];
    const float* Wo    = (const float*)d_in[4];
    const float* Wr    = (const float*)d_in[5];
    const float* Wfc   = (const float*)d_in[6];
    const float* Wproj = (const float*)d_in[7];
    float* out = (float*)d_out;

    static bool init_done = false;
    static cudaStream_t s2;
    static cudaEvent_t evFork, evWo, evMoE;
    if (!init_done) {
        cudaFuncSetAttribute(gemm_fp16x2, cudaFuncAttributeMaxDynamicSharedMemorySize, SMEM_GEMM_BYTES);
        cudaFuncSetAttribute(gemm_fp16x1, cudaFuncAttributeMaxDynamicSharedMemorySize, SMEM_GEMM1_BYTES);
        cudaFuncSetAttribute(attn_mma_kernel, cudaFuncAttributeMaxDynamicSharedMemorySize, ATT_SMEM);
        cudaStreamCreateWithFlags(&s2, cudaStreamNonBlocking);
        cudaEventCreateWithFlags(&evFork, cudaEventDisableTiming);
        cudaEventCreateWithFlags(&evWo,   cudaEventDisableTiming);
        cudaEventCreateWithFlags(&evMoE,  cudaEventDisableTiming);
        init_done = true;
    }

    __half* h1h = (__half*)sym(g_h1_hi);
    __half* h1l = (__half*)sym(g_h1_lo);
    float* qk = (float*)sym(g_qk);
    __nv_bfloat16* qh = (__nv_bfloat16*)sym(g_qhi); __nv_bfloat16* ql = (__nv_bfloat16*)sym(g_qlo);
    __nv_bfloat16* kh = (__nv_bfloat16*)sym(g_khi); __nv_bfloat16* kl = (__nv_bfloat16*)sym(g_klo);
    __half* vh = (__half*)sym(g_vh);
    __half* yb = (__half*)sym(g_y);
    float* x2 = (float*)sym(g_x2);
    float* h2 = (float*)sym(g_h2);
    __half* h2g = (__half*)sym(g_h2g);
    __half* hid = (__half*)sym(g_hid);
    __half* wqkv = (__half*)sym(g_wqkv);
    __half* wo   = (__half*)sym(g_wo);
    __half* wfc  = (__half*)sym(g_wfc);
    __half* wpj  = (__half*)sym(g_wpj);
    int* tileE = (int*)sym(g_tileExpert);
    int* tokR  = (int*)sym(g_tokenOfRow);

    // ---- main stream (0): front section ----
    reset_kernel<<<(GROUP_CAP + 255) / 256, 256>>>();
    cudaEventRecord(evFork, 0);

    // ---- side stream: weight conversions needed later ----
    cudaStreamWaitEvent(s2, evFork, 0);
    wconv_kernel<<<dim3(C/64,  C/64,  1), 256, 0, s2>>>(Wo,    wo,  C,  C);
    cudaEventRecord(evWo, s2);
    wconv_kernel<<<dim3(FF/64, C/64,  E), 256, 0, s2>>>(Wfc,   wfc, C,  FF);
    wconv_kernel<<<dim3(C/64,  FF/64, E), 256, 0, s2>>>(Wproj, wpj, FF, C);
    cudaEventRecord(evMoE, s2);

    // ---- main stream continues ----
    rmsnorm_kernel<<<BT, 256>>>(x, h1h, h1l);
    wconv_kernel<<<dim3(C/64, C/64, 1), 256>>>(Wq, wqkv,         C, C);
    wconv_kernel<<<dim3(C/64, C/64, 1), 256>>>(Wk, wqkv + C*C,   C, C);
    wconv_kernel<<<dim3(C/64, C/64, 1), 256>>>(Wv, wqkv + 2*C*C, C, C);
    gemm_fp16x2<<<dim3(3*C/256, BT/128), 256, SMEM_GEMM_BYTES>>>(
        h1h, h1l, wqkv, qk, vh, 3*C, C);
    qk_rope_kernel<<<BT, 512>>>(qk, qh, ql, kh, kl);
    attn_mma_kernel<<<dim3(T/128, Bq*H), 256, ATT_SMEM>>>(
        qh, ql, kh, kl, vh, yb);

    cudaStreamWaitEvent(0, evWo, 0);
    gemm_fp16x1<<<dim3(C/256, BT/128), 256, SMEM_GEMM1_BYTES>>>(
        yb, wo, 0, x2, nullptr, x, nullptr, nullptr, C, C, 1);
    rmsnorm_router_kernel<<<BT, 256>>>(x2, h2, Wr);
    offsets_kernel<<<1, 32>>>();
    assign_kernel<<<BT, 256>>>(h2);

    cudaStreamWaitEvent(0, evMoE, 0);
    gemm_fp16x1<<<dim3(FF/256, NTILES), 256, SMEM_GEMM1_BYTES>>>(
        h2g, wfc, (size_t)FF * C, nullptr, hid, nullptr, tileE, nullptr, FF, C, 2);
    gemm_fp16x1<<<dim3(C/256, NTILES), 256, SMEM_GEMM1_BYTES>>>(
        hid, wpj, (size_t)C * FF, out, nullptr, x2, tileE, tokR, C, FF, 5);
    scalars_kernel<<<1, 32>>>(out);
}

// round 15
// speedup vs baseline: 2.2332x; 1.1548x over previous
#include <cuda_runtime.h>
#include <cuda_fp16.h>
#include <cstdint>
#include <math.h>

#define Bq 2
#define T 2048
#define C 1024
#define H 16
#define D 64
#define E 4
#define BT (Bq*T)
#define FF (4*C)
#define GROUP_CAP (BT + E*128)
#define NTILES (GROUP_CAP/128)
#define EPS_RMS 1.1920929e-07f

#define SMEM_SWIZZLE_128B(b) ((b) ^ (((b) >> 3) & 0x70))

__device__ __forceinline__ uint32_t smem_to_u32(const void* p) {
    uint32_t a;
    asm("{ .reg .u64 t; cvta.to.shared.u64 t, %1; cvt.u32.u64 %0, t; }" : "=r"(a) : "l"(p));
    return a;
}
__device__ __forceinline__ void ldsm4(uint32_t* r, uint32_t addr) {
    asm volatile("ldmatrix.sync.aligned.m8n8.x4.shared.b16 {%0,%1,%2,%3}, [%4];"
                 : "=r"(r[0]), "=r"(r[1]), "=r"(r[2]), "=r"(r[3]) : "r"(addr));
}
__device__ __forceinline__ void ldsm4t(uint32_t* r, uint32_t addr) {
    asm volatile("ldmatrix.sync.aligned.m8n8.x4.trans.shared.b16 {%0,%1,%2,%3}, [%4];"
                 : "=r"(r[0]), "=r"(r[1]), "=r"(r[2]), "=r"(r[3]) : "r"(addr));
}
__device__ __forceinline__ void mma_f16(float* c, const uint32_t* a, const uint32_t* b) {
    asm volatile("mma.sync.aligned.m16n8k16.row.col.f32.f16.f16.f32 "
        "{%0,%1,%2,%3}, {%4,%5,%6,%7}, {%8,%9}, {%0,%1,%2,%3};"
        : "+f"(c[0]), "+f"(c[1]), "+f"(c[2]), "+f"(c[3])
        : "r"(a[0]), "r"(a[1]), "r"(a[2]), "r"(a[3]), "r"(b[0]), "r"(b[1]));
}
__device__ __forceinline__ float ex2f(float x) {
    float y; asm("ex2.approx.ftz.f32 %0, %1;" : "=f"(y) : "f"(x)); return y;
}
#define CP16(s, g) asm volatile("cp.async.cg.shared.global [%0], [%1], 16;" \
                                :: "r"(s), "l"(g) : "memory")

// ======================= scratch (static device globals) =======================
__device__ __half g_h1[BT*C];
__device__ float g_qk[BT*2*C];
__device__ __half g_qhi[BT*C], g_qlo[BT*C];
__device__ __half g_kh[BT*C];
__device__ __half g_vh[BT*C];
__device__ __half g_y[BT*C];
__device__ float g_x2[BT*C], g_h2[BT*C];
__device__ __half g_h2g[GROUP_CAP*C];
__device__ __half g_hid[(size_t)GROUP_CAP*FF];
__device__ __half g_wqkv[3*C*C];
__device__ __half g_wo[C*C];
__device__ __half g_wfc[(size_t)E*C*FF];   // [E][FF,C]
__device__ __half g_wpj[(size_t)E*FF*C];   // [E][C,FF]
__device__ int   g_expert[BT];
__device__ int   g_counts[E];
__device__ int   g_cursor[E];
__device__ int   g_segstart[E];
__device__ int   g_tileExpert[NTILES];
__device__ int   g_tokenOfRow[GROUP_CAP];
__device__ double g_expsum[E];
__device__ double g_zsum;
__device__ double g_entsum;

__device__ __forceinline__ void hsplit(float v, __half& h, __half& l) {
    h = __float2half(v);
    l = __float2half(v - __half2float(h));
}
__device__ __forceinline__ void packsplith(float v0, float v1, uint32_t& hi, uint32_t& lo) {
    __half h0, l0, h1, l1;
    hsplit(v0, h0, l0); hsplit(v1, h1, l1);
    __half2 hh(h0, h1), ll(l0, l1);
    hi = *reinterpret_cast<uint32_t*>(&hh);
    lo = *reinterpret_cast<uint32_t*>(&ll);
}

// ======================= small kernels =======================
__global__ void reset_kernel() {
    int i = blockIdx.x * blockDim.x + threadIdx.x;
    if (i < E) { g_counts[i] = 0; g_cursor[i] = 0; g_expsum[i] = 0.0; }
    if (i == 0) { g_zsum = 0.0; g_entsum = 0.0; }
    if (i < NTILES) g_tileExpert[i] = -1;
    if (i < GROUP_CAP) g_tokenOfRow[i] = -1;
}

// transpose weights: W [Kd, Nd] fp32 -> T [Nd, Kd] single fp16
__global__ void __launch_bounds__(256) wconv_kernel(
    const float* __restrict__ W, __half* __restrict__ Th, int Kd, int Nd) {
    __shared__ float tile[64][65];
    int b = blockIdx.z;
    const float* Wb = W + (size_t)b * Kd * Nd;
    __half* Tb = Th + (size_t)b * Kd * Nd;
    int n0 = blockIdx.x * 64, k0 = blockIdx.y * 64;
    int tid = threadIdx.x;
    int lr = tid >> 4, lc = (tid & 15) * 4;
    #pragma unroll
    for (int i = 0; i < 4; i++) {
        int k = lr + i * 16;
        float4 v = *(const float4*)(Wb + (size_t)(k0 + k) * Nd + n0 + lc);
        tile[k][lc] = v.x; tile[k][lc+1] = v.y; tile[k][lc+2] = v.z; tile[k][lc+3] = v.w;
    }
    __syncthreads();
    int wn = tid >> 4, wk = (tid & 15) * 4;
    #pragma unroll
    for (int i = 0; i < 4; i++) {
        int n = wn + i * 16;
        __half2 p01 = __floats2half2_rn(tile[wk][n],   tile[wk+1][n]);
        __half2 p23 = __floats2half2_rn(tile[wk+2][n], tile[wk+3][n]);
        size_t o = (size_t)(n0 + n) * Kd + k0 + wk;
        *(uint2*)(Tb + o) = make_uint2(*(uint32_t*)&p01, *(uint32_t*)&p23);
    }
}

// RMSNorm over C -> single fp16
__global__ void rmsnorm_kernel(const float* __restrict__ in, __half* __restrict__ oh) {
    int t = blockIdx.x;
    const float4* ip = (const float4*)(in + (size_t)t * C);
    __shared__ float red[8];
    float4 v = ip[threadIdx.x];
    float ss = v.x*v.x + v.y*v.y + v.z*v.z + v.w*v.w;
    #pragma unroll
    for (int o = 16; o; o >>= 1) ss += __shfl_xor_sync(0xffffffffu, ss, o);
    if ((threadIdx.x & 31) == 0) red[threadIdx.x >> 5] = ss;
    __syncthreads();
    if (threadIdx.x == 0) {
        float s = 0.f;
        #pragma unroll
        for (int w = 0; w < 8; w++) s += red[w];
        red[0] = s;
    }
    __syncthreads();
    float r = rsqrtf(red[0] / (float)C + EPS_RMS);
    __half2 p01 = __floats2half2_rn(v.x * r, v.y * r);
    __half2 p23 = __floats2half2_rn(v.z * r, v.w * r);
    ((uint2*)(oh + (size_t)t * C))[threadIdx.x] =
        make_uint2(*(uint32_t*)&p01, *(uint32_t*)&p23);
}

// RMSNorm fp32 out + fused router
__global__ void rmsnorm_router_kernel(const float* __restrict__ in, float* __restrict__ outf,
                                      const float* __restrict__ Wr) {
    int t = blockIdx.x;
    const float4* ip = (const float4*)(in + (size_t)t * C);
    __shared__ float red[8];
    __shared__ float lred[32];
    float4 v = ip[threadIdx.x];
    float ss = v.x*v.x + v.y*v.y + v.z*v.z + v.w*v.w;
    #pragma unroll
    for (int o = 16; o; o >>= 1) ss += __shfl_xor_sync(0xffffffffu, ss, o);
    if ((threadIdx.x & 31) == 0) red[threadIdx.x >> 5] = ss;
    __syncthreads();
    if (threadIdx.x == 0) {
        float s = 0.f;
        #pragma unroll
        for (int w = 0; w < 8; w++) s += red[w];
        red[0] = s;
    }
    __syncthreads();
    float r = rsqrtf(red[0] / (float)C + EPS_RMS);
    float4 o = make_float4(v.x*r, v.y*r, v.z*r, v.w*r);
    ((float4*)(outf + (size_t)t * C))[threadIdx.x] = o;

    int c0 = threadIdx.x * 4;
    float4 w0 = *(const float4*)(Wr + (size_t)(c0+0) * E);
    float4 w1 = *(const float4*)(Wr + (size_t)(c0+1) * E);
    float4 w2 = *(const float4*)(Wr + (size_t)(c0+2) * E);
    float4 w3 = *(const float4*)(Wr + (size_t)(c0+3) * E);
    float a0 = o.x*w0.x + o.y*w1.x + o.z*w2.x + o.w*w3.x;
    float a1 = o.x*w0.y + o.y*w1.y + o.z*w2.y + o.w*w3.y;
    float a2 = o.x*w0.z + o.y*w1.z + o.z*w2.z + o.w*w3.z;
    float a3 = o.x*w0.w + o.y*w1.w + o.z*w2.w + o.w*w3.w;
    #pragma unroll
    for (int off = 16; off; off >>= 1) {
        a0 += __shfl_xor_sync(0xffffffffu, a0, off);
        a1 += __shfl_xor_sync(0xffffffffu, a1, off);
        a2 += __shfl_xor_sync(0xffffffffu, a2, off);
        a3 += __shfl_xor_sync(0xffffffffu, a3, off);
    }
    if ((threadIdx.x & 31) == 0) {
        int w = threadIdx.x >> 5;
        lred[w*4+0] = a0; lred[w*4+1] = a1; lred[w*4+2] = a2; lred[w*4+3] = a3;
    }
    __syncthreads();
    if (threadIdx.x == 0) {
        float lg[4];
        #pragma unroll
        for (int e = 0; e < 4; e++) {
            float s = 0.f;
            #pragma unroll
            for (int w = 0; w < 8; w++) s += lred[w*4+e];
            lg[e] = s;
        }
        int arg = 0;
        #pragma unroll
        for (int e = 1; e < 4; e++) if (lg[e] > lg[arg]) arg = e;
        float m = fmaxf(fmaxf(lg[0], lg[1]), fmaxf(lg[2], lg[3]));
        float ez[4]; float sum = 0.f;
        #pragma unroll
        for (int e = 0; e < 4; e++) { ez[e] = expf(lg[e] - m); sum += ez[e]; }
        float p[4];
        #pragma unroll
        for (int e = 0; e < 4; e++) p[e] = ez[e] / sum;
        g_expert[t] = arg;
        atomicAdd(&g_counts[arg], 1);
        #pragma unroll
        for (int e = 0; e < 4; e++) atomicAdd(&g_expsum[e], (double)p[e]);
        float lse = m + logf(sum);
        atomicAdd(&g_zsum, (double)lse * (double)lse);
        float ent = 0.f;
        #pragma unroll
        for (int e = 0; e < 4; e++) ent -= p[e] * logf(p[e] + 1e-9f);
        atomicAdd(&g_entsum, (double)ent);
    }
}

// per-head RMSNorm + RoPE; reads qk fp32 [BT,2048]; q -> fp16 pair, k -> single fp16
__global__ void qk_rope_kernel(const float* __restrict__ qk,
                               __half* __restrict__ qhi, __half* __restrict__ qlo,
                               __half* __restrict__ kh) {
    int tok  = blockIdx.x;
    int head = threadIdx.x >> 5;
    int lane = threadIdx.x & 31;
    int tpos = tok % T;
    float ex  = (float)(2 * lane) / 64.0f;
    float inv = 1.0f / powf(10000.0f, ex);
    float ang = (float)tpos * inv;
    float c = cosf(ang), s = sinf(ang);
    size_t obase = (size_t)tok * C + head * D;
    #pragma unroll
    for (int m = 0; m < 2; m++) {
        const float* src = qk + (size_t)tok * 2048 + m * 1024 + head * D;
        float x1 = src[lane], x2 = src[lane + 32];
        float ss = x1*x1 + x2*x2;
        #pragma unroll
        for (int o = 16; o; o >>= 1) ss += __shfl_xor_sync(0xffffffffu, ss, o);
        float r = rsqrtf(ss / (float)D + EPS_RMS);
        x1 *= r; x2 *= r;
        float o1 =  x1 * c + x2 * s;
        float o2 = -x1 * s + x2 * c;
        if (m == 0) {
            __half h, l;
            hsplit(o1, h, l); qhi[obase + lane] = h;      qlo[obase + lane] = l;
            hsplit(o2, h, l); qhi[obase + lane + 32] = h; qlo[obase + lane + 32] = l;
        } else {
            kh[obase + lane]      = __float2half(o1);
            kh[obase + lane + 32] = __float2half(o2);
        }
    }
}

// ======================= HMMA flash attention (QK fp16 pair x single, PV fp16 pair x single) ==
#define AT_QHI 0
#define AT_QLO 16384
#define AT_STG 32768
#define AT_STGSZ 16384
#define AT_K   0
#define AT_V   8192
#define ATT_SMEM (32768 + 2*16384)

__global__ void __launch_bounds__(256) attn_mma_kernel(
    const __half* __restrict__ qhi, const __half* __restrict__ qlo,
    const __half* __restrict__ kk, const __half* __restrict__ vv,
    __half* __restrict__ yo)
{
    extern __shared__ __align__(1024) char smem[];
    uint32_t sb = smem_to_u32(smem);
    int bh = blockIdx.y;
    int b = bh / H, hh = bh % H;
    int qb = blockIdx.x;
    int q0 = qb * 128;
    int tid = threadIdx.x, wid = tid >> 5, lid = tid & 31;
    int nkt = 2 * qb + 2;

    #pragma unroll
    for (int i = 0; i < 4; i++) {
        int lin = tid + i * 256;
        int r = lin >> 3, ch = lin & 7;
        uint32_t so = SMEM_SWIZZLE_128B((uint32_t)(r * 128 + ch * 16));
        size_t g = (size_t)(b*T + q0 + r) * C + hh * D + ch * 8;
        CP16(sb + AT_QHI + so, qhi + g);
        CP16(sb + AT_QLO + so, qlo + g);
    }
    asm volatile("cp.async.commit_group;" ::: "memory");
    #pragma unroll
    for (int i = 0; i < 2; i++) {
        int lin = tid + i * 256;
        int r = lin >> 3, ch = lin & 7;
        uint32_t so = SMEM_SWIZZLE_128B((uint32_t)(r * 128 + ch * 16));
        size_t g = (size_t)(b*T + r) * C + hh * D + ch * 8;
        uint32_t st = sb + AT_STG;
        CP16(st + AT_K + so, kk + g);
        CP16(st + AT_V + so, vv + g);
    }
    asm volatile("cp.async.commit_group;" ::: "memory");

    uint32_t qa_hi[4][4], qa_lo[4][4];
    float oac[8][4];
    #pragma unroll
    for (int j = 0; j < 8; j++)
        #pragma unroll
        for (int r = 0; r < 4; r++) oac[j][r] = 0.f;
    float m0 = -1e30f, m1 = -1e30f, l0 = 0.f, l1 = 0.f;

    int off = lid & 7, part = lid >> 3;
    int qr = lid >> 2, qc = (lid & 3) * 2;
    const float SC2 = 0.18033688011112042f;

    for (int kt = 0; kt < nkt; kt++) {
        if (kt + 1 < nkt) {
            #pragma unroll
            for (int i = 0; i < 2; i++) {
                int lin = tid + i * 256;
                int r = lin >> 3, ch = lin & 7;
                uint32_t so = SMEM_SWIZZLE_128B((uint32_t)(r * 128 + ch * 16));
                size_t g = (size_t)(b*T + (kt + 1) * 64 + r) * C + hh * D + ch * 8;
                uint32_t st = sb + AT_STG + (uint32_t)((kt + 1) & 1) * AT_STGSZ;
                CP16(st + AT_K + so, kk + g);
                CP16(st + AT_V + so, vv + g);
            }
            asm volatile("cp.async.commit_group;" ::: "memory");
            asm volatile("cp.async.wait_group 1;" ::: "memory");
        } else {
            asm volatile("cp.async.wait_group 0;" ::: "memory");
        }
        __syncthreads();

        if (kt == 0) {
            #pragma unroll
            for (int kq = 0; kq < 4; kq++) {
                int row = wid * 16 + (part & 1) * 8 + off;
                int colb = kq * 32 + (part & 2) * 8;
                uint32_t so = SMEM_SWIZZLE_128B((uint32_t)(row * 128 + colb));
                ldsm4(qa_hi[kq], sb + AT_QHI + so);
                ldsm4(qa_lo[kq], sb + AT_QLO + so);
            }
        }

        uint32_t st = sb + AT_STG + (uint32_t)(kt & 1) * AT_STGSZ;

        float s[8][4];
        #pragma unroll
        for (int j = 0; j < 8; j++)
            #pragma unroll
            for (int r = 0; r < 4; r++) s[j][r] = 0.f;
        #pragma unroll
        for (int kq = 0; kq < 4; kq++) {
            #pragma unroll
            for (int jj = 0; jj < 4; jj++) {
                int row = jj * 16 + (part & 2) * 4 + off;
                int colb = kq * 32 + (part & 1) * 16;
                uint32_t so = SMEM_SWIZZLE_128B((uint32_t)(row * 128 + colb));
                uint32_t kf[4];
                ldsm4(kf, st + AT_K + so);
                mma_f16(s[2*jj],     qa_hi[kq], kf);
                mma_f16(s[2*jj],     qa_lo[kq], kf);
                mma_f16(s[2*jj+1],   qa_hi[kq], kf + 2);
                mma_f16(s[2*jj+1],   qa_lo[kq], kf + 2);
            }
        }

        bool domask = (kt >= nkt - 2);
        #pragma unroll
        for (int j = 0; j < 8; j++) {
            #pragma unroll
            for (int r = 0; r < 4; r++) {
                float v = s[j][r] * SC2;
                if (domask) {
                    int key = kt * 64 + j * 8 + qc + (r & 1);
                    int row = q0 + wid * 16 + qr + (r & 2) * 4;
                    if (key > row) v = -1e30f;
                }
                s[j][r] = v;
            }
        }

        float mx0 = -1e30f, mx1 = -1e30f;
        #pragma unroll
        for (int j = 0; j < 8; j++) {
            mx0 = fmaxf(mx0, fmaxf(s[j][0], s[j][1]));
            mx1 = fmaxf(mx1, fmaxf(s[j][2], s[j][3]));
        }
        mx0 = fmaxf(mx0, __shfl_xor_sync(0xffffffffu, mx0, 1));
        mx0 = fmaxf(mx0, __shfl_xor_sync(0xffffffffu, mx0, 2));
        mx1 = fmaxf(mx1, __shfl_xor_sync(0xffffffffu, mx1, 1));
        mx1 = fmaxf(mx1, __shfl_xor_sync(0xffffffffu, mx1, 2));
        float mn0 = fmaxf(m0, mx0), mn1 = fmaxf(m1, mx1);
        float al0 = ex2f(m0 - mn0), al1 = ex2f(m1 - mn1);
        float sm0 = 0.f, sm1 = 0.f;
        #pragma unroll
        for (int j = 0; j < 8; j++) {
            s[j][0] = ex2f(s[j][0] - mn0); sm0 += s[j][0];
            s[j][1] = ex2f(s[j][1] - mn0); sm0 += s[j][1];
            s[j][2] = ex2f(s[j][2] - mn1); sm1 += s[j][2];
            s[j][3] = ex2f(s[j][3] - mn1); sm1 += s[j][3];
        }
        sm0 += __shfl_xor_sync(0xffffffffu, sm0, 1);
        sm0 += __shfl_xor_sync(0xffffffffu, sm0, 2);
        sm1 += __shfl_xor_sync(0xffffffffu, sm1, 1);
        sm1 += __shfl_xor_sync(0xffffffffu, sm1, 2);
        l0 = l0 * al0 + sm0;  l1 = l1 * al1 + sm1;
        m0 = mn0;  m1 = mn1;
        #pragma unroll
        for (int j = 0; j < 8; j++) {
            oac[j][0] *= al0; oac[j][1] *= al0;
            oac[j][2] *= al1; oac[j][3] *= al1;
        }

        #pragma unroll
        for (int kp = 0; kp < 4; kp++) {
            uint32_t pah[4], pal[4];
            packsplith(s[2*kp][0],   s[2*kp][1],   pah[0], pal[0]);
            packsplith(s[2*kp][2],   s[2*kp][3],   pah[1], pal[1]);
            packsplith(s[2*kp+1][0], s[2*kp+1][1], pah[2], pal[2]);
            packsplith(s[2*kp+1][2], s[2*kp+1][3], pah[3], pal[3]);
            #pragma unroll
            for (int jj = 0; jj < 4; jj++) {
                int row = kp * 16 + (part & 1) * 8 + off;
                int colb = jj * 32 + (part & 2) * 8;
                uint32_t so = SMEM_SWIZZLE_128B((uint32_t)(row * 128 + colb));
                uint32_t v4[4];
                ldsm4t(v4, st + AT_V + so);
                mma_f16(oac[2*jj],   pah, v4);
                mma_f16(oac[2*jj],   pal, v4);
                mma_f16(oac[2*jj+1], pah, v4 + 2);
                mma_f16(oac[2*jj+1], pal, v4 + 2);
            }
        }
        __syncthreads();
    }

    float inv0 = 1.f / l0, inv1 = 1.f / l1;
    #pragma unroll
    for (int j = 0; j < 8; j++) {
        size_t i0 = (size_t)(b*T + q0 + wid*16 + qr) * C + hh * D + j * 8 + qc;
        size_t i1 = (size_t)(b*T + q0 + wid*16 + qr + 8) * C + hh * D + j * 8 + qc;
        __half2 p0 = __floats2half2_rn(oac[j][0] * inv0, oac[j][1] * inv0);
        __half2 p1 = __floats2half2_rn(oac[j][2] * inv1, oac[j][3] * inv1);
        *(uint32_t*)(yo + i0) = *(uint32_t*)&p0;
        *(uint32_t*)(yo + i1) = *(uint32_t*)&p1;
    }
}

// ======================= HMMA fp16x1 GEMM — A single x B single, 1 MMA ====================
// epi: 1 Cout = acc + resid; 2 relu(acc)^2 -> single fp16;
//      4 fused QKV: cols [0,2048) fp32 stride 2048, cols [2048,3072) single fp16 stride 1024;
//      5 MoE scatter: out[token*N+col] = acc + resid[token*N+col]
#define KTILE 64
#define X_A 0
#define X_B 16384
#define X_STAGE 49152
#define SMEM_GEMM1_BYTES (2*X_STAGE)

__global__ void __launch_bounds__(256, 1) gemm_fp16x1(
    const __half* __restrict__ Aw,
    const __half* __restrict__ Bw, size_t bstride,
    float* __restrict__ Cout,
    __half* __restrict__ Oh,
    const float* __restrict__ resid,
    const int* __restrict__ tileExpert,
    const int* __restrict__ tokOfRow,
    int N, int K, int epi)
{
    extern __shared__ __align__(1024) char smem[];
    int by = blockIdx.y, bx = blockIdx.x;
    int e = 0;
    if (tileExpert) { e = tileExpert[by]; if (e < 0) return; }
    const __half* Bh = Bw + (size_t)e * bstride;

    uint32_t sb = smem_to_u32(smem);
    int tid = threadIdx.x, wid = tid >> 5, lid = tid & 31;
    int wm = wid & 1, wn = wid >> 1;
    int row0 = by * 128, col0 = bx * 256;
    int nkt = K / KTILE;

    float acc[4][8][4];
    #pragma unroll
    for (int i = 0; i < 4; i++)
        #pragma unroll
        for (int j = 0; j < 8; j++)
            #pragma unroll
            for (int r = 0; r < 4; r++) acc[i][j][r] = 0.f;

    int lr = tid >> 3, lc = tid & 7;

    {
        #pragma unroll
        for (int i = 0; i < 4; i++) {
            int r = lr + i * 32;
            uint32_t so = SMEM_SWIZZLE_128B((uint32_t)(r * 128 + lc * 16));
            size_t ga = (size_t)(row0 + r) * K + lc * 8;
            CP16(sb + X_A + so, Aw + ga);
        }
        #pragma unroll
        for (int i = 0; i < 8; i++) {
            int r = lr + i * 32;
            uint32_t so = SMEM_SWIZZLE_128B((uint32_t)(r * 128 + lc * 16));
            size_t gb = (size_t)(col0 + r) * K + lc * 8;
            CP16(sb + X_B + so, Bh + gb);
        }
        asm volatile("cp.async.commit_group;" ::: "memory");
    }

    for (int kt = 0; kt < nkt; kt++) {
        uint32_t cur = (uint32_t)(kt & 1) * X_STAGE;
        if (kt + 1 < nkt) {
            uint32_t nxt = (uint32_t)((kt + 1) & 1) * X_STAGE;
            int k0 = (kt + 1) * KTILE;
            #pragma unroll
            for (int i = 0; i < 4; i++) {
                int r = lr + i * 32;
                uint32_t so = SMEM_SWIZZLE_128B((uint32_t)(r * 128 + lc * 16));
                size_t ga = (size_t)(row0 + r) * K + k0 + lc * 8;
                CP16(sb + nxt + X_A + so, Aw + ga);
            }
            #pragma unroll
            for (int i = 0; i < 8; i++) {
                int r = lr + i * 32;
                uint32_t so = SMEM_SWIZZLE_128B((uint32_t)(r * 128 + lc * 16));
                size_t gb = (size_t)(col0 + r) * K + k0 + lc * 8;
                CP16(sb + nxt + X_B + so, Bh + gb);
            }
            asm volatile("cp.async.commit_group;" ::: "memory");
            asm volatile("cp.async.wait_group 1;" ::: "memory");
        } else {
            asm volatile("cp.async.wait_group 0;" ::: "memory");
        }
        __syncthreads();

        uint32_t sA = sb + cur + X_A, sB = sb + cur + X_B;
        #pragma unroll
        for (int kq = 0; kq < 4; kq++) {
            int colb = (kq * 16 + (lid >> 4) * 8) * 2;
            uint32_t a[4][4];
            #pragma unroll
            for (int mf = 0; mf < 4; mf++) {
                int rowm = wm * 64 + mf * 16 + (lid & 15);
                uint32_t so = SMEM_SWIZZLE_128B((uint32_t)(rowm * 128 + colb));
                ldsm4(a[mf], sA + so);
            }
            uint32_t b[8][2];
            #pragma unroll
            for (int g = 0; g < 4; g++) {
                int rown = wn * 64 + g * 16 + (lid & 15);
                uint32_t so = SMEM_SWIZZLE_128B((uint32_t)(rown * 128 + colb));
                uint32_t r4[4];
                ldsm4(r4, sB + so);
                b[2*g][0] = r4[0]; b[2*g+1][0] = r4[1];
                b[2*g][1] = r4[2]; b[2*g+1][1] = r4[3];
            }
            #pragma unroll
            for (int mf = 0; mf < 4; mf++)
                #pragma unroll
                for (int nf = 0; nf < 8; nf++)
                    mma_f16(acc[mf][nf], a[mf], b[nf]);
        }
        __syncthreads();
    }

    int qr = lid >> 2, qc = (lid & 3) * 2;
    #pragma unroll
    for (int mf = 0; mf < 4; mf++) {
        #pragma unroll
        for (int nf = 0; nf < 8; nf++) {
            float* cc = acc[mf][nf];
            int col = col0 + wn * 64 + nf * 8 + qc;
            #pragma unroll
            for (int half = 0; half < 2; half++) {
                int row = row0 + wm * 64 + mf * 16 + qr + half * 8;
                float v0 = cc[2*half], v1 = cc[2*half + 1];
                if (epi == 1) {
                    size_t idx = (size_t)row * N + col;
                    float2 rr = *(const float2*)(resid + idx);
                    *(float2*)(Cout + idx) = make_float2(v0 + rr.x, v1 + rr.y);
                } else if (epi == 2) {
                    v0 = fmaxf(v0, 0.f); v0 *= v0;
                    v1 = fmaxf(v1, 0.f); v1 *= v1;
                    size_t idx = (size_t)row * N + col;
                    __half2 p = __floats2half2_rn(v0, v1);
                    *(uint32_t*)(Oh + idx) = *(uint32_t*)&p;
                } else if (epi == 4) {
                    if (col < 2048) {
                        size_t idx = (size_t)row * 2048 + col;
                        *(float2*)(Cout + idx) = make_float2(v0, v1);
                    } else {
                        size_t idx = (size_t)row * 1024 + (col - 2048);
                        __half2 p = __floats2half2_rn(v0, v1);
                        *(uint32_t*)(Oh + idx) = *(uint32_t*)&p;
                    }
                } else {   // epi == 5
                    int t = tokOfRow[row];
                    if (t >= 0) {
                        size_t idx = (size_t)t * N + col;
                        float2 rr = *(const float2*)(resid + idx);
                        *(float2*)(Cout + idx) = make_float2(v0 + rr.x, v1 + rr.y);
                    }
                }
            }
        }
    }
}

// ======================= grouping / scalars =======================
__global__ void offsets_kernel() {
    if (threadIdx.x == 0 && blockIdx.x == 0) {
        int off = 0;
        for (int e = 0; e < E; e++) {
            g_segstart[e] = off;
            int padded = (g_counts[e] + 127) & ~127;
            for (int i = 0; i < padded / 128; i++)
                g_tileExpert[off / 128 + i] = e;
            off += padded;
        }
    }
}

__global__ void assign_kernel(const float* __restrict__ h2) {
    int t = blockIdx.x;
    __shared__ int slot_s;
    if (threadIdx.x == 0) {
        int e = g_expert[t];
        int slot = g_segstart[e] + atomicAdd(&g_cursor[e], 1);
        g_tokenOfRow[slot] = t;
        slot_s = slot;
    }
    __syncthreads();
    int s = slot_s;
    float4 v = ((const float4*)(h2 + (size_t)t * C))[threadIdx.x];
    __half2 p01 = __floats2half2_rn(v.x, v.y);
    __half2 p23 = __floats2half2_rn(v.z, v.w);
    ((uint2*)(g_h2g + (size_t)s * C))[threadIdx.x] =
        make_uint2(*(uint32_t*)&p01, *(uint32_t*)&p23);
}

__global__ void scalars_kernel(float* __restrict__ out) {
    if (threadIdx.x == 0 && blockIdx.x == 0) {
        const double NTOK = (double)BT;
        double aux = 0.0;
        for (int e = 0; e < E; e++) {
            double actual = (double)g_counts[e] / NTOK;
            double expd   = g_expsum[e] / NTOK;
            aux += actual * expd;
        }
        size_t base = (size_t)BT * C;
        out[base + 0] = (float)((double)E * aux);
        out[base + 1] = (float)(g_zsum / NTOK);
        out[base + 2] = (float)((g_entsum / NTOK) / log((double)E));
        for (int e = 0; e < E; e++)
            out[base + 3 + e] = (float)((double)g_counts[e] / NTOK);
    }
}

// ======================= launch =======================
static void* sym(const void* s) { void* p = nullptr; cudaGetSymbolAddress(&p, s); return p; }

extern "C" void kernel_launch(void* const* d_in, const int* in_sizes, int n_in,
                              void* d_out, int out_size)
{
    const float* x     = (const float*)d_in[0];
    const float* Wq    = (const float*)d_in[1];
    const float* Wk    = (const float*)d_in[2];
    const float* Wv    = (const float*)d_in[3];
    const float* Wo    = (const float*)d_in[4];
    const float* Wr    = (const float*)d_in[5];
    const float* Wfc   = (const float*)d_in[6];
    const float* Wproj = (const float*)d_in[7];
    float* out = (float*)d_out;

    static bool init_done = false;
    static cudaStream_t s2;
    static cudaEvent_t evFork, evWo, evMoE;
    if (!init_done) {
        cudaFuncSetAttribute(gemm_fp16x1, cudaFuncAttributeMaxDynamicSharedMemorySize, SMEM_GEMM1_BYTES);
        cudaFuncSetAttribute(attn_mma_kernel, cudaFuncAttributeMaxDynamicSharedMemorySize, ATT_SMEM);
        cudaStreamCreateWithFlags(&s2, cudaStreamNonBlocking);
        cudaEventCreateWithFlags(&evFork, cudaEventDisableTiming);
        cudaEventCreateWithFlags(&evWo,   cudaEventDisableTiming);
        cudaEventCreateWithFlags(&evMoE,  cudaEventDisableTiming);
        init_done = true;
    }

    __half* h1 = (__half*)sym(g_h1);
    float* qk = (float*)sym(g_qk);
    __half* qhp = (__half*)sym(g_qhi); __half* qlp = (__half*)sym(g_qlo);
    __half* khp = (__half*)sym(g_kh);
    __half* vhp = (__half*)sym(g_vh);
    __half* yb = (__half*)sym(g_y);
    float* x2 = (float*)sym(g_x2);
    float* h2 = (float*)sym(g_h2);
    __half* h2g = (__half*)sym(g_h2g);
    __half* hid = (__half*)sym(g_hid);
    __half* wqkv = (__half*)sym(g_wqkv);
    __half* wo   = (__half*)sym(g_wo);
    __half* wfc  = (__half*)sym(g_wfc);
    __half* wpj  = (__half*)sym(g_wpj);
    int* tileE = (int*)sym(g_tileExpert);
    int* tokR  = (int*)sym(g_tokenOfRow);

    // ---- main stream (0): front section ----
    reset_kernel<<<(GROUP_CAP + 255) / 256, 256>>>();
    cudaEventRecord(evFork, 0);

    // ---- side stream: weight conversions needed later ----
    cudaStreamWaitEvent(s2, evFork, 0);
    wconv_kernel<<<dim3(C/64,  C/64,  1), 256, 0, s2>>>(Wo,    wo,  C,  C);
    cudaEventRecord(evWo, s2);
    wconv_kernel<<<dim3(FF/64, C/64,  E), 256, 0, s2>>>(Wfc,   wfc, C,  FF);
    wconv_kernel<<<dim3(C/64,  FF/64, E), 256, 0, s2>>>(Wproj, wpj, FF, C);
    cudaEventRecord(evMoE, s2);

    // ---- main stream continues ----
    rmsnorm_kernel<<<BT, 256>>>(x, h1);
    wconv_kernel<<<dim3(C/64, C/64, 1), 256>>>(Wq, wqkv,         C, C);
    wconv_kernel<<<dim3(C/64, C/64, 1), 256>>>(Wk, wqkv + C*C,   C, C);
    wconv_kernel<<<dim3(C/64, C/64, 1), 256>>>(Wv, wqkv + 2*C*C, C, C);
    gemm_fp16x1<<<dim3(3*C/256, BT/128), 256, SMEM_GEMM1_BYTES>>>(
        h1, wqkv, 0, qk, vhp, nullptr, nullptr, nullptr, 3*C, C, 4);
    qk_rope_kernel<<<BT, 512>>>(qk, qhp, qlp, khp);
    attn_mma_kernel<<<dim3(T/128, Bq*H), 256, ATT_SMEM>>>(
        qhp, qlp, khp, vhp, yb);

    cudaStreamWaitEvent(0, evWo, 0);
    gemm_fp16x1<<<dim3(C/256, BT/128), 256, SMEM_GEMM1_BYTES>>>(
        yb, wo, 0, x2, nullptr, x, nullptr, nullptr, C, C, 1);
    rmsnorm_router_kernel<<<BT, 256>>>(x2, h2, Wr);
    offsets_kernel<<<1, 32>>>();
    assign_kernel<<<BT, 256>>>(h2);

    cudaStreamWaitEvent(0, evMoE, 0);
    gemm_fp16x1<<<dim3(FF/256, NTILES), 256, SMEM_GEMM1_BYTES>>>(
        h2g, wfc, (size_t)FF * C, nullptr, hid, nullptr, tileE, nullptr, FF, C, 2);
    gemm_fp16x1<<<dim3(C/256, NTILES), 256, SMEM_GEMM1_BYTES>>>(
        hid, wpj, (size_t)C * FF, out, nullptr, x2, tileE, tokR, C, FF, 5);
    scalars_kernel<<<1, 32>>>(out);
}

// round 17
// speedup vs baseline: 2.4187x; 1.0831x over previous
#include <cuda_runtime.h>
#include <cuda_fp16.h>
#include <cstdint>
#include <math.h>

#define Bq 2
#define T 2048
#define C 1024
#define H 16
#define D 64
#define E 4
#define BT (Bq*T)
#define FF (4*C)
#define GROUP_CAP (BT + E*128)
#define NTILES (GROUP_CAP/128)
#define EPS_RMS 1.1920929e-07f

#define SMEM_SWIZZLE_128B(b) ((b) ^ (((b) >> 3) & 0x70))

__device__ __forceinline__ uint32_t smem_to_u32(const void* p) {
    uint32_t a;
    asm("{ .reg .u64 t; cvta.to.shared.u64 t, %1; cvt.u32.u64 %0, t; }" : "=r"(a) : "l"(p));
    return a;
}
__device__ __forceinline__ void ldsm4(uint32_t* r, uint32_t addr) {
    asm volatile("ldmatrix.sync.aligned.m8n8.x4.shared.b16 {%0,%1,%2,%3}, [%4];"
                 : "=r"(r[0]), "=r"(r[1]), "=r"(r[2]), "=r"(r[3]) : "r"(addr));
}
__device__ __forceinline__ void ldsm4t(uint32_t* r, uint32_t addr) {
    asm volatile("ldmatrix.sync.aligned.m8n8.x4.trans.shared.b16 {%0,%1,%2,%3}, [%4];"
                 : "=r"(r[0]), "=r"(r[1]), "=r"(r[2]), "=r"(r[3]) : "r"(addr));
}
__device__ __forceinline__ void mma_f16(float* c, const uint32_t* a, const uint32_t* b) {
    asm volatile("mma.sync.aligned.m16n8k16.row.col.f32.f16.f16.f32 "
        "{%0,%1,%2,%3}, {%4,%5,%6,%7}, {%8,%9}, {%0,%1,%2,%3};"
        : "+f"(c[0]), "+f"(c[1]), "+f"(c[2]), "+f"(c[3])
        : "r"(a[0]), "r"(a[1]), "r"(a[2]), "r"(a[3]), "r"(b[0]), "r"(b[1]));
}
__device__ __forceinline__ float ex2f(float x) {
    float y; asm("ex2.approx.ftz.f32 %0, %1;" : "=f"(y) : "f"(x)); return y;
}
#define CP16(s, g) asm volatile("cp.async.cg.shared.global [%0], [%1], 16;" \
                                :: "r"(s), "l"(g) : "memory")

// ======================= scratch (static device globals) =======================
__device__ __half g_h1[BT*C];
__device__ __half g_qkv[BT*3*C];          // q | k | v per token, stride 3072
__device__ __half g_q[BT*C];
__device__ __half g_k[BT*C];
__device__ __half g_y[BT*C];
__device__ float g_x2[BT*C], g_h2[BT*C];
__device__ __half g_h2g[GROUP_CAP*C];
__device__ __half g_hid[(size_t)GROUP_CAP*FF];
__device__ __half g_wqkv[3*C*C];
__device__ __half g_wo[C*C];
__device__ __half g_wfc[(size_t)E*C*FF];
__device__ __half g_wpj[(size_t)E*FF*C];
__device__ int   g_expert[BT];
__device__ int   g_counts[E];
__device__ int   g_cursor[E];
__device__ int   g_segstart[E];
__device__ int   g_tileExpert[NTILES];
__device__ int   g_tokenOfRow[GROUP_CAP];
__device__ double g_expsum[E];
__device__ double g_zsum;
__device__ double g_entsum;

// ======================= small kernels =======================
__global__ void reset_kernel() {
    int i = blockIdx.x * blockDim.x + threadIdx.x;
    if (i < E) { g_counts[i] = 0; g_cursor[i] = 0; g_expsum[i] = 0.0; }
    if (i == 0) { g_zsum = 0.0; g_entsum = 0.0; }
    if (i < NTILES) g_tileExpert[i] = -1;
    if (i < GROUP_CAP) g_tokenOfRow[i] = -1;
}

// transpose weights: W [Kd, Nd] fp32 -> T [Nd, Kd] single fp16
__global__ void __launch_bounds__(256) wconv_kernel(
    const float* __restrict__ W, __half* __restrict__ Th, int Kd, int Nd) {
    __shared__ float tile[64][65];
    int b = blockIdx.z;
    const float* Wb = W + (size_t)b * Kd * Nd;
    __half* Tb = Th + (size_t)b * Kd * Nd;
    int n0 = blockIdx.x * 64, k0 = blockIdx.y * 64;
    int tid = threadIdx.x;
    int lr = tid >> 4, lc = (tid & 15) * 4;
    #pragma unroll
    for (int i = 0; i < 4; i++) {
        int k = lr + i * 16;
        float4 v = *(const float4*)(Wb + (size_t)(k0 + k) * Nd + n0 + lc);
        tile[k][lc] = v.x; tile[k][lc+1] = v.y; tile[k][lc+2] = v.z; tile[k][lc+3] = v.w;
    }
    __syncthreads();
    int wn = tid >> 4, wk = (tid & 15) * 4;
    #pragma unroll
    for (int i = 0; i < 4; i++) {
        int n = wn + i * 16;
        __half2 p01 = __floats2half2_rn(tile[wk][n],   tile[wk+1][n]);
        __half2 p23 = __floats2half2_rn(tile[wk+2][n], tile[wk+3][n]);
        size_t o = (size_t)(n0 + n) * Kd + k0 + wk;
        *(uint2*)(Tb + o) = make_uint2(*(uint32_t*)&p01, *(uint32_t*)&p23);
    }
}

// RMSNorm over C -> single fp16
__global__ void rmsnorm_kernel(const float* __restrict__ in, __half* __restrict__ oh) {
    int t = blockIdx.x;
    const float4* ip = (const float4*)(in + (size_t)t * C);
    __shared__ float red[8];
    float4 v = ip[threadIdx.x];
    float ss = v.x*v.x + v.y*v.y + v.z*v.z + v.w*v.w;
    #pragma unroll
    for (int o = 16; o; o >>= 1) ss += __shfl_xor_sync(0xffffffffu, ss, o);
    if ((threadIdx.x & 31) == 0) red[threadIdx.x >> 5] = ss;
    __syncthreads();
    if (threadIdx.x == 0) {
        float s = 0.f;
        #pragma unroll
        for (int w = 0; w < 8; w++) s += red[w];
        red[0] = s;
    }
    __syncthreads();
    float r = rsqrtf(red[0] / (float)C + EPS_RMS);
    __half2 p01 = __floats2half2_rn(v.x * r, v.y * r);
    __half2 p23 = __floats2half2_rn(v.z * r, v.w * r);
    ((uint2*)(oh + (size_t)t * C))[threadIdx.x] =
        make_uint2(*(uint32_t*)&p01, *(uint32_t*)&p23);
}

// RMSNorm fp32 out + fused router
__global__ void rmsnorm_router_kernel(const float* __restrict__ in, float* __restrict__ outf,
                                      const float* __restrict__ Wr) {
    int t = blockIdx.x;
    const float4* ip = (const float4*)(in + (size_t)t * C);
    __shared__ float red[8];
    __shared__ float lred[32];
    float4 v = ip[threadIdx.x];
    float ss = v.x*v.x + v.y*v.y + v.z*v.z + v.w*v.w;
    #pragma unroll
    for (int o = 16; o; o >>= 1) ss += __shfl_xor_sync(0xffffffffu, ss, o);
    if ((threadIdx.x & 31) == 0) red[threadIdx.x >> 5] = ss;
    __syncthreads();
    if (threadIdx.x == 0) {
        float s = 0.f;
        #pragma unroll
        for (int w = 0; w < 8; w++) s += red[w];
        red[0] = s;
    }
    __syncthreads();
    float r = rsqrtf(red[0] / (float)C + EPS_RMS);
    float4 o = make_float4(v.x*r, v.y*r, v.z*r, v.w*r);
    ((float4*)(outf + (size_t)t * C))[threadIdx.x] = o;

    int c0 = threadIdx.x * 4;
    float4 w0 = *(const float4*)(Wr + (size_t)(c0+0) * E);
    float4 w1 = *(const float4*)(Wr + (size_t)(c0+1) * E);
    float4 w2 = *(const float4*)(Wr + (size_t)(c0+2) * E);
    float4 w3 = *(const float4*)(Wr + (size_t)(c0+3) * E);
    float a0 = o.x*w0.x + o.y*w1.x + o.z*w2.x + o.w*w3.x;
    float a1 = o.x*w0.y + o.y*w1.y + o.z*w2.y + o.w*w3.y;
    float a2 = o.x*w0.z + o.y*w1.z + o.z*w2.z + o.w*w3.z;
    float a3 = o.x*w0.w + o.y*w1.w + o.z*w2.w + o.w*w3.w;
    #pragma unroll
    for (int off = 16; off; off >>= 1) {
        a0 += __shfl_xor_sync(0xffffffffu, a0, off);
        a1 += __shfl_xor_sync(0xffffffffu, a1, off);
        a2 += __shfl_xor_sync(0xffffffffu, a2, off);
        a3 += __shfl_xor_sync(0xffffffffu, a3, off);
    }
    if ((threadIdx.x & 31) == 0) {
        int w = threadIdx.x >> 5;
        lred[w*4+0] = a0; lred[w*4+1] = a1; lred[w*4+2] = a2; lred[w*4+3] = a3;
    }
    __syncthreads();
    if (threadIdx.x == 0) {
        float lg[4];
        #pragma unroll
        for (int e = 0; e < 4; e++) {
            float s = 0.f;
            #pragma unroll
            for (int w = 0; w < 8; w++) s += lred[w*4+e];
            lg[e] = s;
        }
        int arg = 0;
        #pragma unroll
        for (int e = 1; e < 4; e++) if (lg[e] > lg[arg]) arg = e;
        float m = fmaxf(fmaxf(lg[0], lg[1]), fmaxf(lg[2], lg[3]));
        float ez[4]; float sum = 0.f;
        #pragma unroll
        for (int e = 0; e < 4; e++) { ez[e] = expf(lg[e] - m); sum += ez[e]; }
        float p[4];
        #pragma unroll
        for (int e = 0; e < 4; e++) p[e] = ez[e] / sum;
        g_expert[t] = arg;
        atomicAdd(&g_counts[arg], 1);
        #pragma unroll
        for (int e = 0; e < 4; e++) atomicAdd(&g_expsum[e], (double)p[e]);
        float lse = m + logf(sum);
        atomicAdd(&g_zsum, (double)lse * (double)lse);
        float ent = 0.f;
        #pragma unroll
        for (int e = 0; e < 4; e++) ent -= p[e] * logf(p[e] + 1e-9f);
        atomicAdd(&g_entsum, (double)ent);
    }
}

// per-head RMSNorm + RoPE; reads qkv fp16 [BT,3072]; q,k -> single fp16
__global__ void qk_rope_kernel(const __half* __restrict__ qkv,
                               __half* __restrict__ qo, __half* __restrict__ ko) {
    int tok  = blockIdx.x;
    int head = threadIdx.x >> 5;
    int lane = threadIdx.x & 31;
    int tpos = tok % T;
    float ex  = (float)(2 * lane) / 64.0f;
    float inv = 1.0f / powf(10000.0f, ex);
    float ang = (float)tpos * inv;
    float c = cosf(ang), s = sinf(ang);
    size_t obase = (size_t)tok * C + head * D;
    #pragma unroll
    for (int m = 0; m < 2; m++) {
        const __half* src = qkv + (size_t)tok * 3072 + m * 1024 + head * D;
        __half* dst = (m == 0 ? qo : ko) + obase;
        float x1 = __half2float(src[lane]), x2 = __half2float(src[lane + 32]);
        float ss = x1*x1 + x2*x2;
        #pragma unroll
        for (int o = 16; o; o >>= 1) ss += __shfl_xor_sync(0xffffffffu, ss, o);
        float r = rsqrtf(ss / (float)D + EPS_RMS);
        x1 *= r; x2 *= r;
        dst[lane]      = __float2half( x1 * c + x2 * s);
        dst[lane + 32] = __float2half(-x1 * s + x2 * c);
    }
}

// ======================= HMMA flash attention (all single fp16: QK 1 MMA, PV 1 MMA) =======
// Q tile: 128 rows x 128B = 1024 chunks (16B). K/V stage: 64 rows x 128B each = 512+512 chunks.
#define AT_Q   0
#define AT_STG 16384
#define AT_STGSZ 16384
#define AT_K   0
#define AT_V   8192
#define ATT_SMEM (16384 + 2*16384)

__global__ void __launch_bounds__(256) attn_mma_kernel(
    const __half* __restrict__ qq, const __half* __restrict__ kk,
    const __half* __restrict__ qkv,       // v at offset 2048, row stride 3072
    __half* __restrict__ yo)
{
    extern __shared__ __align__(1024) char smem[];
    uint32_t sb = smem_to_u32(smem);
    int bh = blockIdx.y;
    int b = bh / H, hh = bh % H;
    int qb = blockIdx.x;
    int q0 = qb * 128;
    int tid = threadIdx.x, wid = tid >> 5, lid = tid & 31;
    int nkt = 2 * qb + 2;

    // ---- Q tile: 1024 chunks ----
    #pragma unroll
    for (int i = 0; i < 4; i++) {
        int lin = tid + i * 256;
        int r = lin >> 3, ch = lin & 7;
        uint32_t so = SMEM_SWIZZLE_128B((uint32_t)(r * 128 + ch * 16));
        size_t g = (size_t)(b*T + q0 + r) * C + hh * D + ch * 8;
        CP16(sb + AT_Q + so, qq + g);
    }
    asm volatile("cp.async.commit_group;" ::: "memory");
    // ---- K/V stage 0: 1024 chunks (K first 512, V next 512) ----
    #pragma unroll
    for (int i = 0; i < 4; i++) {
        int lin = tid + i * 256;
        uint32_t st = sb + AT_STG;
        if (lin < 512) {
            int r = lin >> 3, ch = lin & 7;
            uint32_t so = SMEM_SWIZZLE_128B((uint32_t)(r * 128 + ch * 16));
            size_t gk = (size_t)(b*T + r) * C + hh * D + ch * 8;
            CP16(st + AT_K + so, kk + gk);
        } else {
            int l2 = lin - 512;
            int r = l2 >> 3, ch = l2 & 7;
            uint32_t so = SMEM_SWIZZLE_128B((uint32_t)(r * 128 + ch * 16));
            size_t gv = (size_t)(b*T + r) * 3072 + 2048 + hh * D + ch * 8;
            CP16(st + AT_V + so, qkv + gv);
        }
    }
    asm volatile("cp.async.commit_group;" ::: "memory");

    uint32_t qa[4][4];
    float oac[8][4];
    #pragma unroll
    for (int j = 0; j < 8; j++)
        #pragma unroll
        for (int r = 0; r < 4; r++) oac[j][r] = 0.f;
    float m0 = -1e30f, m1 = -1e30f, l0 = 0.f, l1 = 0.f;

    int off = lid & 7, part = lid >> 3;
    int qr = lid >> 2, qc = (lid & 3) * 2;
    const float SC2 = 0.18033688011112042f;

    for (int kt = 0; kt < nkt; kt++) {
        if (kt + 1 < nkt) {
            #pragma unroll
            for (int i = 0; i < 4; i++) {
                int lin = tid + i * 256;
                uint32_t st = sb + AT_STG + (uint32_t)((kt + 1) & 1) * AT_STGSZ;
                if (lin < 512) {
                    int r = lin >> 3, ch = lin & 7;
                    uint32_t so = SMEM_SWIZZLE_128B((uint32_t)(r * 128 + ch * 16));
                    size_t gk = (size_t)(b*T + (kt + 1) * 64 + r) * C + hh * D + ch * 8;
                    CP16(st + AT_K + so, kk + gk);
                } else {
                    int l2 = lin - 512;
                    int r = l2 >> 3, ch = l2 & 7;
                    uint32_t so = SMEM_SWIZZLE_128B((uint32_t)(r * 128 + ch * 16));
                    size_t gv = (size_t)(b*T + (kt + 1) * 64 + r) * 3072 + 2048 + hh * D + ch * 8;
                    CP16(st + AT_V + so, qkv + gv);
                }
            }
            asm volatile("cp.async.commit_group;" ::: "memory");
            asm volatile("cp.async.wait_group 1;" ::: "memory");
        } else {
            asm volatile("cp.async.wait_group 0;" ::: "memory");
        }
        __syncthreads();

        if (kt == 0) {
            #pragma unroll
            for (int kq = 0; kq < 4; kq++) {
                int row = wid * 16 + (part & 1) * 8 + off;
                int colb = kq * 32 + (part & 2) * 8;
                uint32_t so = SMEM_SWIZZLE_128B((uint32_t)(row * 128 + colb));
                ldsm4(qa[kq], sb + AT_Q + so);
            }
        }

        uint32_t st = sb + AT_STG + (uint32_t)(kt & 1) * AT_STGSZ;

        float s[8][4];
        #pragma unroll
        for (int j = 0; j < 8; j++)
            #pragma unroll
            for (int r = 0; r < 4; r++) s[j][r] = 0.f;
        #pragma unroll
        for (int kq = 0; kq < 4; kq++) {
            #pragma unroll
            for (int jj = 0; jj < 4; jj++) {
                int row = jj * 16 + (part & 2) * 4 + off;
                int colb = kq * 32 + (part & 1) * 16;
                uint32_t so = SMEM_SWIZZLE_128B((uint32_t)(row * 128 + colb));
                uint32_t kf[4];
                ldsm4(kf, st + AT_K + so);
                mma_f16(s[2*jj],   qa[kq], kf);
                mma_f16(s[2*jj+1], qa[kq], kf + 2);
            }
        }

        bool domask = (kt >= nkt - 2);
        #pragma unroll
        for (int j = 0; j < 8; j++) {
            #pragma unroll
            for (int r = 0; r < 4; r++) {
                float v = s[j][r] * SC2;
                if (domask) {
                    int key = kt * 64 + j * 8 + qc + (r & 1);
                    int row = q0 + wid * 16 + qr + (r & 2) * 4;
                    if (key > row) v = -1e30f;
                }
                s[j][r] = v;
            }
        }

        float mx0 = -1e30f, mx1 = -1e30f;
        #pragma unroll
        for (int j = 0; j < 8; j++) {
            mx0 = fmaxf(mx0, fmaxf(s[j][0], s[j][1]));
            mx1 = fmaxf(mx1, fmaxf(s[j][2], s[j][3]));
        }
        mx0 = fmaxf(mx0, __shfl_xor_sync(0xffffffffu, mx0, 1));
        mx0 = fmaxf(mx0, __shfl_xor_sync(0xffffffffu, mx0, 2));
        mx1 = fmaxf(mx1, __shfl_xor_sync(0xffffffffu, mx1, 1));
        mx1 = fmaxf(mx1, __shfl_xor_sync(0xffffffffu, mx1, 2));
        float mn0 = fmaxf(m0, mx0), mn1 = fmaxf(m1, mx1);
        float al0 = ex2f(m0 - mn0), al1 = ex2f(m1 - mn1);
        float sm0 = 0.f, sm1 = 0.f;
        #pragma unroll
        for (int j = 0; j < 8; j++) {
            s[j][0] = ex2f(s[j][0] - mn0); sm0 += s[j][0];
            s[j][1] = ex2f(s[j][1] - mn0); sm0 += s[j][1];
            s[j][2] = ex2f(s[j][2] - mn1); sm1 += s[j][2];
            s[j][3] = ex2f(s[j][3] - mn1); sm1 += s[j][3];
        }
        sm0 += __shfl_xor_sync(0xffffffffu, sm0, 1);
        sm0 += __shfl_xor_sync(0xffffffffu, sm0, 2);
        sm1 += __shfl_xor_sync(0xffffffffu, sm1, 1);
        sm1 += __shfl_xor_sync(0xffffffffu, sm1, 2);
        l0 = l0 * al0 + sm0;  l1 = l1 * al1 + sm1;
        m0 = mn0;  m1 = mn1;
        #pragma unroll
        for (int j = 0; j < 8; j++) {
            oac[j][0] *= al0; oac[j][1] *= al0;
            oac[j][2] *= al1; oac[j][3] *= al1;
        }

        #pragma unroll
        for (int kp = 0; kp < 4; kp++) {
            uint32_t pa[4];
            __half2 h01 = __floats2half2_rn(s[2*kp][0],   s[2*kp][1]);
            __half2 h23 = __floats2half2_rn(s[2*kp][2],   s[2*kp][3]);
            __half2 h45 = __floats2half2_rn(s[2*kp+1][0], s[2*kp+1][1]);
            __half2 h67 = __floats2half2_rn(s[2*kp+1][2], s[2*kp+1][3]);
            pa[0] = *(uint32_t*)&h01; pa[1] = *(uint32_t*)&h23;
            pa[2] = *(uint32_t*)&h45; pa[3] = *(uint32_t*)&h67;
            #pragma unroll
            for (int jj = 0; jj < 4; jj++) {
                int row = kp * 16 + (part & 1) * 8 + off;
                int colb = jj * 32 + (part & 2) * 8;
                uint32_t so = SMEM_SWIZZLE_128B((uint32_t)(row * 128 + colb));
                uint32_t v4[4];
                ldsm4t(v4, st + AT_V + so);
                mma_f16(oac[2*jj],   pa, v4);
                mma_f16(oac[2*jj+1], pa, v4 + 2);
            }
        }
        __syncthreads();
    }

    float inv0 = 1.f / l0, inv1 = 1.f / l1;
    #pragma unroll
    for (int j = 0; j < 8; j++) {
        size_t i0 = (size_t)(b*T + q0 + wid*16 + qr) * C + hh * D + j * 8 + qc;
        size_t i1 = (size_t)(b*T + q0 + wid*16 + qr + 8) * C + hh * D + j * 8 + qc;
        __half2 p0 = __floats2half2_rn(oac[j][0] * inv0, oac[j][1] * inv0);
        __half2 p1 = __floats2half2_rn(oac[j][2] * inv1, oac[j][3] * inv1);
        *(uint32_t*)(yo + i0) = *(uint32_t*)&p0;
        *(uint32_t*)(yo + i1) = *(uint32_t*)&p1;
    }
}

// ======================= HMMA fp16x1 GEMM — A single x B single, 1 MMA ====================
// epi: 1 Cout = acc + resid; 2 relu(acc)^2 -> single fp16; 3 single fp16 out;
//      5 MoE scatter: out[token*N+col] = acc + resid[token*N+col]
#define KTILE 64
#define X_A 0
#define X_B 16384
#define X_STAGE 49152
#define SMEM_GEMM1_BYTES (2*X_STAGE)

__global__ void __launch_bounds__(256, 1) gemm_fp16x1(
    const __half* __restrict__ Aw,
    const __half* __restrict__ Bw, size_t bstride,
    float* __restrict__ Cout,
    __half* __restrict__ Oh,
    const float* __restrict__ resid,
    const int* __restrict__ tileExpert,
    const int* __restrict__ tokOfRow,
    int N, int K, int epi)
{
    extern __shared__ __align__(1024) char smem[];
    int by = blockIdx.y, bx = blockIdx.x;
    int e = 0;
    if (tileExpert) { e = tileExpert[by]; if (e < 0) return; }
    const __half* Bh = Bw + (size_t)e * bstride;

    uint32_t sb = smem_to_u32(smem);
    int tid = threadIdx.x, wid = tid >> 5, lid = tid & 31;
    int wm = wid & 1, wn = wid >> 1;
    int row0 = by * 128, col0 = bx * 256;
    int nkt = K / KTILE;

    float acc[4][8][4];
    #pragma unroll
    for (int i = 0; i < 4; i++)
        #pragma unroll
        for (int j = 0; j < 8; j++)
            #pragma unroll
            for (int r = 0; r < 4; r++) acc[i][j][r] = 0.f;

    int lr = tid >> 3, lc = tid & 7;

    {
        #pragma unroll
        for (int i = 0; i < 4; i++) {
            int r = lr + i * 32;
            uint32_t so = SMEM_SWIZZLE_128B((uint32_t)(r * 128 + lc * 16));
            size_t ga = (size_t)(row0 + r) * K + lc * 8;
            CP16(sb + X_A + so, Aw + ga);
        }
        #pragma unroll
        for (int i = 0; i < 8; i++) {
            int r = lr + i * 32;
            uint32_t so = SMEM_SWIZZLE_128B((uint32_t)(r * 128 + lc * 16));
            size_t gb = (size_t)(col0 + r) * K + lc * 8;
            CP16(sb + X_B + so, Bh + gb);
        }
        asm volatile("cp.async.commit_group;" ::: "memory");
    }

    for (int kt = 0; kt < nkt; kt++) {
        uint32_t cur = (uint32_t)(kt & 1) * X_STAGE;
        if (kt + 1 < nkt) {
            uint32_t nxt = (uint32_t)((kt + 1) & 1) * X_STAGE;
            int k0 = (kt + 1) * KTILE;
            #pragma unroll
            for (int i = 0; i < 4; i++) {
                int r = lr + i * 32;
                uint32_t so = SMEM_SWIZZLE_128B((uint32_t)(r * 128 + lc * 16));
                size_t ga = (size_t)(row0 + r) * K + k0 + lc * 8;
                CP16(sb + nxt + X_A + so, Aw + ga);
            }
            #pragma unroll
            for (int i = 0; i < 8; i++) {
                int r = lr + i * 32;
                uint32_t so = SMEM_SWIZZLE_128B((uint32_t)(r * 128 + lc * 16));
                size_t gb = (size_t)(col0 + r) * K + k0 + lc * 8;
                CP16(sb + nxt + X_B + so, Bh + gb);
            }
            asm volatile("cp.async.commit_group;" ::: "memory");
            asm volatile("cp.async.wait_group 1;" ::: "memory");
        } else {
            asm volatile("cp.async.wait_group 0;" ::: "memory");
        }
        __syncthreads();

        uint32_t sA = sb + cur + X_A, sB = sb + cur + X_B;
        #pragma unroll
        for (int kq = 0; kq < 4; kq++) {
            int colb = (kq * 16 + (lid >> 4) * 8) * 2;
            uint32_t a[4][4];
            #pragma unroll
            for (int mf = 0; mf < 4; mf++) {
                int rowm = wm * 64 + mf * 16 + (lid & 15);
                uint32_t so = SMEM_SWIZZLE_128B((uint32_t)(rowm * 128 + colb));
                ldsm4(a[mf], sA + so);
            }
            uint32_t b[8][2];
            #pragma unroll
            for (int g = 0; g < 4; g++) {
                int rown = wn * 64 + g * 16 + (lid & 15);
                uint32_t so = SMEM_SWIZZLE_128B((uint32_t)(rown * 128 + colb));
                uint32_t r4[4];
                ldsm4(r4, sB + so);
                b[2*g][0] = r4[0]; b[2*g+1][0] = r4[1];
                b[2*g][1] = r4[2]; b[2*g+1][1] = r4[3];
            }
            #pragma unroll
            for (int mf = 0; mf < 4; mf++)
                #pragma unroll
                for (int nf = 0; nf < 8; nf++)
                    mma_f16(acc[mf][nf], a[mf], b[nf]);
        }
        __syncthreads();
    }

    int qr = lid >> 2, qc = (lid & 3) * 2;
    #pragma unroll
    for (int mf = 0; mf < 4; mf++) {
        #pragma unroll
        for (int nf = 0; nf < 8; nf++) {
            float* cc = acc[mf][nf];
            int col = col0 + wn * 64 + nf * 8 + qc;
            #pragma unroll
            for (int half = 0; half < 2; half++) {
                int row = row0 + wm * 64 + mf * 16 + qr + half * 8;
                float v0 = cc[2*half], v1 = cc[2*half + 1];
                if (epi == 1) {
                    size_t idx = (size_t)row * N + col;
                    float2 rr = *(const float2*)(resid + idx);
                    *(float2*)(Cout + idx) = make_float2(v0 + rr.x, v1 + rr.y);
                } else if (epi == 2) {
                    v0 = fmaxf(v0, 0.f); v0 *= v0;
                    v1 = fmaxf(v1, 0.f); v1 *= v1;
                    size_t idx = (size_t)row * N + col;
                    __half2 p = __floats2half2_rn(v0, v1);
                    *(uint32_t*)(Oh + idx) = *(uint32_t*)&p;
                } else if (epi == 3) {
                    size_t idx = (size_t)row * N + col;
                    __half2 p = __floats2half2_rn(v0, v1);
                    *(uint32_t*)(Oh + idx) = *(uint32_t*)&p;
                } else {   // epi == 5
                    int t = tokOfRow[row];
                    if (t >= 0) {
                        size_t idx = (size_t)t * N + col;
                        float2 rr = *(const float2*)(resid + idx);
                        *(float2*)(Cout + idx) = make_float2(v0 + rr.x, v1 + rr.y);
                    }
                }
            }
        }
    }
}

// ======================= grouping / scalars =======================
__global__ void offsets_kernel() {
    if (threadIdx.x == 0 && blockIdx.x == 0) {
        int off = 0;
        for (int e = 0; e < E; e++) {
            g_segstart[e] = off;
            int padded = (g_counts[e] + 127) & ~127;
            for (int i = 0; i < padded / 128; i++)
                g_tileExpert[off / 128 + i] = e;
            off += padded;
        }
    }
}

__global__ void assign_kernel(const float* __restrict__ h2) {
    int t = blockIdx.x;
    __shared__ int slot_s;
    if (threadIdx.x == 0) {
        int e = g_expert[t];
        int slot = g_segstart[e] + atomicAdd(&g_cursor[e], 1);
        g_tokenOfRow[slot] = t;
        slot_s = slot;
    }
    __syncthreads();
    int s = slot_s;
    float4 v = ((const float4*)(h2 + (size_t)t * C))[threadIdx.x];
    __half2 p01 = __floats2half2_rn(v.x, v.y);
    __half2 p23 = __floats2half2_rn(v.z, v.w);
    ((uint2*)(g_h2g + (size_t)s * C))[threadIdx.x] =
        make_uint2(*(uint32_t*)&p01, *(uint32_t*)&p23);
}

__global__ void scalars_kernel(float* __restrict__ out) {
    if (threadIdx.x == 0 && blockIdx.x == 0) {
        const double NTOK = (double)BT;
        double aux = 0.0;
        for (int e = 0; e < E; e++) {
            double actual = (double)g_counts[e] / NTOK;
            double expd   = g_expsum[e] / NTOK;
            aux += actual * expd;
        }
        size_t base = (size_t)BT * C;
        out[base + 0] = (float)((double)E * aux);
        out[base + 1] = (float)(g_zsum / NTOK);
        out[base + 2] = (float)((g_entsum / NTOK) / log((double)E));
        for (int e = 0; e < E; e++)
            out[base + 3 + e] = (float)((double)g_counts[e] / NTOK);
    }
}

// ======================= launch =======================
static void* sym(const void* s) { void* p = nullptr; cudaGetSymbolAddress(&p, s); return p; }

extern "C" void kernel_launch(void* const* d_in, const int* in_sizes, int n_in,
                              void* d_out, int out_size)
{
    const float* x     = (const float*)d_in[0];
    const float* Wq    = (const float*)d_in[1];
    const float* Wk    = (const float*)d_in[2];
    const float* Wv    = (const float*)d_in[3];
    const float* Wo    = (const float*)d_in[4];
    const float* Wr    = (const float*)d_in[5];
    const float* Wfc   = (const float*)d_in[6];
    const float* Wproj = (const float*)d_in[7];
    float* out = (float*)d_out;

    static bool init_done = false;
    static cudaStream_t s2;
    static cudaEvent_t evFork, evWo, evMoE;
    if (!init_done) {
        cudaFuncSetAttribute(gemm_fp16x1, cudaFuncAttributeMaxDynamicSharedMemorySize, SMEM_GEMM1_BYTES);
        cudaFuncSetAttribute(attn_mma_kernel, cudaFuncAttributeMaxDynamicSharedMemorySize, ATT_SMEM);
        cudaStreamCreateWithFlags(&s2, cudaStreamNonBlocking);
        cudaEventCreateWithFlags(&evFork, cudaEventDisableTiming);
        cudaEventCreateWithFlags(&evWo,   cudaEventDisableTiming);
        cudaEventCreateWithFlags(&evMoE,  cudaEventDisableTiming);
        init_done = true;
    }

    __half* h1 = (__half*)sym(g_h1);
    __half* qkv = (__half*)sym(g_qkv);
    __half* qb = (__half*)sym(g_q);
    __half* kb = (__half*)sym(g_k);
    __half* yb = (__half*)sym(g_y);
    float* x2 = (float*)sym(g_x2);
    float* h2 = (float*)sym(g_h2);
    __half* h2g = (__half*)sym(g_h2g);
    __half* hid = (__half*)sym(g_hid);
    __half* wqkv = (__half*)sym(g_wqkv);
    __half* wo   = (__half*)sym(g_wo);
    __half* wfc  = (__half*)sym(g_wfc);
    __half* wpj  = (__half*)sym(g_wpj);
    int* tileE = (int*)sym(g_tileExpert);
    int* tokR  = (int*)sym(g_tokenOfRow);

    // ---- main stream (0): front section ----
    reset_kernel<<<(GROUP_CAP + 255) / 256, 256>>>();
    cudaEventRecord(evFork, 0);

    // ---- side stream: weight conversions needed later ----
    cudaStreamWaitEvent(s2, evFork, 0);
    wconv_kernel<<<dim3(C/64,  C/64,  1), 256, 0, s2>>>(Wo,    wo,  C,  C);
    cudaEventRecord(evWo, s2);
    wconv_kernel<<<dim3(FF/64, C/64,  E), 256, 0, s2>>>(Wfc,   wfc, C,  FF);
    wconv_kernel<<<dim3(C/64,  FF/64, E), 256, 0, s2>>>(Wproj, wpj, FF, C);
    cudaEventRecord(evMoE, s2);

    // ---- main stream continues ----
    rmsnorm_kernel<<<BT, 256>>>(x, h1);
    wconv_kernel<<<dim3(C/64, C/64, 1), 256>>>(Wq, wqkv,         C, C);
    wconv_kernel<<<dim3(C/64, C/64, 1), 256>>>(Wk, wqkv + C*C,   C, C);
    wconv_kernel<<<dim3(C/64, C/64, 1), 256>>>(Wv, wqkv + 2*C*C, C, C);
    gemm_fp16x1<<<dim3(3*C/256, BT/128), 256, SMEM_GEMM1_BYTES>>>(
        h1, wqkv, 0, nullptr, qkv, nullptr, nullptr, nullptr, 3*C, C, 3);
    qk_rope_kernel<<<BT, 512>>>(qkv, qb, kb);
    attn_mma_kernel<<<dim3(T/128, Bq*H), 256, ATT_SMEM>>>(qb, kb, qkv, yb);

    cudaStreamWaitEvent(0, evWo, 0);
    gemm_fp16x1<<<dim3(C/256, BT/128), 256, SMEM_GEMM1_BYTES>>>(
        yb, wo, 0, x2, nullptr, x, nullptr, nullptr, C, C, 1);
    rmsnorm_router_kernel<<<BT, 256>>>(x2, h2, Wr);
    offsets_kernel<<<1, 32>>>();
    assign_kernel<<<BT, 256>>>(h2);

    cudaStreamWaitEvent(0, evMoE, 0);
    gemm_fp16x1<<<dim3(FF/256, NTILES), 256, SMEM_GEMM1_BYTES>>>(
        h2g, wfc, (size_t)FF * C, nullptr, hid, nullptr, tileE, nullptr, FF, C, 2);
    gemm_fp16x1<<<dim3(C/256, NTILES), 256, SMEM_GEMM1_BYTES>>>(
        hid, wpj, (size_t)C * FF, out, nullptr, x2, tileE, tokR, C, FF, 5);
    scalars_kernel<<<1, 32>>>(out);
}